// round 9
// baseline (speedup 1.0000x reference)
#include <cuda_runtime.h>
#include <cuda_bf16.h>
#include <cstdint>

// ---------------------------------------------------------------------------
// BiMamba refiner block, round 8: pre-split bf16 hi/lo operands in gmem,
// cp.async 3-stage pipelined MMA GEMMs (no in-loop conversion work).
// ---------------------------------------------------------------------------

#define BB      2
#define TT      4
#define NP      196
#define LL      784
#define MM      1568
#define CM      768
#define DI      1536
#define DS      16
#define DR      48
#define DCONV   4

// ---------------- scratch ---------------------------------------------------
__device__ float g_xz  [2 * MM * 2 * DI];
__device__ float g_xb  [2 * MM * DI];
__device__ float g_xdbl[2 * MM * 80];
__device__ float g_dt  [2 * MM * DI];
__device__ float g_out [MM * 2 * CM];
__device__ float g_A   [2 * DI * DS];
__device__ int   g_arith;

// bf16 hi/lo operand buffers
__device__ __nv_bfloat16 g_ahi[2 * MM * DI];     // activations A (max 2*MM x 1536)
__device__ __nv_bfloat16 g_alo[2 * MM * DI];
__device__ __nv_bfloat16 g_bhi[MM * 2 * CM];     // secondary activations (o_out splits)
__device__ __nv_bfloat16 g_blo[MM * 2 * CM];
__device__ __nv_bfloat16 g_whi[2 * 3072 * CM];   // weights (max in_proj size)
__device__ __nv_bfloat16 g_wlo[2 * 3072 * CM];

__device__ __forceinline__ int map_row(int l, int dir) {
    if (dir == 0) return l;
    int t = l / NP, n = l - t * NP;
    return (TT - 1 - t) * NP + n;
}
__device__ __forceinline__ float sigmoidf_(float v) { return 1.0f / (1.0f + __expf(-v)); }
__device__ __forceinline__ float siluf_(float v)    { return v * sigmoidf_(v); }

__device__ __forceinline__ void mma_bf16(float c[4],
                                         uint32_t a0, uint32_t a1, uint32_t a2, uint32_t a3,
                                         uint32_t b0, uint32_t b1) {
    asm volatile(
        "mma.sync.aligned.m16n8k16.row.col.f32.bf16.bf16.f32 "
        "{%0,%1,%2,%3},{%4,%5,%6,%7},{%8,%9},{%0,%1,%2,%3};"
        : "+f"(c[0]), "+f"(c[1]), "+f"(c[2]), "+f"(c[3])
        : "r"(a0), "r"(a1), "r"(a2), "r"(a3), "r"(b0), "r"(b1));
}
__device__ __forceinline__ void ldsm_x4(uint32_t& r0, uint32_t& r1, uint32_t& r2,
                                        uint32_t& r3, uint32_t addr) {
    asm volatile("ldmatrix.sync.aligned.m8n8.x4.shared.b16 {%0,%1,%2,%3}, [%4];"
                 : "=r"(r0), "=r"(r1), "=r"(r2), "=r"(r3) : "r"(addr));
}
__device__ __forceinline__ void cp16(uint32_t dst, const void* src, int sz) {
    asm volatile("cp.async.cg.shared.global [%0], [%1], 16, %2;"
                 :: "r"(dst), "l"(src), "r"(sz) : "memory");
}
#define CP_COMMIT() asm volatile("cp.async.commit_group;" ::: "memory")

// swizzled 16B-chunk index for (row, chunk) in a [rows][2-chunk] tile
__device__ __forceinline__ int swz(int row, int chunk) {
    return row * 2 + (chunk ^ ((row >> 2) & 1));
}

// ---------------------------------------------------------------------------
__global__ void setup_A_kernel(const float* __restrict__ A_log) {
    int i = blockIdx.x * blockDim.x + threadIdx.x;
    if (i < 2 * DI * DS) g_A[i] = -expf(A_log[i]);
}

__global__ void check_arith_kernel() {
    __shared__ int bad;
    if (threadIdx.x == 0) bad = 0;
    __syncthreads();
    for (int row = threadIdx.x; row < 2 * DI; row += blockDim.x) {
        const float* a = &g_A[row * DS];
        float a0 = a[0], da = a[1] - a[0];
        for (int n = 2; n < DS; n++) {
            float expect = a0 + n * da;
            if (fabsf(a[n] - expect) > 1e-4f * (1.0f + fabsf(a[n]))) { bad = 1; break; }
        }
    }
    __syncthreads();
    if (threadIdx.x == 0) g_arith = bad ? 0 : 1;
}

// split fp32 [rows][srcStride] (first K cols) into bf16 hi/lo [rows][K]
__global__ void split_arr(const float* __restrict__ src, int srcStride, int K,
                          __nv_bfloat16* __restrict__ hi,
                          __nv_bfloat16* __restrict__ lo, long rows) {
    long idx = (long)blockIdx.x * blockDim.x + threadIdx.x;
    if (idx >= rows * (long)K) return;
    long row = idx / K;
    int  k   = (int)(idx - row * K);
    float v = src[row * (long)srcStride + k];
    __nv_bfloat16 h = __float2bfloat16(v);
    hi[idx] = h;
    lo[idx] = __float2bfloat16(v - __bfloat162float(h));
}

// RMSNorm: writes bf16 hi/lo directly (A operand of in_proj), stride CM
__global__ void rmsnorm_kernel(const float* __restrict__ x,
                               const float* __restrict__ norm_w) {
    int gid = blockIdx.x;
    int dir = gid / MM;
    int rem = gid - dir * MM;
    int b   = rem / LL, l = rem - b * LL;
    int lo_ = map_row(l, dir);
    const float* row = x + (size_t)(b * LL + lo_) * CM;

    float s = 0.f;
    for (int c = threadIdx.x; c < CM; c += blockDim.x) {
        float v = row[c];
        s += v * v;
    }
    __shared__ float warp_s[8];
    for (int off = 16; off > 0; off >>= 1) s += __shfl_down_sync(0xffffffffu, s, off);
    if ((threadIdx.x & 31) == 0) warp_s[threadIdx.x >> 5] = s;
    __syncthreads();
    if (threadIdx.x < 8) {
        float t = warp_s[threadIdx.x];
        for (int off = 4; off > 0; off >>= 1) t += __shfl_down_sync(0xffu, t, off);
        if (threadIdx.x == 0) warp_s[0] = t;
    }
    __syncthreads();
    float scale = rsqrtf(warp_s[0] / (float)CM + 1e-5f);

    const float* nw = norm_w + dir * CM;
    for (int c = threadIdx.x; c < CM; c += blockDim.x) {
        float v = row[c] * scale * nw[c];
        __nv_bfloat16 h = __float2bfloat16(v);
        g_ahi[(size_t)gid * CM + c] = h;
        g_alo[(size_t)gid * CM + c] = __float2bfloat16(v - __bfloat162float(h));
    }
}

// ---------------------------------------------------------------------------
// cp.async pipelined bf16 hi/lo MMA GEMM: C[M,N] = A[M,K] * W[N,K]^T
// BM=128, BN=128, BK=16, 3 stages. 8 warps (2m x 4n), warp tile 64x32.
// ---------------------------------------------------------------------------
#define EPI_STORE    0
#define EPI_SOFTPLUS 1
#define EPI_RESID    2
#define EPI_GATE     3
#define EPI_BIAS     4

template <int EPI>
__global__ void __launch_bounds__(256)
gemm_as(const __nv_bfloat16* __restrict__ Ahib, const __nv_bfloat16* __restrict__ Alob,
        int ldaK, size_t sA,
        const __nv_bfloat16* __restrict__ Whib, const __nv_bfloat16* __restrict__ Wlob,
        size_t sW,
        float* __restrict__ Cb, int ldc, size_t sC,
        int M, int N, int K,
        const float* __restrict__ biasb, size_t sBias,
        const float* __restrict__ aux,
        __nv_bfloat16* __restrict__ ehi, __nv_bfloat16* __restrict__ elo) {
    constexpr int ST = 3;
    __shared__ uint4 AhS[ST][256], AlS[ST][256], BhS[ST][256], BlS[ST][256];

    const int t    = threadIdx.x;
    const int lane = t & 31;
    const int w    = t >> 5;
    const int wm   = (w & 1) * 64;
    const int wn   = (w >> 1) * 32;
    const int g    = lane >> 2;
    const int tg   = lane & 3;

    const int m0  = blockIdx.y * 128;
    const int n0  = blockIdx.x * 128;
    const int dir = blockIdx.z;

    const __nv_bfloat16* Ahi = Ahib + (size_t)dir * sA;
    const __nv_bfloat16* Alo = Alob + (size_t)dir * sA;
    const __nv_bfloat16* Whi = Whib + (size_t)dir * sW;
    const __nv_bfloat16* Wlo = Wlob + (size_t)dir * sW;
    float* C = Cb + (size_t)dir * sC;
    const float* bias = biasb ? biasb + (size_t)dir * sBias : nullptr;

    // staging: thread t -> (row t>>1, chunk t&1) for each of the 4 arrays
    const int srow = t >> 1;
    const int sko  = (t & 1) * 8;
    const int gm   = m0 + srow;
    const bool av  = gm < M;
    const int gmc  = av ? gm : 0;
    const int gn   = n0 + srow;                   // always < N (N % 128 == 0)
    const __nv_bfloat16* aph = Ahi + (size_t)gmc * ldaK + sko;
    const __nv_bfloat16* apl = Alo + (size_t)gmc * ldaK + sko;
    const __nv_bfloat16* bph = Whi + (size_t)gn * K + sko;
    const __nv_bfloat16* bpl = Wlo + (size_t)gn * K + sko;
    const int asz = av ? 16 : 0;

    const uint32_t sOff = (uint32_t)(swz(srow, t & 1) * 16);
    const uint32_t bAh = (uint32_t)__cvta_generic_to_shared(&AhS[0][0]);
    const uint32_t bAl = (uint32_t)__cvta_generic_to_shared(&AlS[0][0]);
    const uint32_t bBh = (uint32_t)__cvta_generic_to_shared(&BhS[0][0]);
    const uint32_t bBl = (uint32_t)__cvta_generic_to_shared(&BlS[0][0]);

    auto issue = [&](int kt) {
        int s  = kt % ST;
        int k0 = kt * 16;
        uint32_t so = s * 4096 + sOff;
        cp16(bAh + so, aph + k0, asz);
        cp16(bAl + so, apl + k0, asz);
        cp16(bBh + so, bph + k0, 16);
        cp16(bBl + so, bpl + k0, 16);
        CP_COMMIT();
    };

    // ldmatrix lane maps (precompute per-fragment byte offsets within a stage)
    const int a_r = lane & 15;
    const int a_c = lane >> 4;
    const int b_r = (lane & 7) + ((lane & 16) ? 8 : 0);
    const int b_c = (lane >> 3) & 1;
    uint32_t offA[4];
#pragma unroll
    for (int i = 0; i < 4; i++)
        offA[i] = (uint32_t)(swz(wm + i * 16 + a_r, a_c) * 16);
    const uint32_t offB0 = (uint32_t)(swz(wn + b_r,      b_c) * 16);
    const uint32_t offB1 = (uint32_t)(swz(wn + 16 + b_r, b_c) * 16);

    float acc[4][4][4];
#pragma unroll
    for (int i = 0; i < 4; i++)
#pragma unroll
        for (int j = 0; j < 4; j++)
#pragma unroll
            for (int r = 0; r < 4; r++) acc[i][j][r] = 0.f;

    const int nk = K / 16;
    issue(0);
    if (nk > 1) issue(1);

    for (int kt = 0; kt < nk; kt++) {
        if (kt + 1 < nk)
            asm volatile("cp.async.wait_group 1;" ::: "memory");
        else
            asm volatile("cp.async.wait_group 0;" ::: "memory");
        __syncthreads();

        const uint32_t stg = (uint32_t)((kt % ST) * 4096);
        uint32_t ah[4][4], al[4][4], bh[8], bl[8];
        ldsm_x4(bh[0], bh[1], bh[2], bh[3], bBh + stg + offB0);
        ldsm_x4(bh[4], bh[5], bh[6], bh[7], bBh + stg + offB1);
        ldsm_x4(bl[0], bl[1], bl[2], bl[3], bBl + stg + offB0);
        ldsm_x4(bl[4], bl[5], bl[6], bl[7], bBl + stg + offB1);
#pragma unroll
        for (int i = 0; i < 4; i++) {
            ldsm_x4(ah[i][0], ah[i][1], ah[i][2], ah[i][3], bAh + stg + offA[i]);
            ldsm_x4(al[i][0], al[i][1], al[i][2], al[i][3], bAl + stg + offA[i]);
        }

#pragma unroll
        for (int j = 0; j < 4; j++) {
            uint32_t b0h = bh[j * 2], b1h = bh[j * 2 + 1];
            uint32_t b0l = bl[j * 2], b1l = bl[j * 2 + 1];
#pragma unroll
            for (int i = 0; i < 4; i++) {
                mma_bf16(acc[i][j], ah[i][0], ah[i][1], ah[i][2], ah[i][3], b0h, b1h);
                mma_bf16(acc[i][j], ah[i][0], ah[i][1], ah[i][2], ah[i][3], b0l, b1l);
                mma_bf16(acc[i][j], al[i][0], al[i][1], al[i][2], al[i][3], b0h, b1h);
            }
        }

        __syncthreads();           // all warps done reading stage before refill
        if (kt + 2 < nk) issue(kt + 2);
    }

    auto emit = [&](int m, int n, float v) {
        if (m >= M || n >= N) return;
        if (EPI == EPI_STORE) {
            C[(size_t)m * ldc + n] = v;
        } else if (EPI == EPI_SOFTPLUS) {
            v += bias[n];
            C[(size_t)m * ldc + n] = (v > 20.f) ? v : log1pf(__expf(v));
        } else if (EPI == EPI_RESID) {
            int b = m / LL, l = m - b * LL;
            int lo_ = map_row(l, dir);
            int row = b * LL + lo_;
            size_t idx = ((size_t)row * 2 + dir) * CM + n;
            float val = aux[(size_t)row * CM + n] + v;
            C[idx] = val;
            __nv_bfloat16 h = __float2bfloat16(val);
            ehi[idx] = h;
            elo[idx] = __float2bfloat16(val - __bfloat162float(h));
        } else if (EPI == EPI_GATE) {
            float gg = sigmoidf_(v + bias[n]);
            float of = aux[(size_t)m * (2 * CM) + n];
            float ob = aux[(size_t)m * (2 * CM) + CM + n];
            float val = gg * of + (1.f - gg) * ob;
            size_t idx = (size_t)m * ldc + n;
            __nv_bfloat16 h = __float2bfloat16(val);
            ehi[idx] = h;
            elo[idx] = __float2bfloat16(val - __bfloat162float(h));
        } else {
            C[(size_t)m * ldc + n] = v + bias[n];
        }
    };

#pragma unroll
    for (int i = 0; i < 4; i++) {
        int mr = m0 + wm + i * 16 + g;
#pragma unroll
        for (int j = 0; j < 4; j++) {
            int nc = n0 + wn + j * 8 + 2 * tg;
            emit(mr,     nc,     acc[i][j][0]);
            emit(mr,     nc + 1, acc[i][j][1]);
            emit(mr + 8, nc,     acc[i][j][2]);
            emit(mr + 8, nc + 1, acc[i][j][3]);
        }
    }
}

// ---------------------------------------------------------------------------
// SIMT split-K GEMM for the skinny x_proj (N=80)
// ---------------------------------------------------------------------------
template <int TM, int TN, int TK, int KS>
__global__ void __launch_bounds__(256, 2)
gemm_splitk(const float* __restrict__ Ab, int lda, size_t sA,
            const float* __restrict__ Wb, size_t sW,
            float* __restrict__ Cb, int ldc, size_t sC,
            int M, int N, int K) {
    constexpr int RM = TM / 16;
    constexpr int RN = TN / 16;
    constexpr int A4 = TM * TK / 4;
    constexpr int B4 = TN * TK / 4;
    constexpr int RA = (A4 + 255) / 256;
    constexpr int RB = (B4 + 255) / 256;

    __shared__ float As[2][TK][TM + 4];
    __shared__ float Bs[2][TK][TN + 4];

    const int t  = threadIdx.x;
    const int tx = t & 15;
    const int ty = t >> 4;
    const int m0 = blockIdx.y * TM;
    const int n0 = blockIdx.x * TN;

    const int z = blockIdx.z;
    const int dir   = z / KS;
    const int split = z % KS;

    const float* A = Ab + (size_t)dir * sA;
    const float* W = Wb + (size_t)dir * sW;
    float*       C = Cb + (size_t)dir * sC;

    const int Kpart = K / KS;
    const int kbeg  = split * Kpart;
    const int nk    = Kpart / TK;

    float4 ra[RA], rb[RB];

    auto gload = [&](int k0) {
#pragma unroll
        for (int i = 0; i < RA; i++) {
            int idx = t + i * 256;
            float4 v = make_float4(0.f, 0.f, 0.f, 0.f);
            if (idx < A4) {
                int m = idx / (TK / 4), kq = idx % (TK / 4);
                int gm = m0 + m;
                if (gm < M) v = *(const float4*)&A[(size_t)gm * lda + k0 + kq * 4];
            }
            ra[i] = v;
        }
#pragma unroll
        for (int i = 0; i < RB; i++) {
            int idx = t + i * 256;
            float4 v = make_float4(0.f, 0.f, 0.f, 0.f);
            if (idx < B4) {
                int n = idx / (TK / 4), kq = idx % (TK / 4);
                int gn = n0 + n;
                if (gn < N) v = *(const float4*)&W[(size_t)gn * K + k0 + kq * 4];
            }
            rb[i] = v;
        }
    };
    auto sstore = [&](int s) {
#pragma unroll
        for (int i = 0; i < RA; i++) {
            int idx = t + i * 256;
            if (idx < A4) {
                int m = idx / (TK / 4), kq = (idx % (TK / 4)) * 4;
                As[s][kq + 0][m] = ra[i].x; As[s][kq + 1][m] = ra[i].y;
                As[s][kq + 2][m] = ra[i].z; As[s][kq + 3][m] = ra[i].w;
            }
        }
#pragma unroll
        for (int i = 0; i < RB; i++) {
            int idx = t + i * 256;
            if (idx < B4) {
                int n = idx / (TK / 4), kq = (idx % (TK / 4)) * 4;
                Bs[s][kq + 0][n] = rb[i].x; Bs[s][kq + 1][n] = rb[i].y;
                Bs[s][kq + 2][n] = rb[i].z; Bs[s][kq + 3][n] = rb[i].w;
            }
        }
    };

    float acc[RM][RN];
#pragma unroll
    for (int i = 0; i < RM; i++)
#pragma unroll
        for (int j = 0; j < RN; j++) acc[i][j] = 0.f;

    gload(kbeg);
    sstore(0);
    __syncthreads();

    int cur = 0;
    for (int kt = 0; kt < nk; kt++) {
        if (kt + 1 < nk) gload(kbeg + (kt + 1) * TK);
#pragma unroll
        for (int k = 0; k < TK; k++) {
            float af[RM], bf[RN];
#pragma unroll
            for (int i = 0; i < RM; i++) af[i] = As[cur][k][ty * RM + i];
#pragma unroll
            for (int j = 0; j < RN; j++) bf[j] = Bs[cur][k][tx * RN + j];
#pragma unroll
            for (int i = 0; i < RM; i++)
#pragma unroll
                for (int j = 0; j < RN; j++)
                    acc[i][j] = fmaf(af[i], bf[j], acc[i][j]);
        }
        __syncthreads();
        if (kt + 1 < nk) {
            sstore(cur ^ 1);
            __syncthreads();
            cur ^= 1;
        }
    }

#pragma unroll
    for (int i = 0; i < RM; i++) {
        int m = m0 + ty * RM + i;
        if (m >= M) continue;
#pragma unroll
        for (int j = 0; j < RN; j++) {
            int n = n0 + tx * RN + j;
            if (n >= N) continue;
            atomicAdd(&C[(size_t)m * ldc + n], acc[i][j]);
        }
    }
}

// ---------------------------------------------------------------------------
__global__ void conv_silu_kernel(const float* __restrict__ conv_w,
                                 const float* __restrict__ conv_b) {
    int idx = blockIdx.x * blockDim.x + threadIdx.x;
    if (idx >= 2 * MM * DI) return;
    int d = idx % DI;
    int r = idx / DI;
    int dir = r / MM;
    int l = r % LL;

    const float* w = conv_w + (size_t)(dir * DI + d) * DCONV;
    float acc = conv_b[dir * DI + d];
#pragma unroll
    for (int j = 0; j < DCONV; j++) {
        int ls = l - (DCONV - 1) + j;
        if (ls >= 0)
            acc = fmaf(w[j], g_xz[(size_t)(r - (DCONV - 1) + j) * (2 * DI) + d], acc);
    }
    g_xb[(size_t)r * DI + d] = siluf_(acc);
}

// ---------------------------------------------------------------------------
// scan: writes y*silu(z) as bf16 hi/lo into g_ahi/g_alo (stride DI)
// ---------------------------------------------------------------------------
__global__ void __launch_bounds__(128, 8)
scan_kernel(const float* __restrict__ Dp) {
    int d   = blockIdx.x * blockDim.x + threadIdx.x;
    int b   = blockIdx.y;
    int dir = blockIdx.z;
    if (d >= DI) return;

    const float* Arow = &g_A[(dir * DI + d) * DS];
    float a0 = Arow[0];
    float da = Arow[1] - Arow[0];
    float Ar[DS];
    bool arith = (g_arith != 0);
    if (!arith) {
#pragma unroll
        for (int n = 0; n < DS; n++) Ar[n] = Arow[n];
    }

    float h[DS];
#pragma unroll
    for (int n = 0; n < DS; n++) h[n] = 0.f;

    float Dd = Dp[dir * DI + d];
    size_t r0 = (size_t)dir * MM + (size_t)b * LL;

    for (int l = 0; l < LL; l++) {
        size_t r = r0 + l;
        float u  = g_xb[r * DI + d];
        float dt = g_dt[r * DI + d];
        const float4* BC = (const float4*)(&g_xdbl[r * 80 + DR]);
        float4 Bv0 = __ldg(&BC[0]), Bv1 = __ldg(&BC[1]);
        float4 Bv2 = __ldg(&BC[2]), Bv3 = __ldg(&BC[3]);
        float4 Cv0 = __ldg(&BC[4]), Cv1 = __ldg(&BC[5]);
        float4 Cv2 = __ldg(&BC[6]), Cv3 = __ldg(&BC[7]);
        float Bl[DS] = {Bv0.x, Bv0.y, Bv0.z, Bv0.w, Bv1.x, Bv1.y, Bv1.z, Bv1.w,
                        Bv2.x, Bv2.y, Bv2.z, Bv2.w, Bv3.x, Bv3.y, Bv3.z, Bv3.w};
        float Cl[DS] = {Cv0.x, Cv0.y, Cv0.z, Cv0.w, Cv1.x, Cv1.y, Cv1.z, Cv1.w,
                        Cv2.x, Cv2.y, Cv2.z, Cv2.w, Cv3.x, Cv3.y, Cv3.z, Cv3.w};

        float du = dt * u;
        float yv = 0.f;
        if (arith) {
            float p  = __expf(dt * a0);
            float rr = __expf(dt * da);
#pragma unroll
            for (int n = 0; n < DS; n++) {
                h[n] = fmaf(p, h[n], du * Bl[n]);
                yv   = fmaf(h[n], Cl[n], yv);
                p *= rr;
            }
        } else {
#pragma unroll
            for (int n = 0; n < DS; n++) {
                float p = __expf(dt * Ar[n]);
                h[n] = fmaf(p, h[n], du * Bl[n]);
                yv   = fmaf(h[n], Cl[n], yv);
            }
        }
        yv = fmaf(u, Dd, yv);
        float z = g_xz[r * (2 * DI) + DI + d];
        float val = yv * siluf_(z);
        __nv_bfloat16 hv = __float2bfloat16(val);
        g_ahi[r * DI + d] = hv;
        g_alo[r * DI + d] = __float2bfloat16(val - __bfloat162float(hv));
    }
}

// ---------------------------------------------------------------------------
extern "C" void kernel_launch(void* const* d_in, const int* in_sizes, int n_in,
                              void* d_out, int out_size) {
    const float* x         = (const float*)d_in[0];
    const float* norm_w    = (const float*)d_in[1];
    const float* in_proj_w = (const float*)d_in[2];
    const float* conv_w    = (const float*)d_in[3];
    const float* conv_b    = (const float*)d_in[4];
    const float* x_proj_w  = (const float*)d_in[5];
    const float* dt_proj_w = (const float*)d_in[6];
    const float* dt_proj_b = (const float*)d_in[7];
    const float* A_log     = (const float*)d_in[8];
    const float* Dp        = (const float*)d_in[9];
    const float* mix_out_w = (const float*)d_in[10];
    const float* gate_w    = (const float*)d_in[11];
    const float* gate_b    = (const float*)d_in[12];
    const float* proj_w    = (const float*)d_in[13];
    const float* proj_b    = (const float*)d_in[14];
    float* out = (float*)d_out;

    float *xz, *xb, *xdbl, *dt, *o_out;
    __nv_bfloat16 *ahi, *alo, *bhi, *blo, *whi, *wlo;
    cudaGetSymbolAddress((void**)&xz,    g_xz);
    cudaGetSymbolAddress((void**)&xb,    g_xb);
    cudaGetSymbolAddress((void**)&xdbl,  g_xdbl);
    cudaGetSymbolAddress((void**)&dt,    g_dt);
    cudaGetSymbolAddress((void**)&o_out, g_out);
    cudaGetSymbolAddress((void**)&ahi,   g_ahi);
    cudaGetSymbolAddress((void**)&alo,   g_alo);
    cudaGetSymbolAddress((void**)&bhi,   g_bhi);
    cudaGetSymbolAddress((void**)&blo,   g_blo);
    cudaGetSymbolAddress((void**)&whi,   g_whi);
    cudaGetSymbolAddress((void**)&wlo,   g_wlo);

    auto splitw = [&](const float* src, int stride, int K, long rows) {
        long tot = rows * (long)K;
        split_arr<<<(unsigned)((tot + 255) / 256), 256>>>(src, stride, K, whi, wlo, rows);
    };

    setup_A_kernel<<<(2 * DI * DS + 255) / 256, 256>>>(A_log);
    check_arith_kernel<<<1, 256>>>();

    const int MY = (MM + 127) / 128;   // 13

    // in_proj: A from rmsnorm (hi/lo), W split
    rmsnorm_kernel<<<2 * MM, 256>>>(x, norm_w);
    splitw(in_proj_w, CM, CM, 2L * 2 * DI);
    gemm_as<EPI_STORE><<<dim3(2 * DI / 128, MY, 2), 256>>>(
        ahi, alo, CM, (size_t)MM * CM,
        whi, wlo, (size_t)2 * DI * CM,
        xz, 2 * DI, (size_t)MM * 2 * DI,
        MM, 2 * DI, CM, nullptr, 0, nullptr, nullptr, nullptr);

    conv_silu_kernel<<<(2 * MM * DI + 255) / 256, 256>>>(conv_w, conv_b);

    // x_proj: SIMT split-K fp32
    cudaMemsetAsync(xdbl, 0, sizeof(float) * 2 * MM * 80);
    gemm_splitk<128, 80, 16, 8><<<dim3(1, MY, 2 * 8), 256>>>(
        xb, DI, (size_t)MM * DI,
        x_proj_w, (size_t)80 * DI,
        xdbl, 80, (size_t)MM * 80,
        MM, 80, DI);

    // dt_proj + softplus: A = first 48 cols of xdbl (split), K=48
    {
        long tot = 2L * MM * DR;
        split_arr<<<(unsigned)((tot + 255) / 256), 256>>>(xdbl, 80, DR, ahi, alo, 2L * MM);
    }
    splitw(dt_proj_w, DR, DR, 2L * DI);
    gemm_as<EPI_SOFTPLUS><<<dim3(DI / 128, MY, 2), 256>>>(
        ahi, alo, DR, (size_t)MM * DR,
        whi, wlo, (size_t)DI * DR,
        dt, DI, (size_t)MM * DI,
        MM, DI, DR, dt_proj_b, DI, nullptr, nullptr, nullptr);

    // scan -> ahi/alo (stride DI)
    scan_kernel<<<dim3(DI / 128, BB, 2), 128>>>(Dp);

    // out_proj + residual + flip-scatter; epilogue splits into bhi/blo
    splitw(mix_out_w, DI, DI, 2L * CM);
    gemm_as<EPI_RESID><<<dim3(CM / 128, MY, 2), 256>>>(
        ahi, alo, DI, (size_t)MM * DI,
        whi, wlo, (size_t)CM * DI,
        o_out, 0, 0,
        MM, CM, DI, nullptr, 0, x, bhi, blo);

    // gate GEMM + sigmoid combine; epilogue splits comb into ahi/alo
    splitw(gate_w, 2 * CM, 2 * CM, (long)CM);
    gemm_as<EPI_GATE><<<dim3(CM / 128, MY, 1), 256>>>(
        bhi, blo, 2 * CM, 0,
        whi, wlo, 0,
        nullptr, CM, 0,
        MM, CM, 2 * CM, gate_b, 0, o_out, ahi, alo);

    // final projection + bias
    splitw(proj_w, CM, CM, (long)CM);
    gemm_as<EPI_BIAS><<<dim3(CM / 128, MY, 1), 256>>>(
        ahi, alo, CM, 0,
        whi, wlo, 0,
        out, CM, 0,
        MM, CM, CM, proj_b, 0, nullptr, nullptr, nullptr);

    (void)in_sizes; (void)n_in; (void)out_size;
}

// round 10
// speedup vs baseline: 1.0462x; 1.0462x over previous
#include <cuda_runtime.h>
#include <cuda_bf16.h>
#include <cstdint>

// ---------------------------------------------------------------------------
// BiMamba refiner block, round 9: R7 bf16x2 MMA base + BM-templated tiles so
// the tail GEMMs (out_proj/gate/final) fill the chip; wider scan grid.
// ---------------------------------------------------------------------------

#define BB      2
#define TT      4
#define NP      196
#define LL      784
#define MM      1568
#define CM      768
#define DI      1536
#define DS      16
#define DR      48
#define DCONV   4

// ---------------- scratch ---------------------------------------------------
__device__ float g_xn  [2 * MM * CM];
__device__ float g_xz  [2 * MM * 2 * DI];
__device__ float g_xb  [2 * MM * DI];
__device__ float g_xdbl[2 * MM * 80];
__device__ float g_dt  [2 * MM * DI];
__device__ float g_y   [2 * MM * DI];
__device__ float g_out [MM * 2 * CM];
__device__ float g_comb[MM * CM];
__device__ float g_A   [2 * DI * DS];
__device__ int   g_arith;

__device__ __forceinline__ int map_row(int l, int dir) {
    if (dir == 0) return l;
    int t = l / NP, n = l - t * NP;
    return (TT - 1 - t) * NP + n;
}
__device__ __forceinline__ float sigmoidf_(float v) { return 1.0f / (1.0f + __expf(-v)); }
__device__ __forceinline__ float siluf_(float v)    { return v * sigmoidf_(v); }

// pack two floats into bf16x2 hi and lo residual
__device__ __forceinline__ void split2(float x, float y, uint32_t& hi, uint32_t& lo) {
    __nv_bfloat16 hx = __float2bfloat16(x);
    __nv_bfloat16 hy = __float2bfloat16(y);
    __nv_bfloat16 lx = __float2bfloat16(x - __bfloat162float(hx));
    __nv_bfloat16 ly = __float2bfloat16(y - __bfloat162float(hy));
    __nv_bfloat162 h2 = __halves2bfloat162(hx, hy);
    __nv_bfloat162 l2 = __halves2bfloat162(lx, ly);
    hi = *reinterpret_cast<uint32_t*>(&h2);
    lo = *reinterpret_cast<uint32_t*>(&l2);
}

__device__ __forceinline__ void mma_bf16(float c[4],
                                         uint32_t a0, uint32_t a1, uint32_t a2, uint32_t a3,
                                         uint32_t b0, uint32_t b1) {
    asm volatile(
        "mma.sync.aligned.m16n8k16.row.col.f32.bf16.bf16.f32 "
        "{%0,%1,%2,%3},{%4,%5,%6,%7},{%8,%9},{%0,%1,%2,%3};"
        : "+f"(c[0]), "+f"(c[1]), "+f"(c[2]), "+f"(c[3])
        : "r"(a0), "r"(a1), "r"(a2), "r"(a3), "r"(b0), "r"(b1));
}

__device__ __forceinline__ void ldsm_x4(uint32_t& r0, uint32_t& r1, uint32_t& r2,
                                        uint32_t& r3, uint32_t addr) {
    asm volatile("ldmatrix.sync.aligned.m8n8.x4.shared.b16 {%0,%1,%2,%3}, [%4];"
                 : "=r"(r0), "=r"(r1), "=r"(r2), "=r"(r3) : "r"(addr));
}

// swizzled 16B-chunk index for (row, chunk) in a [rows][2-chunk] tile
__device__ __forceinline__ int swz(int row, int chunk) {
    return row * 2 + (chunk ^ ((row >> 2) & 1));
}

// ---------------------------------------------------------------------------
__global__ void setup_A_kernel(const float* __restrict__ A_log) {
    int i = blockIdx.x * blockDim.x + threadIdx.x;
    if (i < 2 * DI * DS) g_A[i] = -expf(A_log[i]);
}

__global__ void check_arith_kernel() {
    __shared__ int bad;
    if (threadIdx.x == 0) bad = 0;
    __syncthreads();
    for (int row = threadIdx.x; row < 2 * DI; row += blockDim.x) {
        const float* a = &g_A[row * DS];
        float a0 = a[0], da = a[1] - a[0];
        for (int n = 2; n < DS; n++) {
            float expect = a0 + n * da;
            if (fabsf(a[n] - expect) > 1e-4f * (1.0f + fabsf(a[n]))) { bad = 1; break; }
        }
    }
    __syncthreads();
    if (threadIdx.x == 0) g_arith = bad ? 0 : 1;
}

__global__ void rmsnorm_kernel(const float* __restrict__ x,
                               const float* __restrict__ norm_w) {
    int gid = blockIdx.x;
    int dir = gid / MM;
    int rem = gid - dir * MM;
    int b   = rem / LL, l = rem - b * LL;
    int lo  = map_row(l, dir);
    const float* row = x + (size_t)(b * LL + lo) * CM;

    float s = 0.f;
    for (int c = threadIdx.x; c < CM; c += blockDim.x) {
        float v = row[c];
        s += v * v;
    }
    __shared__ float warp_s[8];
    for (int off = 16; off > 0; off >>= 1) s += __shfl_down_sync(0xffffffffu, s, off);
    if ((threadIdx.x & 31) == 0) warp_s[threadIdx.x >> 5] = s;
    __syncthreads();
    if (threadIdx.x < 8) {
        float t = warp_s[threadIdx.x];
        for (int off = 4; off > 0; off >>= 1) t += __shfl_down_sync(0xffu, t, off);
        if (threadIdx.x == 0) warp_s[0] = t;
    }
    __syncthreads();
    float scale = rsqrtf(warp_s[0] / (float)CM + 1e-5f);

    float* dst = g_xn + (size_t)gid * CM;
    const float* nw = norm_w + dir * CM;
    for (int c = threadIdx.x; c < CM; c += blockDim.x)
        dst[c] = row[c] * scale * nw[c];
}

// ---------------------------------------------------------------------------
// bf16x2 tensor-core GEMM with ldmatrix: C[M,N] = A[M,K] * W[N,K]^T
// BM templated (128 or 64), BN=128, BK=16. 8 warps (2m x 4n),
// warp tile (BM/2)x32, MI = BM/32 m-frags per warp.
// ---------------------------------------------------------------------------
#define EPI_STORE    0
#define EPI_SOFTPLUS 1
#define EPI_RESID    2
#define EPI_GATE     3
#define EPI_BIAS     4

template <int BM, int EPI>
__global__ void __launch_bounds__(256)
gemm_bf16x2(const float* __restrict__ Ab, int lda, size_t sA,
            const float* __restrict__ Wb, size_t sW,
            float* __restrict__ Cb, int ldc, size_t sC,
            int M, int N, int K,
            const float* __restrict__ biasb, size_t sBias,
            const float* __restrict__ aux) {
    constexpr int BN = 128;
    constexpr int NF = 4;
    constexpr int MI = BM / 32;          // m-frags per warp

    __shared__ uint4 AhS[2][BM * 2], AlS[2][BM * 2];
    __shared__ uint4 BhS[2][BN * 2], BlS[2][BN * 2];

    const int t    = threadIdx.x;
    const int lane = t & 31;
    const int w    = t >> 5;
    const int wm   = (w & 1) * (BM / 2);
    const int wn   = (w >> 1) * 32;
    const int g    = lane >> 2;
    const int tg   = lane & 3;

    const int m0  = blockIdx.y * BM;
    const int n0  = blockIdx.x * BN;
    const int dir = blockIdx.z;

    const float* A = Ab + (size_t)dir * sA;
    const float* W = Wb + (size_t)dir * sW;
    float*       C = Cb + (size_t)dir * sC;
    const float* bias = biasb ? biasb + (size_t)dir * sBias : nullptr;

    // staging: thread t -> (row t>>1, chunk t&1); A only if t < BM*2
    const int srow = t >> 1;
    const int skh  = (t & 1) * 8;
    const bool doA = (t < BM * 2);

    float4 ra0, ra1, rb0, rb1;
    auto gload = [&](int k0) {
        if (doA) {
            int gm = m0 + srow;
            if (gm < M) {
                ra0 = *(const float4*)&A[(size_t)gm * lda + k0 + skh];
                ra1 = *(const float4*)&A[(size_t)gm * lda + k0 + skh + 4];
            } else {
                ra0 = make_float4(0.f, 0.f, 0.f, 0.f); ra1 = ra0;
            }
        }
        int gn = n0 + srow;
        if (gn < N) {
            rb0 = *(const float4*)&W[(size_t)gn * K + k0 + skh];
            rb1 = *(const float4*)&W[(size_t)gn * K + k0 + skh + 4];
        } else {
            rb0 = make_float4(0.f, 0.f, 0.f, 0.f); rb1 = rb0;
        }
    };
    auto sstore = [&](int s) {
        uint4 h4, l4;
        if (doA) {
            split2(ra0.x, ra0.y, h4.x, l4.x);
            split2(ra0.z, ra0.w, h4.y, l4.y);
            split2(ra1.x, ra1.y, h4.z, l4.z);
            split2(ra1.z, ra1.w, h4.w, l4.w);
            int ai = swz(srow, t & 1);
            AhS[s][ai] = h4; AlS[s][ai] = l4;
        }
        split2(rb0.x, rb0.y, h4.x, l4.x);
        split2(rb0.z, rb0.w, h4.y, l4.y);
        split2(rb1.x, rb1.y, h4.z, l4.z);
        split2(rb1.z, rb1.w, h4.w, l4.w);
        int bi = swz(srow, t & 1);
        BhS[s][bi] = h4; BlS[s][bi] = l4;
    };

    // ldmatrix lane->(row,chunk) maps
    const int a_r = lane & 15;
    const int a_c = lane >> 4;
    const int b_r = (lane & 7) + ((lane & 16) ? 8 : 0);
    const int b_c = (lane >> 3) & 1;

    const uint32_t baseAh = (uint32_t)__cvta_generic_to_shared(&AhS[0][0]);
    const uint32_t baseAl = (uint32_t)__cvta_generic_to_shared(&AlS[0][0]);
    const uint32_t baseBh = (uint32_t)__cvta_generic_to_shared(&BhS[0][0]);
    const uint32_t baseBl = (uint32_t)__cvta_generic_to_shared(&BlS[0][0]);
    const uint32_t strideA = BM * 2 * 16;
    const uint32_t strideB = BN * 2 * 16;

    float acc[MI][NF][4];
#pragma unroll
    for (int i = 0; i < MI; i++)
#pragma unroll
        for (int j = 0; j < NF; j++)
#pragma unroll
            for (int r = 0; r < 4; r++) acc[i][j][r] = 0.f;

    const int nk = K / 16;
    gload(0);
    sstore(0);
    __syncthreads();

    int cur = 0;
    for (int kt = 0; kt < nk; kt++) {
        if (kt + 1 < nk) gload((kt + 1) * 16);

        uint32_t ah[MI][4], al[MI][4];
        uint32_t bh[8], bl[8];
        {
            uint32_t off0 = (uint32_t)(swz(wn + b_r,      b_c) * 16);
            uint32_t off1 = (uint32_t)(swz(wn + 16 + b_r, b_c) * 16);
            ldsm_x4(bh[0], bh[1], bh[2], bh[3], baseBh + cur * strideB + off0);
            ldsm_x4(bh[4], bh[5], bh[6], bh[7], baseBh + cur * strideB + off1);
            ldsm_x4(bl[0], bl[1], bl[2], bl[3], baseBl + cur * strideB + off0);
            ldsm_x4(bl[4], bl[5], bl[6], bl[7], baseBl + cur * strideB + off1);
        }
#pragma unroll
        for (int i = 0; i < MI; i++) {
            int row = wm + i * 16 + a_r;
            uint32_t off = (uint32_t)(swz(row, a_c) * 16);
            ldsm_x4(ah[i][0], ah[i][1], ah[i][2], ah[i][3], baseAh + cur * strideA + off);
            ldsm_x4(al[i][0], al[i][1], al[i][2], al[i][3], baseAl + cur * strideA + off);
        }

#pragma unroll
        for (int j = 0; j < NF; j++) {
            uint32_t b0h = bh[j * 2], b1h = bh[j * 2 + 1];
            uint32_t b0l = bl[j * 2], b1l = bl[j * 2 + 1];
#pragma unroll
            for (int i = 0; i < MI; i++) {
                mma_bf16(acc[i][j], ah[i][0], ah[i][1], ah[i][2], ah[i][3], b0h, b1h);
                mma_bf16(acc[i][j], ah[i][0], ah[i][1], ah[i][2], ah[i][3], b0l, b1l);
                mma_bf16(acc[i][j], al[i][0], al[i][1], al[i][2], al[i][3], b0h, b1h);
            }
        }

        if (kt + 1 < nk) sstore(cur ^ 1);
        __syncthreads();
        cur ^= 1;
    }

    auto emit = [&](int m, int n, float v) {
        if (m >= M || n >= N) return;
        if (EPI == EPI_STORE) {
            C[(size_t)m * ldc + n] = v;
        } else if (EPI == EPI_SOFTPLUS) {
            v += bias[n];
            C[(size_t)m * ldc + n] = (v > 20.f) ? v : log1pf(__expf(v));
        } else if (EPI == EPI_RESID) {
            int b = m / LL, l = m - b * LL;
            int lo = map_row(l, dir);
            int row = b * LL + lo;
            C[((size_t)row * 2 + dir) * CM + n] = aux[(size_t)row * CM + n] + v;
        } else if (EPI == EPI_GATE) {
            float gg = sigmoidf_(v + bias[n]);
            float of = aux[(size_t)m * (2 * CM) + n];
            float ob = aux[(size_t)m * (2 * CM) + CM + n];
            C[(size_t)m * ldc + n] = gg * of + (1.f - gg) * ob;
        } else {
            C[(size_t)m * ldc + n] = v + bias[n];
        }
    };

#pragma unroll
    for (int i = 0; i < MI; i++) {
        int mr = m0 + wm + i * 16 + g;
#pragma unroll
        for (int j = 0; j < NF; j++) {
            int nc = n0 + wn + j * 8 + 2 * tg;
            emit(mr,     nc,     acc[i][j][0]);
            emit(mr,     nc + 1, acc[i][j][1]);
            emit(mr + 8, nc,     acc[i][j][2]);
            emit(mr + 8, nc + 1, acc[i][j][3]);
        }
    }
}

// ---------------------------------------------------------------------------
// SIMT split-K GEMM for the skinny x_proj (N=80)
// ---------------------------------------------------------------------------
template <int TM, int TN, int TK, int KS>
__global__ void __launch_bounds__(256, 2)
gemm_splitk(const float* __restrict__ Ab, int lda, size_t sA,
            const float* __restrict__ Wb, size_t sW,
            float* __restrict__ Cb, int ldc, size_t sC,
            int M, int N, int K) {
    constexpr int RM = TM / 16;
    constexpr int RN = TN / 16;
    constexpr int A4 = TM * TK / 4;
    constexpr int B4 = TN * TK / 4;
    constexpr int RA = (A4 + 255) / 256;
    constexpr int RB = (B4 + 255) / 256;

    __shared__ float As[2][TK][TM + 4];
    __shared__ float Bs[2][TK][TN + 4];

    const int t  = threadIdx.x;
    const int tx = t & 15;
    const int ty = t >> 4;
    const int m0 = blockIdx.y * TM;
    const int n0 = blockIdx.x * TN;

    const int z = blockIdx.z;
    const int dir   = z / KS;
    const int split = z % KS;

    const float* A = Ab + (size_t)dir * sA;
    const float* W = Wb + (size_t)dir * sW;
    float*       C = Cb + (size_t)dir * sC;

    const int Kpart = K / KS;
    const int kbeg  = split * Kpart;
    const int nk    = Kpart / TK;

    float4 ra[RA], rb[RB];

    auto gload = [&](int k0) {
#pragma unroll
        for (int i = 0; i < RA; i++) {
            int idx = t + i * 256;
            float4 v = make_float4(0.f, 0.f, 0.f, 0.f);
            if (idx < A4) {
                int m = idx / (TK / 4), kq = idx % (TK / 4);
                int gm = m0 + m;
                if (gm < M) v = *(const float4*)&A[(size_t)gm * lda + k0 + kq * 4];
            }
            ra[i] = v;
        }
#pragma unroll
        for (int i = 0; i < RB; i++) {
            int idx = t + i * 256;
            float4 v = make_float4(0.f, 0.f, 0.f, 0.f);
            if (idx < B4) {
                int n = idx / (TK / 4), kq = idx % (TK / 4);
                int gn = n0 + n;
                if (gn < N) v = *(const float4*)&W[(size_t)gn * K + k0 + kq * 4];
            }
            rb[i] = v;
        }
    };
    auto sstore = [&](int s) {
#pragma unroll
        for (int i = 0; i < RA; i++) {
            int idx = t + i * 256;
            if (idx < A4) {
                int m = idx / (TK / 4), kq = (idx % (TK / 4)) * 4;
                As[s][kq + 0][m] = ra[i].x; As[s][kq + 1][m] = ra[i].y;
                As[s][kq + 2][m] = ra[i].z; As[s][kq + 3][m] = ra[i].w;
            }
        }
#pragma unroll
        for (int i = 0; i < RB; i++) {
            int idx = t + i * 256;
            if (idx < B4) {
                int n = idx / (TK / 4), kq = (idx % (TK / 4)) * 4;
                Bs[s][kq + 0][n] = rb[i].x; Bs[s][kq + 1][n] = rb[i].y;
                Bs[s][kq + 2][n] = rb[i].z; Bs[s][kq + 3][n] = rb[i].w;
            }
        }
    };

    float acc[RM][RN];
#pragma unroll
    for (int i = 0; i < RM; i++)
#pragma unroll
        for (int j = 0; j < RN; j++) acc[i][j] = 0.f;

    gload(kbeg);
    sstore(0);
    __syncthreads();

    int cur = 0;
    for (int kt = 0; kt < nk; kt++) {
        if (kt + 1 < nk) gload(kbeg + (kt + 1) * TK);
#pragma unroll
        for (int k = 0; k < TK; k++) {
            float af[RM], bf[RN];
#pragma unroll
            for (int i = 0; i < RM; i++) af[i] = As[cur][k][ty * RM + i];
#pragma unroll
            for (int j = 0; j < RN; j++) bf[j] = Bs[cur][k][tx * RN + j];
#pragma unroll
            for (int i = 0; i < RM; i++)
#pragma unroll
                for (int j = 0; j < RN; j++)
                    acc[i][j] = fmaf(af[i], bf[j], acc[i][j]);
        }
        __syncthreads();
        if (kt + 1 < nk) {
            sstore(cur ^ 1);
            __syncthreads();
            cur ^= 1;
        }
    }

#pragma unroll
    for (int i = 0; i < RM; i++) {
        int m = m0 + ty * RM + i;
        if (m >= M) continue;
#pragma unroll
        for (int j = 0; j < RN; j++) {
            int n = n0 + tx * RN + j;
            if (n >= N) continue;
            atomicAdd(&C[(size_t)m * ldc + n], acc[i][j]);
        }
    }
}

// ---------------------------------------------------------------------------
__global__ void conv_silu_kernel(const float* __restrict__ conv_w,
                                 const float* __restrict__ conv_b) {
    int idx = blockIdx.x * blockDim.x + threadIdx.x;
    if (idx >= 2 * MM * DI) return;
    int d = idx % DI;
    int r = idx / DI;
    int dir = r / MM;
    int l = r % LL;

    const float* w = conv_w + (size_t)(dir * DI + d) * DCONV;
    float acc = conv_b[dir * DI + d];
#pragma unroll
    for (int j = 0; j < DCONV; j++) {
        int ls = l - (DCONV - 1) + j;
        if (ls >= 0)
            acc = fmaf(w[j], g_xz[(size_t)(r - (DCONV - 1) + j) * (2 * DI) + d], acc);
    }
    g_xb[(size_t)r * DI + d] = siluf_(acc);
}

// ---------------------------------------------------------------------------
// scan, 64-thread blocks (96 CTAs -> ~2x the SMs engaged vs 128-thread)
// ---------------------------------------------------------------------------
__global__ void __launch_bounds__(64, 8)
scan_kernel(const float* __restrict__ Dp) {
    int d   = blockIdx.x * blockDim.x + threadIdx.x;
    int b   = blockIdx.y;
    int dir = blockIdx.z;
    if (d >= DI) return;

    const float* Arow = &g_A[(dir * DI + d) * DS];
    float a0 = Arow[0];
    float da = Arow[1] - Arow[0];
    float Ar[DS];
    bool arith = (g_arith != 0);
    if (!arith) {
#pragma unroll
        for (int n = 0; n < DS; n++) Ar[n] = Arow[n];
    }

    float h[DS];
#pragma unroll
    for (int n = 0; n < DS; n++) h[n] = 0.f;

    float Dd = Dp[dir * DI + d];
    size_t r0 = (size_t)dir * MM + (size_t)b * LL;

    for (int l = 0; l < LL; l++) {
        size_t r = r0 + l;
        float u  = g_xb[r * DI + d];
        float dt = g_dt[r * DI + d];
        const float4* BC = (const float4*)(&g_xdbl[r * 80 + DR]);
        float4 Bv0 = __ldg(&BC[0]), Bv1 = __ldg(&BC[1]);
        float4 Bv2 = __ldg(&BC[2]), Bv3 = __ldg(&BC[3]);
        float4 Cv0 = __ldg(&BC[4]), Cv1 = __ldg(&BC[5]);
        float4 Cv2 = __ldg(&BC[6]), Cv3 = __ldg(&BC[7]);
        float Bl[DS] = {Bv0.x, Bv0.y, Bv0.z, Bv0.w, Bv1.x, Bv1.y, Bv1.z, Bv1.w,
                        Bv2.x, Bv2.y, Bv2.z, Bv2.w, Bv3.x, Bv3.y, Bv3.z, Bv3.w};
        float Cl[DS] = {Cv0.x, Cv0.y, Cv0.z, Cv0.w, Cv1.x, Cv1.y, Cv1.z, Cv1.w,
                        Cv2.x, Cv2.y, Cv2.z, Cv2.w, Cv3.x, Cv3.y, Cv3.z, Cv3.w};

        float du = dt * u;
        float yv = 0.f;
        if (arith) {
            float p  = __expf(dt * a0);
            float rr = __expf(dt * da);
#pragma unroll
            for (int n = 0; n < DS; n++) {
                h[n] = fmaf(p, h[n], du * Bl[n]);
                yv   = fmaf(h[n], Cl[n], yv);
                p *= rr;
            }
        } else {
#pragma unroll
            for (int n = 0; n < DS; n++) {
                float p = __expf(dt * Ar[n]);
                h[n] = fmaf(p, h[n], du * Bl[n]);
                yv   = fmaf(h[n], Cl[n], yv);
            }
        }
        yv = fmaf(u, Dd, yv);
        float z = g_xz[r * (2 * DI) + DI + d];
        g_y[r * DI + d] = yv * siluf_(z);
    }
}

// ---------------------------------------------------------------------------
extern "C" void kernel_launch(void* const* d_in, const int* in_sizes, int n_in,
                              void* d_out, int out_size) {
    const float* x         = (const float*)d_in[0];
    const float* norm_w    = (const float*)d_in[1];
    const float* in_proj_w = (const float*)d_in[2];
    const float* conv_w    = (const float*)d_in[3];
    const float* conv_b    = (const float*)d_in[4];
    const float* x_proj_w  = (const float*)d_in[5];
    const float* dt_proj_w = (const float*)d_in[6];
    const float* dt_proj_b = (const float*)d_in[7];
    const float* A_log     = (const float*)d_in[8];
    const float* Dp        = (const float*)d_in[9];
    const float* mix_out_w = (const float*)d_in[10];
    const float* gate_w    = (const float*)d_in[11];
    const float* gate_b    = (const float*)d_in[12];
    const float* proj_w    = (const float*)d_in[13];
    const float* proj_b    = (const float*)d_in[14];
    float* out = (float*)d_out;

    float *xn, *xz, *xb, *xdbl, *dt, *y, *o_out, *comb;
    cudaGetSymbolAddress((void**)&xn,    g_xn);
    cudaGetSymbolAddress((void**)&xz,    g_xz);
    cudaGetSymbolAddress((void**)&xb,    g_xb);
    cudaGetSymbolAddress((void**)&xdbl,  g_xdbl);
    cudaGetSymbolAddress((void**)&dt,    g_dt);
    cudaGetSymbolAddress((void**)&y,     g_y);
    cudaGetSymbolAddress((void**)&o_out, g_out);
    cudaGetSymbolAddress((void**)&comb,  g_comb);

    setup_A_kernel<<<(2 * DI * DS + 255) / 256, 256>>>(A_log);
    check_arith_kernel<<<1, 256>>>();

    rmsnorm_kernel<<<2 * MM, 256>>>(x, norm_w);

    const int MY128 = (MM + 127) / 128;   // 13
    const int MY64  = (MM + 63) / 64;     // 25

    // in_proj: (1568x768) @ (3072x768)^T — BM=128, 624 CTAs
    gemm_bf16x2<128, EPI_STORE><<<dim3(2 * DI / 128, MY128, 2), 256>>>(
        xn, CM, (size_t)MM * CM,
        in_proj_w, (size_t)2 * DI * CM,
        xz, 2 * DI, (size_t)MM * 2 * DI,
        MM, 2 * DI, CM, nullptr, 0, nullptr);

    conv_silu_kernel<<<(2 * MM * DI + 255) / 256, 256>>>(conv_w, conv_b);

    // x_proj: (1568x1536) @ (80x1536)^T, split-K=8 SIMT
    cudaMemsetAsync(xdbl, 0, sizeof(float) * 2 * MM * 80);
    gemm_splitk<128, 80, 16, 8><<<dim3(1, MY128, 2 * 8), 256>>>(
        xb, DI, (size_t)MM * DI,
        x_proj_w, (size_t)80 * DI,
        xdbl, 80, (size_t)MM * 80,
        MM, 80, DI);

    // dt_proj + softplus: BM=128, 312 CTAs
    gemm_bf16x2<128, EPI_SOFTPLUS><<<dim3(DI / 128, MY128, 2), 256>>>(
        xdbl, 80, (size_t)MM * 80,
        dt_proj_w, (size_t)DI * DR,
        dt, DI, (size_t)MM * DI,
        MM, DI, DR, dt_proj_b, DI, nullptr);

    scan_kernel<<<dim3(DI / 64, BB, 2), 64>>>(Dp);

    // out_proj + residual + flip-scatter — BM=64, 300 CTAs
    gemm_bf16x2<64, EPI_RESID><<<dim3(CM / 128, MY64, 2), 256>>>(
        y, DI, (size_t)MM * DI,
        mix_out_w, (size_t)CM * DI,
        o_out, 0, 0,
        MM, CM, DI, nullptr, 0, x);

    // gate GEMM + sigmoid combine — BM=64, 150 CTAs
    gemm_bf16x2<64, EPI_GATE><<<dim3(CM / 128, MY64, 1), 256>>>(
        o_out, 2 * CM, 0,
        gate_w, 0,
        comb, CM, 0,
        MM, CM, 2 * CM, gate_b, 0, o_out);

    // final projection + bias — BM=64, 150 CTAs
    gemm_bf16x2<64, EPI_BIAS><<<dim3(CM / 128, MY64, 1), 256>>>(
        comb, CM, 0,
        proj_w, 0,
        out, CM, 0,
        MM, CM, CM, proj_b, 0, nullptr);

    (void)in_sizes; (void)n_in; (void)out_size;
}

// round 11
// speedup vs baseline: 1.8815x; 1.7984x over previous
#include <cuda_runtime.h>
#include <cuda_bf16.h>
#include <cstdint>

// ---------------------------------------------------------------------------
// BiMamba refiner block, round 10: R9 GEMMs + chunked parallel selective scan
// (8 chunks, exp(sum dt * A) chunk-transition, 3-pass).
// ---------------------------------------------------------------------------

#define BB      2
#define TT      4
#define NP      196
#define LL      784
#define MM      1568
#define CM      768
#define DI      1536
#define DS      16
#define DR      48
#define DCONV   4
#define CH      8
#define CLEN    98      // LL / CH

// ---------------- scratch ---------------------------------------------------
__device__ float g_xn  [2 * MM * CM];
__device__ float g_xz  [2 * MM * 2 * DI];
__device__ float g_xb  [2 * MM * DI];
__device__ float g_xdbl[2 * MM * 80];
__device__ float g_dt  [2 * MM * DI];
__device__ float g_y   [2 * MM * DI];
__device__ float g_out [MM * 2 * CM];
__device__ float g_comb[MM * CM];
__device__ float g_A   [2 * DI * DS];
__device__ int   g_arith;
// scan chunk scratch
__device__ float g_S    [2 * BB * CH * DI * DS];
__device__ float g_h0   [2 * BB * CH * DI * DS];
__device__ float g_sumdt[2 * BB * CH * DI];

__device__ __forceinline__ int map_row(int l, int dir) {
    if (dir == 0) return l;
    int t = l / NP, n = l - t * NP;
    return (TT - 1 - t) * NP + n;
}
__device__ __forceinline__ float sigmoidf_(float v) { return 1.0f / (1.0f + __expf(-v)); }
__device__ __forceinline__ float siluf_(float v)    { return v * sigmoidf_(v); }

// pack two floats into bf16x2 hi and lo residual
__device__ __forceinline__ void split2(float x, float y, uint32_t& hi, uint32_t& lo) {
    __nv_bfloat16 hx = __float2bfloat16(x);
    __nv_bfloat16 hy = __float2bfloat16(y);
    __nv_bfloat16 lx = __float2bfloat16(x - __bfloat162float(hx));
    __nv_bfloat16 ly = __float2bfloat16(y - __bfloat162float(hy));
    __nv_bfloat162 h2 = __halves2bfloat162(hx, hy);
    __nv_bfloat162 l2 = __halves2bfloat162(lx, ly);
    hi = *reinterpret_cast<uint32_t*>(&h2);
    lo = *reinterpret_cast<uint32_t*>(&l2);
}

__device__ __forceinline__ void mma_bf16(float c[4],
                                         uint32_t a0, uint32_t a1, uint32_t a2, uint32_t a3,
                                         uint32_t b0, uint32_t b1) {
    asm volatile(
        "mma.sync.aligned.m16n8k16.row.col.f32.bf16.bf16.f32 "
        "{%0,%1,%2,%3},{%4,%5,%6,%7},{%8,%9},{%0,%1,%2,%3};"
        : "+f"(c[0]), "+f"(c[1]), "+f"(c[2]), "+f"(c[3])
        : "r"(a0), "r"(a1), "r"(a2), "r"(a3), "r"(b0), "r"(b1));
}

__device__ __forceinline__ void ldsm_x4(uint32_t& r0, uint32_t& r1, uint32_t& r2,
                                        uint32_t& r3, uint32_t addr) {
    asm volatile("ldmatrix.sync.aligned.m8n8.x4.shared.b16 {%0,%1,%2,%3}, [%4];"
                 : "=r"(r0), "=r"(r1), "=r"(r2), "=r"(r3) : "r"(addr));
}

__device__ __forceinline__ int swz(int row, int chunk) {
    return row * 2 + (chunk ^ ((row >> 2) & 1));
}

// ---------------------------------------------------------------------------
__global__ void setup_A_kernel(const float* __restrict__ A_log) {
    int i = blockIdx.x * blockDim.x + threadIdx.x;
    if (i < 2 * DI * DS) g_A[i] = -expf(A_log[i]);
}

__global__ void check_arith_kernel() {
    __shared__ int bad;
    if (threadIdx.x == 0) bad = 0;
    __syncthreads();
    for (int row = threadIdx.x; row < 2 * DI; row += blockDim.x) {
        const float* a = &g_A[row * DS];
        float a0 = a[0], da = a[1] - a[0];
        for (int n = 2; n < DS; n++) {
            float expect = a0 + n * da;
            if (fabsf(a[n] - expect) > 1e-4f * (1.0f + fabsf(a[n]))) { bad = 1; break; }
        }
    }
    __syncthreads();
    if (threadIdx.x == 0) g_arith = bad ? 0 : 1;
}

__global__ void rmsnorm_kernel(const float* __restrict__ x,
                               const float* __restrict__ norm_w) {
    int gid = blockIdx.x;
    int dir = gid / MM;
    int rem = gid - dir * MM;
    int b   = rem / LL, l = rem - b * LL;
    int lo  = map_row(l, dir);
    const float* row = x + (size_t)(b * LL + lo) * CM;

    float s = 0.f;
    for (int c = threadIdx.x; c < CM; c += blockDim.x) {
        float v = row[c];
        s += v * v;
    }
    __shared__ float warp_s[8];
    for (int off = 16; off > 0; off >>= 1) s += __shfl_down_sync(0xffffffffu, s, off);
    if ((threadIdx.x & 31) == 0) warp_s[threadIdx.x >> 5] = s;
    __syncthreads();
    if (threadIdx.x < 8) {
        float t = warp_s[threadIdx.x];
        for (int off = 4; off > 0; off >>= 1) t += __shfl_down_sync(0xffu, t, off);
        if (threadIdx.x == 0) warp_s[0] = t;
    }
    __syncthreads();
    float scale = rsqrtf(warp_s[0] / (float)CM + 1e-5f);

    float* dst = g_xn + (size_t)gid * CM;
    const float* nw = norm_w + dir * CM;
    for (int c = threadIdx.x; c < CM; c += blockDim.x)
        dst[c] = row[c] * scale * nw[c];
}

// ---------------------------------------------------------------------------
// bf16x2 MMA GEMM (unchanged from round 9)
// ---------------------------------------------------------------------------
#define EPI_STORE    0
#define EPI_SOFTPLUS 1
#define EPI_RESID    2
#define EPI_GATE     3
#define EPI_BIAS     4

template <int BM, int EPI>
__global__ void __launch_bounds__(256)
gemm_bf16x2(const float* __restrict__ Ab, int lda, size_t sA,
            const float* __restrict__ Wb, size_t sW,
            float* __restrict__ Cb, int ldc, size_t sC,
            int M, int N, int K,
            const float* __restrict__ biasb, size_t sBias,
            const float* __restrict__ aux) {
    constexpr int BN = 128;
    constexpr int NF = 4;
    constexpr int MI = BM / 32;

    __shared__ uint4 AhS[2][BM * 2], AlS[2][BM * 2];
    __shared__ uint4 BhS[2][BN * 2], BlS[2][BN * 2];

    const int t    = threadIdx.x;
    const int lane = t & 31;
    const int w    = t >> 5;
    const int wm   = (w & 1) * (BM / 2);
    const int wn   = (w >> 1) * 32;
    const int g    = lane >> 2;
    const int tg   = lane & 3;

    const int m0  = blockIdx.y * BM;
    const int n0  = blockIdx.x * BN;
    const int dir = blockIdx.z;

    const float* A = Ab + (size_t)dir * sA;
    const float* W = Wb + (size_t)dir * sW;
    float*       C = Cb + (size_t)dir * sC;
    const float* bias = biasb ? biasb + (size_t)dir * sBias : nullptr;

    const int srow = t >> 1;
    const int skh  = (t & 1) * 8;
    const bool doA = (t < BM * 2);

    float4 ra0, ra1, rb0, rb1;
    auto gload = [&](int k0) {
        if (doA) {
            int gm = m0 + srow;
            if (gm < M) {
                ra0 = *(const float4*)&A[(size_t)gm * lda + k0 + skh];
                ra1 = *(const float4*)&A[(size_t)gm * lda + k0 + skh + 4];
            } else {
                ra0 = make_float4(0.f, 0.f, 0.f, 0.f); ra1 = ra0;
            }
        }
        int gn = n0 + srow;
        if (gn < N) {
            rb0 = *(const float4*)&W[(size_t)gn * K + k0 + skh];
            rb1 = *(const float4*)&W[(size_t)gn * K + k0 + skh + 4];
        } else {
            rb0 = make_float4(0.f, 0.f, 0.f, 0.f); rb1 = rb0;
        }
    };
    auto sstore = [&](int s) {
        uint4 h4, l4;
        if (doA) {
            split2(ra0.x, ra0.y, h4.x, l4.x);
            split2(ra0.z, ra0.w, h4.y, l4.y);
            split2(ra1.x, ra1.y, h4.z, l4.z);
            split2(ra1.z, ra1.w, h4.w, l4.w);
            int ai = swz(srow, t & 1);
            AhS[s][ai] = h4; AlS[s][ai] = l4;
        }
        split2(rb0.x, rb0.y, h4.x, l4.x);
        split2(rb0.z, rb0.w, h4.y, l4.y);
        split2(rb1.x, rb1.y, h4.z, l4.z);
        split2(rb1.z, rb1.w, h4.w, l4.w);
        int bi = swz(srow, t & 1);
        BhS[s][bi] = h4; BlS[s][bi] = l4;
    };

    const int a_r = lane & 15;
    const int a_c = lane >> 4;
    const int b_r = (lane & 7) + ((lane & 16) ? 8 : 0);
    const int b_c = (lane >> 3) & 1;

    const uint32_t baseAh = (uint32_t)__cvta_generic_to_shared(&AhS[0][0]);
    const uint32_t baseAl = (uint32_t)__cvta_generic_to_shared(&AlS[0][0]);
    const uint32_t baseBh = (uint32_t)__cvta_generic_to_shared(&BhS[0][0]);
    const uint32_t baseBl = (uint32_t)__cvta_generic_to_shared(&BlS[0][0]);
    const uint32_t strideA = BM * 2 * 16;
    const uint32_t strideB = BN * 2 * 16;

    float acc[MI][NF][4];
#pragma unroll
    for (int i = 0; i < MI; i++)
#pragma unroll
        for (int j = 0; j < NF; j++)
#pragma unroll
            for (int r = 0; r < 4; r++) acc[i][j][r] = 0.f;

    const int nk = K / 16;
    gload(0);
    sstore(0);
    __syncthreads();

    int cur = 0;
    for (int kt = 0; kt < nk; kt++) {
        if (kt + 1 < nk) gload((kt + 1) * 16);

        uint32_t ah[MI][4], al[MI][4];
        uint32_t bh[8], bl[8];
        {
            uint32_t off0 = (uint32_t)(swz(wn + b_r,      b_c) * 16);
            uint32_t off1 = (uint32_t)(swz(wn + 16 + b_r, b_c) * 16);
            ldsm_x4(bh[0], bh[1], bh[2], bh[3], baseBh + cur * strideB + off0);
            ldsm_x4(bh[4], bh[5], bh[6], bh[7], baseBh + cur * strideB + off1);
            ldsm_x4(bl[0], bl[1], bl[2], bl[3], baseBl + cur * strideB + off0);
            ldsm_x4(bl[4], bl[5], bl[6], bl[7], baseBl + cur * strideB + off1);
        }
#pragma unroll
        for (int i = 0; i < MI; i++) {
            int row = wm + i * 16 + a_r;
            uint32_t off = (uint32_t)(swz(row, a_c) * 16);
            ldsm_x4(ah[i][0], ah[i][1], ah[i][2], ah[i][3], baseAh + cur * strideA + off);
            ldsm_x4(al[i][0], al[i][1], al[i][2], al[i][3], baseAl + cur * strideA + off);
        }

#pragma unroll
        for (int j = 0; j < NF; j++) {
            uint32_t b0h = bh[j * 2], b1h = bh[j * 2 + 1];
            uint32_t b0l = bl[j * 2], b1l = bl[j * 2 + 1];
#pragma unroll
            for (int i = 0; i < MI; i++) {
                mma_bf16(acc[i][j], ah[i][0], ah[i][1], ah[i][2], ah[i][3], b0h, b1h);
                mma_bf16(acc[i][j], ah[i][0], ah[i][1], ah[i][2], ah[i][3], b0l, b1l);
                mma_bf16(acc[i][j], al[i][0], al[i][1], al[i][2], al[i][3], b0h, b1h);
            }
        }

        if (kt + 1 < nk) sstore(cur ^ 1);
        __syncthreads();
        cur ^= 1;
    }

    auto emit = [&](int m, int n, float v) {
        if (m >= M || n >= N) return;
        if (EPI == EPI_STORE) {
            C[(size_t)m * ldc + n] = v;
        } else if (EPI == EPI_SOFTPLUS) {
            v += bias[n];
            C[(size_t)m * ldc + n] = (v > 20.f) ? v : log1pf(__expf(v));
        } else if (EPI == EPI_RESID) {
            int b = m / LL, l = m - b * LL;
            int lo = map_row(l, dir);
            int row = b * LL + lo;
            C[((size_t)row * 2 + dir) * CM + n] = aux[(size_t)row * CM + n] + v;
        } else if (EPI == EPI_GATE) {
            float gg = sigmoidf_(v + bias[n]);
            float of = aux[(size_t)m * (2 * CM) + n];
            float ob = aux[(size_t)m * (2 * CM) + CM + n];
            C[(size_t)m * ldc + n] = gg * of + (1.f - gg) * ob;
        } else {
            C[(size_t)m * ldc + n] = v + bias[n];
        }
    };

#pragma unroll
    for (int i = 0; i < MI; i++) {
        int mr = m0 + wm + i * 16 + g;
#pragma unroll
        for (int j = 0; j < NF; j++) {
            int nc = n0 + wn + j * 8 + 2 * tg;
            emit(mr,     nc,     acc[i][j][0]);
            emit(mr,     nc + 1, acc[i][j][1]);
            emit(mr + 8, nc,     acc[i][j][2]);
            emit(mr + 8, nc + 1, acc[i][j][3]);
        }
    }
}

// ---------------------------------------------------------------------------
// SIMT split-K GEMM for the skinny x_proj (N=80)
// ---------------------------------------------------------------------------
template <int TM, int TN, int TK, int KS>
__global__ void __launch_bounds__(256, 2)
gemm_splitk(const float* __restrict__ Ab, int lda, size_t sA,
            const float* __restrict__ Wb, size_t sW,
            float* __restrict__ Cb, int ldc, size_t sC,
            int M, int N, int K) {
    constexpr int RM = TM / 16;
    constexpr int RN = TN / 16;
    constexpr int A4 = TM * TK / 4;
    constexpr int B4 = TN * TK / 4;
    constexpr int RA = (A4 + 255) / 256;
    constexpr int RB = (B4 + 255) / 256;

    __shared__ float As[2][TK][TM + 4];
    __shared__ float Bs[2][TK][TN + 4];

    const int t  = threadIdx.x;
    const int tx = t & 15;
    const int ty = t >> 4;
    const int m0 = blockIdx.y * TM;
    const int n0 = blockIdx.x * TN;

    const int z = blockIdx.z;
    const int dir   = z / KS;
    const int split = z % KS;

    const float* A = Ab + (size_t)dir * sA;
    const float* W = Wb + (size_t)dir * sW;
    float*       C = Cb + (size_t)dir * sC;

    const int Kpart = K / KS;
    const int kbeg  = split * Kpart;
    const int nk    = Kpart / TK;

    float4 ra[RA], rb[RB];

    auto gload = [&](int k0) {
#pragma unroll
        for (int i = 0; i < RA; i++) {
            int idx = t + i * 256;
            float4 v = make_float4(0.f, 0.f, 0.f, 0.f);
            if (idx < A4) {
                int m = idx / (TK / 4), kq = idx % (TK / 4);
                int gm = m0 + m;
                if (gm < M) v = *(const float4*)&A[(size_t)gm * lda + k0 + kq * 4];
            }
            ra[i] = v;
        }
#pragma unroll
        for (int i = 0; i < RB; i++) {
            int idx = t + i * 256;
            float4 v = make_float4(0.f, 0.f, 0.f, 0.f);
            if (idx < B4) {
                int n = idx / (TK / 4), kq = idx % (TK / 4);
                int gn = n0 + n;
                if (gn < N) v = *(const float4*)&W[(size_t)gn * K + k0 + kq * 4];
            }
            rb[i] = v;
        }
    };
    auto sstore = [&](int s) {
#pragma unroll
        for (int i = 0; i < RA; i++) {
            int idx = t + i * 256;
            if (idx < A4) {
                int m = idx / (TK / 4), kq = (idx % (TK / 4)) * 4;
                As[s][kq + 0][m] = ra[i].x; As[s][kq + 1][m] = ra[i].y;
                As[s][kq + 2][m] = ra[i].z; As[s][kq + 3][m] = ra[i].w;
            }
        }
#pragma unroll
        for (int i = 0; i < RB; i++) {
            int idx = t + i * 256;
            if (idx < B4) {
                int n = idx / (TK / 4), kq = (idx % (TK / 4)) * 4;
                Bs[s][kq + 0][n] = rb[i].x; Bs[s][kq + 1][n] = rb[i].y;
                Bs[s][kq + 2][n] = rb[i].z; Bs[s][kq + 3][n] = rb[i].w;
            }
        }
    };

    float acc[RM][RN];
#pragma unroll
    for (int i = 0; i < RM; i++)
#pragma unroll
        for (int j = 0; j < RN; j++) acc[i][j] = 0.f;

    gload(kbeg);
    sstore(0);
    __syncthreads();

    int cur = 0;
    for (int kt = 0; kt < nk; kt++) {
        if (kt + 1 < nk) gload(kbeg + (kt + 1) * TK);
#pragma unroll
        for (int k = 0; k < TK; k++) {
            float af[RM], bf[RN];
#pragma unroll
            for (int i = 0; i < RM; i++) af[i] = As[cur][k][ty * RM + i];
#pragma unroll
            for (int j = 0; j < RN; j++) bf[j] = Bs[cur][k][tx * RN + j];
#pragma unroll
            for (int i = 0; i < RM; i++)
#pragma unroll
                for (int j = 0; j < RN; j++)
                    acc[i][j] = fmaf(af[i], bf[j], acc[i][j]);
        }
        __syncthreads();
        if (kt + 1 < nk) {
            sstore(cur ^ 1);
            __syncthreads();
            cur ^= 1;
        }
    }

#pragma unroll
    for (int i = 0; i < RM; i++) {
        int m = m0 + ty * RM + i;
        if (m >= M) continue;
#pragma unroll
        for (int j = 0; j < RN; j++) {
            int n = n0 + tx * RN + j;
            if (n >= N) continue;
            atomicAdd(&C[(size_t)m * ldc + n], acc[i][j]);
        }
    }
}

// ---------------------------------------------------------------------------
__global__ void conv_silu_kernel(const float* __restrict__ conv_w,
                                 const float* __restrict__ conv_b) {
    int idx = blockIdx.x * blockDim.x + threadIdx.x;
    if (idx >= 2 * MM * DI) return;
    int d = idx % DI;
    int r = idx / DI;
    int dir = r / MM;
    int l = r % LL;

    const float* w = conv_w + (size_t)(dir * DI + d) * DCONV;
    float acc = conv_b[dir * DI + d];
#pragma unroll
    for (int j = 0; j < DCONV; j++) {
        int ls = l - (DCONV - 1) + j;
        if (ls >= 0)
            acc = fmaf(w[j], g_xz[(size_t)(r - (DCONV - 1) + j) * (2 * DI) + d], acc);
    }
    g_xb[(size_t)r * DI + d] = siluf_(acc);
}

// ---------------------------------------------------------------------------
// chunked scan, pass 1: per (d,b,dir,chunk) local scan from h=0.
// Stores S[16] and sum(dt). grid (DI/128, BB, 2*CH), block 128.
// ---------------------------------------------------------------------------
__global__ void __launch_bounds__(128, 8)
scan_p1() {
    int d   = blockIdx.x * blockDim.x + threadIdx.x;
    int b   = blockIdx.y;
    int z   = blockIdx.z;
    int dir = z >> 3;
    int c   = z & 7;

    const float* Arow = &g_A[(dir * DI + d) * DS];
    float a0 = Arow[0];
    float da = Arow[1] - Arow[0];
    float Ar[DS];
    bool arith = (g_arith != 0);
    if (!arith) {
#pragma unroll
        for (int n = 0; n < DS; n++) Ar[n] = Arow[n];
    }

    float h[DS];
#pragma unroll
    for (int n = 0; n < DS; n++) h[n] = 0.f;
    float sdt = 0.f;

    size_t r0 = (size_t)dir * MM + (size_t)b * LL + (size_t)c * CLEN;
    for (int l = 0; l < CLEN; l++) {
        size_t r = r0 + l;
        float u  = g_xb[r * DI + d];
        float dt = g_dt[r * DI + d];
        const float4* Bv = (const float4*)(&g_xdbl[r * 80 + DR]);
        float4 B0 = __ldg(&Bv[0]), B1 = __ldg(&Bv[1]);
        float4 B2 = __ldg(&Bv[2]), B3 = __ldg(&Bv[3]);
        float Bl[DS] = {B0.x, B0.y, B0.z, B0.w, B1.x, B1.y, B1.z, B1.w,
                        B2.x, B2.y, B2.z, B2.w, B3.x, B3.y, B3.z, B3.w};
        float du = dt * u;
        if (arith) {
            float p  = __expf(dt * a0);
            float rr = __expf(dt * da);
#pragma unroll
            for (int n = 0; n < DS; n++) {
                h[n] = fmaf(p, h[n], du * Bl[n]);
                p *= rr;
            }
        } else {
#pragma unroll
            for (int n = 0; n < DS; n++)
                h[n] = fmaf(__expf(dt * Ar[n]), h[n], du * Bl[n]);
        }
        sdt += dt;
    }

    size_t base = (((size_t)(dir * BB + b) * CH + c) * DI + d);
    g_sumdt[base] = sdt;
    float4* Sp = (float4*)&g_S[base * DS];
#pragma unroll
    for (int q = 0; q < 4; q++)
        Sp[q] = make_float4(h[q * 4], h[q * 4 + 1], h[q * 4 + 2], h[q * 4 + 3]);
}

// ---------------------------------------------------------------------------
// chunked scan, pass 2: sequential combine over CH chunks per (d,b,dir).
// h0[c] = state entering chunk c. 2*BB*DI = 6144 threads.
// ---------------------------------------------------------------------------
__global__ void scan_p2() {
    int idx = blockIdx.x * blockDim.x + threadIdx.x;
    if (idx >= 2 * BB * DI) return;
    int d  = idx % DI;
    int bd = idx / DI;         // dir*BB + b
    int dir = bd / BB;

    const float* Arow = &g_A[(dir * DI + d) * DS];
    float a0 = Arow[0];
    float da = Arow[1] - Arow[0];
    float Ar[DS];
    bool arith = (g_arith != 0);
    if (!arith) {
#pragma unroll
        for (int n = 0; n < DS; n++) Ar[n] = Arow[n];
    }

    float h[DS];
#pragma unroll
    for (int n = 0; n < DS; n++) h[n] = 0.f;

    for (int c = 0; c < CH; c++) {
        size_t base = (((size_t)bd * CH + c) * DI + d);
        float4* Hp = (float4*)&g_h0[base * DS];
#pragma unroll
        for (int q = 0; q < 4; q++)
            Hp[q] = make_float4(h[q * 4], h[q * 4 + 1], h[q * 4 + 2], h[q * 4 + 3]);

        float sdt = g_sumdt[base];
        const float4* Sp = (const float4*)&g_S[base * DS];
        float4 S0 = Sp[0], S1 = Sp[1], S2 = Sp[2], S3 = Sp[3];
        float Sl[DS] = {S0.x, S0.y, S0.z, S0.w, S1.x, S1.y, S1.z, S1.w,
                        S2.x, S2.y, S2.z, S2.w, S3.x, S3.y, S3.z, S3.w};
        if (arith) {
            float p  = __expf(sdt * a0);
            float rr = __expf(sdt * da);
#pragma unroll
            for (int n = 0; n < DS; n++) {
                h[n] = fmaf(p, h[n], Sl[n]);
                p *= rr;
            }
        } else {
#pragma unroll
            for (int n = 0; n < DS; n++)
                h[n] = fmaf(__expf(sdt * Ar[n]), h[n], Sl[n]);
        }
    }
}

// ---------------------------------------------------------------------------
// chunked scan, pass 3: full scan from h0[c], emit y*silu(z).
// ---------------------------------------------------------------------------
__global__ void __launch_bounds__(128, 8)
scan_p3(const float* __restrict__ Dp) {
    int d   = blockIdx.x * blockDim.x + threadIdx.x;
    int b   = blockIdx.y;
    int z   = blockIdx.z;
    int dir = z >> 3;
    int c   = z & 7;

    const float* Arow = &g_A[(dir * DI + d) * DS];
    float a0 = Arow[0];
    float da = Arow[1] - Arow[0];
    float Ar[DS];
    bool arith = (g_arith != 0);
    if (!arith) {
#pragma unroll
        for (int n = 0; n < DS; n++) Ar[n] = Arow[n];
    }

    size_t base = (((size_t)(dir * BB + b) * CH + c) * DI + d);
    float h[DS];
    {
        const float4* Hp = (const float4*)&g_h0[base * DS];
        float4 H0 = Hp[0], H1 = Hp[1], H2 = Hp[2], H3 = Hp[3];
        h[0] = H0.x;  h[1] = H0.y;  h[2] = H0.z;  h[3] = H0.w;
        h[4] = H1.x;  h[5] = H1.y;  h[6] = H1.z;  h[7] = H1.w;
        h[8] = H2.x;  h[9] = H2.y;  h[10] = H2.z; h[11] = H2.w;
        h[12] = H3.x; h[13] = H3.y; h[14] = H3.z; h[15] = H3.w;
    }

    float Dd = Dp[dir * DI + d];
    size_t r0 = (size_t)dir * MM + (size_t)b * LL + (size_t)c * CLEN;

    for (int l = 0; l < CLEN; l++) {
        size_t r = r0 + l;
        float u  = g_xb[r * DI + d];
        float dt = g_dt[r * DI + d];
        const float4* BC = (const float4*)(&g_xdbl[r * 80 + DR]);
        float4 Bv0 = __ldg(&BC[0]), Bv1 = __ldg(&BC[1]);
        float4 Bv2 = __ldg(&BC[2]), Bv3 = __ldg(&BC[3]);
        float4 Cv0 = __ldg(&BC[4]), Cv1 = __ldg(&BC[5]);
        float4 Cv2 = __ldg(&BC[6]), Cv3 = __ldg(&BC[7]);
        float Bl[DS] = {Bv0.x, Bv0.y, Bv0.z, Bv0.w, Bv1.x, Bv1.y, Bv1.z, Bv1.w,
                        Bv2.x, Bv2.y, Bv2.z, Bv2.w, Bv3.x, Bv3.y, Bv3.z, Bv3.w};
        float Cl[DS] = {Cv0.x, Cv0.y, Cv0.z, Cv0.w, Cv1.x, Cv1.y, Cv1.z, Cv1.w,
                        Cv2.x, Cv2.y, Cv2.z, Cv2.w, Cv3.x, Cv3.y, Cv3.z, Cv3.w};

        float du = dt * u;
        float yv = 0.f;
        if (arith) {
            float p  = __expf(dt * a0);
            float rr = __expf(dt * da);
#pragma unroll
            for (int n = 0; n < DS; n++) {
                h[n] = fmaf(p, h[n], du * Bl[n]);
                yv   = fmaf(h[n], Cl[n], yv);
                p *= rr;
            }
        } else {
#pragma unroll
            for (int n = 0; n < DS; n++) {
                float p = __expf(dt * Ar[n]);
                h[n] = fmaf(p, h[n], du * Bl[n]);
                yv   = fmaf(h[n], Cl[n], yv);
            }
        }
        yv = fmaf(u, Dd, yv);
        float zz = g_xz[r * (2 * DI) + DI + d];
        g_y[r * DI + d] = yv * siluf_(zz);
    }
}

// ---------------------------------------------------------------------------
extern "C" void kernel_launch(void* const* d_in, const int* in_sizes, int n_in,
                              void* d_out, int out_size) {
    const float* x         = (const float*)d_in[0];
    const float* norm_w    = (const float*)d_in[1];
    const float* in_proj_w = (const float*)d_in[2];
    const float* conv_w    = (const float*)d_in[3];
    const float* conv_b    = (const float*)d_in[4];
    const float* x_proj_w  = (const float*)d_in[5];
    const float* dt_proj_w = (const float*)d_in[6];
    const float* dt_proj_b = (const float*)d_in[7];
    const float* A_log     = (const float*)d_in[8];
    const float* Dp        = (const float*)d_in[9];
    const float* mix_out_w = (const float*)d_in[10];
    const float* gate_w    = (const float*)d_in[11];
    const float* gate_b    = (const float*)d_in[12];
    const float* proj_w    = (const float*)d_in[13];
    const float* proj_b    = (const float*)d_in[14];
    float* out = (float*)d_out;

    float *xn, *xz, *xb, *xdbl, *dt, *y, *o_out, *comb;
    cudaGetSymbolAddress((void**)&xn,    g_xn);
    cudaGetSymbolAddress((void**)&xz,    g_xz);
    cudaGetSymbolAddress((void**)&xb,    g_xb);
    cudaGetSymbolAddress((void**)&xdbl,  g_xdbl);
    cudaGetSymbolAddress((void**)&dt,    g_dt);
    cudaGetSymbolAddress((void**)&y,     g_y);
    cudaGetSymbolAddress((void**)&o_out, g_out);
    cudaGetSymbolAddress((void**)&comb,  g_comb);

    setup_A_kernel<<<(2 * DI * DS + 255) / 256, 256>>>(A_log);
    check_arith_kernel<<<1, 256>>>();

    rmsnorm_kernel<<<2 * MM, 256>>>(x, norm_w);

    const int MY128 = (MM + 127) / 128;   // 13
    const int MY64  = (MM + 63) / 64;     // 25

    // in_proj: BM=128, 624 CTAs
    gemm_bf16x2<128, EPI_STORE><<<dim3(2 * DI / 128, MY128, 2), 256>>>(
        xn, CM, (size_t)MM * CM,
        in_proj_w, (size_t)2 * DI * CM,
        xz, 2 * DI, (size_t)MM * 2 * DI,
        MM, 2 * DI, CM, nullptr, 0, nullptr);

    conv_silu_kernel<<<(2 * MM * DI + 255) / 256, 256>>>(conv_w, conv_b);

    // x_proj: split-K=8 SIMT
    cudaMemsetAsync(xdbl, 0, sizeof(float) * 2 * MM * 80);
    gemm_splitk<128, 80, 16, 8><<<dim3(1, MY128, 2 * 8), 256>>>(
        xb, DI, (size_t)MM * DI,
        x_proj_w, (size_t)80 * DI,
        xdbl, 80, (size_t)MM * 80,
        MM, 80, DI);

    // dt_proj + softplus
    gemm_bf16x2<128, EPI_SOFTPLUS><<<dim3(DI / 128, MY128, 2), 256>>>(
        xdbl, 80, (size_t)MM * 80,
        dt_proj_w, (size_t)DI * DR,
        dt, DI, (size_t)MM * DI,
        MM, DI, DR, dt_proj_b, DI, nullptr);

    // chunked parallel scan
    scan_p1<<<dim3(DI / 128, BB, 2 * CH), 128>>>();
    scan_p2<<<(2 * BB * DI + 255) / 256, 256>>>();
    scan_p3<<<dim3(DI / 128, BB, 2 * CH), 128>>>(Dp);

    // out_proj + residual + flip-scatter — BM=64
    gemm_bf16x2<64, EPI_RESID><<<dim3(CM / 128, MY64, 2), 256>>>(
        y, DI, (size_t)MM * DI,
        mix_out_w, (size_t)CM * DI,
        o_out, 0, 0,
        MM, CM, DI, nullptr, 0, x);

    // gate GEMM + sigmoid combine — BM=64
    gemm_bf16x2<64, EPI_GATE><<<dim3(CM / 128, MY64, 1), 256>>>(
        o_out, 2 * CM, 0,
        gate_w, 0,
        comb, CM, 0,
        MM, CM, 2 * CM, gate_b, 0, o_out);

    // final projection + bias — BM=64
    gemm_bf16x2<64, EPI_BIAS><<<dim3(CM / 128, MY64, 1), 256>>>(
        comb, CM, 0,
        proj_w, 0,
        out, CM, 0,
        MM, CM, CM, proj_b, 0, nullptr);

    (void)in_sizes; (void)n_in; (void)out_size;
}

// round 12
// speedup vs baseline: 1.9940x; 1.0598x over previous
#include <cuda_runtime.h>
#include <cuda_bf16.h>
#include <cstdint>

// ---------------------------------------------------------------------------
// BiMamba refiner block, round 11: chunked scan with CH=49 (CLEN=16) for
// 6x shorter serial chains; GEMMs unchanged from round 10.
// ---------------------------------------------------------------------------

#define BB      2
#define TT      4
#define NP      196
#define LL      784
#define MM      1568
#define CM      768
#define DI      1536
#define DS      16
#define DR      48
#define DCONV   4
#define CH      49
#define CLEN    16      // LL / CH

// ---------------- scratch ---------------------------------------------------
__device__ float g_xn  [2 * MM * CM];
__device__ float g_xz  [2 * MM * 2 * DI];
__device__ float g_xb  [2 * MM * DI];
__device__ float g_xdbl[2 * MM * 80];
__device__ float g_dt  [2 * MM * DI];
__device__ float g_y   [2 * MM * DI];
__device__ float g_out [MM * 2 * CM];
__device__ float g_comb[MM * CM];
__device__ float g_A   [2 * DI * DS];
__device__ int   g_arith;
// scan chunk scratch
__device__ float g_S    [2 * BB * CH * DI * DS];
__device__ float g_h0   [2 * BB * CH * DI * DS];
__device__ float g_sumdt[2 * BB * CH * DI];

__device__ __forceinline__ int map_row(int l, int dir) {
    if (dir == 0) return l;
    int t = l / NP, n = l - t * NP;
    return (TT - 1 - t) * NP + n;
}
__device__ __forceinline__ float sigmoidf_(float v) { return 1.0f / (1.0f + __expf(-v)); }
__device__ __forceinline__ float siluf_(float v)    { return v * sigmoidf_(v); }

// pack two floats into bf16x2 hi and lo residual
__device__ __forceinline__ void split2(float x, float y, uint32_t& hi, uint32_t& lo) {
    __nv_bfloat16 hx = __float2bfloat16(x);
    __nv_bfloat16 hy = __float2bfloat16(y);
    __nv_bfloat16 lx = __float2bfloat16(x - __bfloat162float(hx));
    __nv_bfloat16 ly = __float2bfloat16(y - __bfloat162float(hy));
    __nv_bfloat162 h2 = __halves2bfloat162(hx, hy);
    __nv_bfloat162 l2 = __halves2bfloat162(lx, ly);
    hi = *reinterpret_cast<uint32_t*>(&h2);
    lo = *reinterpret_cast<uint32_t*>(&l2);
}

__device__ __forceinline__ void mma_bf16(float c[4],
                                         uint32_t a0, uint32_t a1, uint32_t a2, uint32_t a3,
                                         uint32_t b0, uint32_t b1) {
    asm volatile(
        "mma.sync.aligned.m16n8k16.row.col.f32.bf16.bf16.f32 "
        "{%0,%1,%2,%3},{%4,%5,%6,%7},{%8,%9},{%0,%1,%2,%3};"
        : "+f"(c[0]), "+f"(c[1]), "+f"(c[2]), "+f"(c[3])
        : "r"(a0), "r"(a1), "r"(a2), "r"(a3), "r"(b0), "r"(b1));
}

__device__ __forceinline__ void ldsm_x4(uint32_t& r0, uint32_t& r1, uint32_t& r2,
                                        uint32_t& r3, uint32_t addr) {
    asm volatile("ldmatrix.sync.aligned.m8n8.x4.shared.b16 {%0,%1,%2,%3}, [%4];"
                 : "=r"(r0), "=r"(r1), "=r"(r2), "=r"(r3) : "r"(addr));
}

__device__ __forceinline__ int swz(int row, int chunk) {
    return row * 2 + (chunk ^ ((row >> 2) & 1));
}

// ---------------------------------------------------------------------------
__global__ void setup_A_kernel(const float* __restrict__ A_log) {
    int i = blockIdx.x * blockDim.x + threadIdx.x;
    if (i < 2 * DI * DS) g_A[i] = -expf(A_log[i]);
}

__global__ void check_arith_kernel() {
    __shared__ int bad;
    if (threadIdx.x == 0) bad = 0;
    __syncthreads();
    for (int row = threadIdx.x; row < 2 * DI; row += blockDim.x) {
        const float* a = &g_A[row * DS];
        float a0 = a[0], da = a[1] - a[0];
        for (int n = 2; n < DS; n++) {
            float expect = a0 + n * da;
            if (fabsf(a[n] - expect) > 1e-4f * (1.0f + fabsf(a[n]))) { bad = 1; break; }
        }
    }
    __syncthreads();
    if (threadIdx.x == 0) g_arith = bad ? 0 : 1;
}

__global__ void rmsnorm_kernel(const float* __restrict__ x,
                               const float* __restrict__ norm_w) {
    int gid = blockIdx.x;
    int dir = gid / MM;
    int rem = gid - dir * MM;
    int b   = rem / LL, l = rem - b * LL;
    int lo  = map_row(l, dir);
    const float* row = x + (size_t)(b * LL + lo) * CM;

    float s = 0.f;
    for (int c = threadIdx.x; c < CM; c += blockDim.x) {
        float v = row[c];
        s += v * v;
    }
    __shared__ float warp_s[8];
    for (int off = 16; off > 0; off >>= 1) s += __shfl_down_sync(0xffffffffu, s, off);
    if ((threadIdx.x & 31) == 0) warp_s[threadIdx.x >> 5] = s;
    __syncthreads();
    if (threadIdx.x < 8) {
        float t = warp_s[threadIdx.x];
        for (int off = 4; off > 0; off >>= 1) t += __shfl_down_sync(0xffu, t, off);
        if (threadIdx.x == 0) warp_s[0] = t;
    }
    __syncthreads();
    float scale = rsqrtf(warp_s[0] / (float)CM + 1e-5f);

    float* dst = g_xn + (size_t)gid * CM;
    const float* nw = norm_w + dir * CM;
    for (int c = threadIdx.x; c < CM; c += blockDim.x)
        dst[c] = row[c] * scale * nw[c];
}

// ---------------------------------------------------------------------------
// bf16x2 MMA GEMM (unchanged)
// ---------------------------------------------------------------------------
#define EPI_STORE    0
#define EPI_SOFTPLUS 1
#define EPI_RESID    2
#define EPI_GATE     3
#define EPI_BIAS     4

template <int BM, int EPI>
__global__ void __launch_bounds__(256)
gemm_bf16x2(const float* __restrict__ Ab, int lda, size_t sA,
            const float* __restrict__ Wb, size_t sW,
            float* __restrict__ Cb, int ldc, size_t sC,
            int M, int N, int K,
            const float* __restrict__ biasb, size_t sBias,
            const float* __restrict__ aux) {
    constexpr int BN = 128;
    constexpr int NF = 4;
    constexpr int MI = BM / 32;

    __shared__ uint4 AhS[2][BM * 2], AlS[2][BM * 2];
    __shared__ uint4 BhS[2][BN * 2], BlS[2][BN * 2];

    const int t    = threadIdx.x;
    const int lane = t & 31;
    const int w    = t >> 5;
    const int wm   = (w & 1) * (BM / 2);
    const int wn   = (w >> 1) * 32;
    const int g    = lane >> 2;
    const int tg   = lane & 3;

    const int m0  = blockIdx.y * BM;
    const int n0  = blockIdx.x * BN;
    const int dir = blockIdx.z;

    const float* A = Ab + (size_t)dir * sA;
    const float* W = Wb + (size_t)dir * sW;
    float*       C = Cb + (size_t)dir * sC;
    const float* bias = biasb ? biasb + (size_t)dir * sBias : nullptr;

    const int srow = t >> 1;
    const int skh  = (t & 1) * 8;
    const bool doA = (t < BM * 2);

    float4 ra0, ra1, rb0, rb1;
    auto gload = [&](int k0) {
        if (doA) {
            int gm = m0 + srow;
            if (gm < M) {
                ra0 = *(const float4*)&A[(size_t)gm * lda + k0 + skh];
                ra1 = *(const float4*)&A[(size_t)gm * lda + k0 + skh + 4];
            } else {
                ra0 = make_float4(0.f, 0.f, 0.f, 0.f); ra1 = ra0;
            }
        }
        int gn = n0 + srow;
        if (gn < N) {
            rb0 = *(const float4*)&W[(size_t)gn * K + k0 + skh];
            rb1 = *(const float4*)&W[(size_t)gn * K + k0 + skh + 4];
        } else {
            rb0 = make_float4(0.f, 0.f, 0.f, 0.f); rb1 = rb0;
        }
    };
    auto sstore = [&](int s) {
        uint4 h4, l4;
        if (doA) {
            split2(ra0.x, ra0.y, h4.x, l4.x);
            split2(ra0.z, ra0.w, h4.y, l4.y);
            split2(ra1.x, ra1.y, h4.z, l4.z);
            split2(ra1.z, ra1.w, h4.w, l4.w);
            int ai = swz(srow, t & 1);
            AhS[s][ai] = h4; AlS[s][ai] = l4;
        }
        split2(rb0.x, rb0.y, h4.x, l4.x);
        split2(rb0.z, rb0.w, h4.y, l4.y);
        split2(rb1.x, rb1.y, h4.z, l4.z);
        split2(rb1.z, rb1.w, h4.w, l4.w);
        int bi = swz(srow, t & 1);
        BhS[s][bi] = h4; BlS[s][bi] = l4;
    };

    const int a_r = lane & 15;
    const int a_c = lane >> 4;
    const int b_r = (lane & 7) + ((lane & 16) ? 8 : 0);
    const int b_c = (lane >> 3) & 1;

    const uint32_t baseAh = (uint32_t)__cvta_generic_to_shared(&AhS[0][0]);
    const uint32_t baseAl = (uint32_t)__cvta_generic_to_shared(&AlS[0][0]);
    const uint32_t baseBh = (uint32_t)__cvta_generic_to_shared(&BhS[0][0]);
    const uint32_t baseBl = (uint32_t)__cvta_generic_to_shared(&BlS[0][0]);
    const uint32_t strideA = BM * 2 * 16;
    const uint32_t strideB = BN * 2 * 16;

    float acc[MI][NF][4];
#pragma unroll
    for (int i = 0; i < MI; i++)
#pragma unroll
        for (int j = 0; j < NF; j++)
#pragma unroll
            for (int r = 0; r < 4; r++) acc[i][j][r] = 0.f;

    const int nk = K / 16;
    gload(0);
    sstore(0);
    __syncthreads();

    int cur = 0;
    for (int kt = 0; kt < nk; kt++) {
        if (kt + 1 < nk) gload((kt + 1) * 16);

        uint32_t ah[MI][4], al[MI][4];
        uint32_t bh[8], bl[8];
        {
            uint32_t off0 = (uint32_t)(swz(wn + b_r,      b_c) * 16);
            uint32_t off1 = (uint32_t)(swz(wn + 16 + b_r, b_c) * 16);
            ldsm_x4(bh[0], bh[1], bh[2], bh[3], baseBh + cur * strideB + off0);
            ldsm_x4(bh[4], bh[5], bh[6], bh[7], baseBh + cur * strideB + off1);
            ldsm_x4(bl[0], bl[1], bl[2], bl[3], baseBl + cur * strideB + off0);
            ldsm_x4(bl[4], bl[5], bl[6], bl[7], baseBl + cur * strideB + off1);
        }
#pragma unroll
        for (int i = 0; i < MI; i++) {
            int row = wm + i * 16 + a_r;
            uint32_t off = (uint32_t)(swz(row, a_c) * 16);
            ldsm_x4(ah[i][0], ah[i][1], ah[i][2], ah[i][3], baseAh + cur * strideA + off);
            ldsm_x4(al[i][0], al[i][1], al[i][2], al[i][3], baseAl + cur * strideA + off);
        }

#pragma unroll
        for (int j = 0; j < NF; j++) {
            uint32_t b0h = bh[j * 2], b1h = bh[j * 2 + 1];
            uint32_t b0l = bl[j * 2], b1l = bl[j * 2 + 1];
#pragma unroll
            for (int i = 0; i < MI; i++) {
                mma_bf16(acc[i][j], ah[i][0], ah[i][1], ah[i][2], ah[i][3], b0h, b1h);
                mma_bf16(acc[i][j], ah[i][0], ah[i][1], ah[i][2], ah[i][3], b0l, b1l);
                mma_bf16(acc[i][j], al[i][0], al[i][1], al[i][2], al[i][3], b0h, b1h);
            }
        }

        if (kt + 1 < nk) sstore(cur ^ 1);
        __syncthreads();
        cur ^= 1;
    }

    auto emit = [&](int m, int n, float v) {
        if (m >= M || n >= N) return;
        if (EPI == EPI_STORE) {
            C[(size_t)m * ldc + n] = v;
        } else if (EPI == EPI_SOFTPLUS) {
            v += bias[n];
            C[(size_t)m * ldc + n] = (v > 20.f) ? v : log1pf(__expf(v));
        } else if (EPI == EPI_RESID) {
            int b = m / LL, l = m - b * LL;
            int lo = map_row(l, dir);
            int row = b * LL + lo;
            C[((size_t)row * 2 + dir) * CM + n] = aux[(size_t)row * CM + n] + v;
        } else if (EPI == EPI_GATE) {
            float gg = sigmoidf_(v + bias[n]);
            float of = aux[(size_t)m * (2 * CM) + n];
            float ob = aux[(size_t)m * (2 * CM) + CM + n];
            C[(size_t)m * ldc + n] = gg * of + (1.f - gg) * ob;
        } else {
            C[(size_t)m * ldc + n] = v + bias[n];
        }
    };

#pragma unroll
    for (int i = 0; i < MI; i++) {
        int mr = m0 + wm + i * 16 + g;
#pragma unroll
        for (int j = 0; j < NF; j++) {
            int nc = n0 + wn + j * 8 + 2 * tg;
            emit(mr,     nc,     acc[i][j][0]);
            emit(mr,     nc + 1, acc[i][j][1]);
            emit(mr + 8, nc,     acc[i][j][2]);
            emit(mr + 8, nc + 1, acc[i][j][3]);
        }
    }
}

// ---------------------------------------------------------------------------
// SIMT split-K GEMM for the skinny x_proj (N=80)
// ---------------------------------------------------------------------------
template <int TM, int TN, int TK, int KS>
__global__ void __launch_bounds__(256, 2)
gemm_splitk(const float* __restrict__ Ab, int lda, size_t sA,
            const float* __restrict__ Wb, size_t sW,
            float* __restrict__ Cb, int ldc, size_t sC,
            int M, int N, int K) {
    constexpr int RM = TM / 16;
    constexpr int RN = TN / 16;
    constexpr int A4 = TM * TK / 4;
    constexpr int B4 = TN * TK / 4;
    constexpr int RA = (A4 + 255) / 256;
    constexpr int RB = (B4 + 255) / 256;

    __shared__ float As[2][TK][TM + 4];
    __shared__ float Bs[2][TK][TN + 4];

    const int t  = threadIdx.x;
    const int tx = t & 15;
    const int ty = t >> 4;
    const int m0 = blockIdx.y * TM;
    const int n0 = blockIdx.x * TN;

    const int z = blockIdx.z;
    const int dir   = z / KS;
    const int split = z % KS;

    const float* A = Ab + (size_t)dir * sA;
    const float* W = Wb + (size_t)dir * sW;
    float*       C = Cb + (size_t)dir * sC;

    const int Kpart = K / KS;
    const int kbeg  = split * Kpart;
    const int nk    = Kpart / TK;

    float4 ra[RA], rb[RB];

    auto gload = [&](int k0) {
#pragma unroll
        for (int i = 0; i < RA; i++) {
            int idx = t + i * 256;
            float4 v = make_float4(0.f, 0.f, 0.f, 0.f);
            if (idx < A4) {
                int m = idx / (TK / 4), kq = idx % (TK / 4);
                int gm = m0 + m;
                if (gm < M) v = *(const float4*)&A[(size_t)gm * lda + k0 + kq * 4];
            }
            ra[i] = v;
        }
#pragma unroll
        for (int i = 0; i < RB; i++) {
            int idx = t + i * 256;
            float4 v = make_float4(0.f, 0.f, 0.f, 0.f);
            if (idx < B4) {
                int n = idx / (TK / 4), kq = idx % (TK / 4);
                int gn = n0 + n;
                if (gn < N) v = *(const float4*)&W[(size_t)gn * K + k0 + kq * 4];
            }
            rb[i] = v;
        }
    };
    auto sstore = [&](int s) {
#pragma unroll
        for (int i = 0; i < RA; i++) {
            int idx = t + i * 256;
            if (idx < A4) {
                int m = idx / (TK / 4), kq = (idx % (TK / 4)) * 4;
                As[s][kq + 0][m] = ra[i].x; As[s][kq + 1][m] = ra[i].y;
                As[s][kq + 2][m] = ra[i].z; As[s][kq + 3][m] = ra[i].w;
            }
        }
#pragma unroll
        for (int i = 0; i < RB; i++) {
            int idx = t + i * 256;
            if (idx < B4) {
                int n = idx / (TK / 4), kq = (idx % (TK / 4)) * 4;
                Bs[s][kq + 0][n] = rb[i].x; Bs[s][kq + 1][n] = rb[i].y;
                Bs[s][kq + 2][n] = rb[i].z; Bs[s][kq + 3][n] = rb[i].w;
            }
        }
    };

    float acc[RM][RN];
#pragma unroll
    for (int i = 0; i < RM; i++)
#pragma unroll
        for (int j = 0; j < RN; j++) acc[i][j] = 0.f;

    gload(kbeg);
    sstore(0);
    __syncthreads();

    int cur = 0;
    for (int kt = 0; kt < nk; kt++) {
        if (kt + 1 < nk) gload(kbeg + (kt + 1) * TK);
#pragma unroll
        for (int k = 0; k < TK; k++) {
            float af[RM], bf[RN];
#pragma unroll
            for (int i = 0; i < RM; i++) af[i] = As[cur][k][ty * RM + i];
#pragma unroll
            for (int j = 0; j < RN; j++) bf[j] = Bs[cur][k][tx * RN + j];
#pragma unroll
            for (int i = 0; i < RM; i++)
#pragma unroll
                for (int j = 0; j < RN; j++)
                    acc[i][j] = fmaf(af[i], bf[j], acc[i][j]);
        }
        __syncthreads();
        if (kt + 1 < nk) {
            sstore(cur ^ 1);
            __syncthreads();
            cur ^= 1;
        }
    }

#pragma unroll
    for (int i = 0; i < RM; i++) {
        int m = m0 + ty * RM + i;
        if (m >= M) continue;
#pragma unroll
        for (int j = 0; j < RN; j++) {
            int n = n0 + tx * RN + j;
            if (n >= N) continue;
            atomicAdd(&C[(size_t)m * ldc + n], acc[i][j]);
        }
    }
}

// ---------------------------------------------------------------------------
__global__ void conv_silu_kernel(const float* __restrict__ conv_w,
                                 const float* __restrict__ conv_b) {
    int idx = blockIdx.x * blockDim.x + threadIdx.x;
    if (idx >= 2 * MM * DI) return;
    int d = idx % DI;
    int r = idx / DI;
    int dir = r / MM;
    int l = r % LL;

    const float* w = conv_w + (size_t)(dir * DI + d) * DCONV;
    float acc = conv_b[dir * DI + d];
#pragma unroll
    for (int j = 0; j < DCONV; j++) {
        int ls = l - (DCONV - 1) + j;
        if (ls >= 0)
            acc = fmaf(w[j], g_xz[(size_t)(r - (DCONV - 1) + j) * (2 * DI) + d], acc);
    }
    g_xb[(size_t)r * DI + d] = siluf_(acc);
}

// ---------------------------------------------------------------------------
// chunked scan, pass 1: per (d,b,dir,chunk) local scan from h=0.
// grid (DI/128, BB, 2*CH), block 128.
// ---------------------------------------------------------------------------
__global__ void __launch_bounds__(128, 8)
scan_p1() {
    int d   = blockIdx.x * blockDim.x + threadIdx.x;
    int b   = blockIdx.y;
    int z   = blockIdx.z;
    int dir = z / CH;
    int c   = z % CH;

    const float* Arow = &g_A[(dir * DI + d) * DS];
    float a0 = Arow[0];
    float da = Arow[1] - Arow[0];
    float Ar[DS];
    bool arith = (g_arith != 0);
    if (!arith) {
#pragma unroll
        for (int n = 0; n < DS; n++) Ar[n] = Arow[n];
    }

    float h[DS];
#pragma unroll
    for (int n = 0; n < DS; n++) h[n] = 0.f;
    float sdt = 0.f;

    size_t r0 = (size_t)dir * MM + (size_t)b * LL + (size_t)c * CLEN;
    for (int l = 0; l < CLEN; l++) {
        size_t r = r0 + l;
        float u  = g_xb[r * DI + d];
        float dt = g_dt[r * DI + d];
        const float4* Bv = (const float4*)(&g_xdbl[r * 80 + DR]);
        float4 B0 = __ldg(&Bv[0]), B1 = __ldg(&Bv[1]);
        float4 B2 = __ldg(&Bv[2]), B3 = __ldg(&Bv[3]);
        float Bl[DS] = {B0.x, B0.y, B0.z, B0.w, B1.x, B1.y, B1.z, B1.w,
                        B2.x, B2.y, B2.z, B2.w, B3.x, B3.y, B3.z, B3.w};
        float du = dt * u;
        if (arith) {
            float p  = __expf(dt * a0);
            float rr = __expf(dt * da);
#pragma unroll
            for (int n = 0; n < DS; n++) {
                h[n] = fmaf(p, h[n], du * Bl[n]);
                p *= rr;
            }
        } else {
#pragma unroll
            for (int n = 0; n < DS; n++)
                h[n] = fmaf(__expf(dt * Ar[n]), h[n], du * Bl[n]);
        }
        sdt += dt;
    }

    size_t base = (((size_t)(dir * BB + b) * CH + c) * DI + d);
    g_sumdt[base] = sdt;
    float4* Sp = (float4*)&g_S[base * DS];
#pragma unroll
    for (int q = 0; q < 4; q++)
        Sp[q] = make_float4(h[q * 4], h[q * 4 + 1], h[q * 4 + 2], h[q * 4 + 3]);
}

// ---------------------------------------------------------------------------
// chunked scan, pass 2: sequential combine over CH chunks per (d,b,dir).
// ---------------------------------------------------------------------------
__global__ void scan_p2() {
    int idx = blockIdx.x * blockDim.x + threadIdx.x;
    if (idx >= 2 * BB * DI) return;
    int d  = idx % DI;
    int bd = idx / DI;         // dir*BB + b
    int dir = bd / BB;

    const float* Arow = &g_A[(dir * DI + d) * DS];
    float a0 = Arow[0];
    float da = Arow[1] - Arow[0];
    float Ar[DS];
    bool arith = (g_arith != 0);
    if (!arith) {
#pragma unroll
        for (int n = 0; n < DS; n++) Ar[n] = Arow[n];
    }

    float h[DS];
#pragma unroll
    for (int n = 0; n < DS; n++) h[n] = 0.f;

    for (int c = 0; c < CH; c++) {
        size_t base = (((size_t)bd * CH + c) * DI + d);
        float4* Hp = (float4*)&g_h0[base * DS];
#pragma unroll
        for (int q = 0; q < 4; q++)
            Hp[q] = make_float4(h[q * 4], h[q * 4 + 1], h[q * 4 + 2], h[q * 4 + 3]);

        float sdt = g_sumdt[base];
        const float4* Sp = (const float4*)&g_S[base * DS];
        float4 S0 = Sp[0], S1 = Sp[1], S2 = Sp[2], S3 = Sp[3];
        float Sl[DS] = {S0.x, S0.y, S0.z, S0.w, S1.x, S1.y, S1.z, S1.w,
                        S2.x, S2.y, S2.z, S2.w, S3.x, S3.y, S3.z, S3.w};
        if (arith) {
            float p  = __expf(sdt * a0);
            float rr = __expf(sdt * da);
#pragma unroll
            for (int n = 0; n < DS; n++) {
                h[n] = fmaf(p, h[n], Sl[n]);
                p *= rr;
            }
        } else {
#pragma unroll
            for (int n = 0; n < DS; n++)
                h[n] = fmaf(__expf(sdt * Ar[n]), h[n], Sl[n]);
        }
    }
}

// ---------------------------------------------------------------------------
// chunked scan, pass 3: full scan from h0[c], emit y*silu(z).
// ---------------------------------------------------------------------------
__global__ void __launch_bounds__(128, 8)
scan_p3(const float* __restrict__ Dp) {
    int d   = blockIdx.x * blockDim.x + threadIdx.x;
    int b   = blockIdx.y;
    int z   = blockIdx.z;
    int dir = z / CH;
    int c   = z % CH;

    const float* Arow = &g_A[(dir * DI + d) * DS];
    float a0 = Arow[0];
    float da = Arow[1] - Arow[0];
    float Ar[DS];
    bool arith = (g_arith != 0);
    if (!arith) {
#pragma unroll
        for (int n = 0; n < DS; n++) Ar[n] = Arow[n];
    }

    size_t base = (((size_t)(dir * BB + b) * CH + c) * DI + d);
    float h[DS];
    {
        const float4* Hp = (const float4*)&g_h0[base * DS];
        float4 H0 = Hp[0], H1 = Hp[1], H2 = Hp[2], H3 = Hp[3];
        h[0] = H0.x;  h[1] = H0.y;  h[2] = H0.z;  h[3] = H0.w;
        h[4] = H1.x;  h[5] = H1.y;  h[6] = H1.z;  h[7] = H1.w;
        h[8] = H2.x;  h[9] = H2.y;  h[10] = H2.z; h[11] = H2.w;
        h[12] = H3.x; h[13] = H3.y; h[14] = H3.z; h[15] = H3.w;
    }

    float Dd = Dp[dir * DI + d];
    size_t r0 = (size_t)dir * MM + (size_t)b * LL + (size_t)c * CLEN;

    for (int l = 0; l < CLEN; l++) {
        size_t r = r0 + l;
        float u  = g_xb[r * DI + d];
        float dt = g_dt[r * DI + d];
        const float4* BC = (const float4*)(&g_xdbl[r * 80 + DR]);
        float4 Bv0 = __ldg(&BC[0]), Bv1 = __ldg(&BC[1]);
        float4 Bv2 = __ldg(&BC[2]), Bv3 = __ldg(&BC[3]);
        float4 Cv0 = __ldg(&BC[4]), Cv1 = __ldg(&BC[5]);
        float4 Cv2 = __ldg(&BC[6]), Cv3 = __ldg(&BC[7]);
        float Bl[DS] = {Bv0.x, Bv0.y, Bv0.z, Bv0.w, Bv1.x, Bv1.y, Bv1.z, Bv1.w,
                        Bv2.x, Bv2.y, Bv2.z, Bv2.w, Bv3.x, Bv3.y, Bv3.z, Bv3.w};
        float Cl[DS] = {Cv0.x, Cv0.y, Cv0.z, Cv0.w, Cv1.x, Cv1.y, Cv1.z, Cv1.w,
                        Cv2.x, Cv2.y, Cv2.z, Cv2.w, Cv3.x, Cv3.y, Cv3.z, Cv3.w};

        float du = dt * u;
        float yv = 0.f;
        if (arith) {
            float p  = __expf(dt * a0);
            float rr = __expf(dt * da);
#pragma unroll
            for (int n = 0; n < DS; n++) {
                h[n] = fmaf(p, h[n], du * Bl[n]);
                yv   = fmaf(h[n], Cl[n], yv);
                p *= rr;
            }
        } else {
#pragma unroll
            for (int n = 0; n < DS; n++) {
                float p = __expf(dt * Ar[n]);
                h[n] = fmaf(p, h[n], du * Bl[n]);
                yv   = fmaf(h[n], Cl[n], yv);
            }
        }
        yv = fmaf(u, Dd, yv);
        float zz = g_xz[r * (2 * DI) + DI + d];
        g_y[r * DI + d] = yv * siluf_(zz);
    }
}

// ---------------------------------------------------------------------------
extern "C" void kernel_launch(void* const* d_in, const int* in_sizes, int n_in,
                              void* d_out, int out_size) {
    const float* x         = (const float*)d_in[0];
    const float* norm_w    = (const float*)d_in[1];
    const float* in_proj_w = (const float*)d_in[2];
    const float* conv_w    = (const float*)d_in[3];
    const float* conv_b    = (const float*)d_in[4];
    const float* x_proj_w  = (const float*)d_in[5];
    const float* dt_proj_w = (const float*)d_in[6];
    const float* dt_proj_b = (const float*)d_in[7];
    const float* A_log     = (const float*)d_in[8];
    const float* Dp        = (const float*)d_in[9];
    const float* mix_out_w = (const float*)d_in[10];
    const float* gate_w    = (const float*)d_in[11];
    const float* gate_b    = (const float*)d_in[12];
    const float* proj_w    = (const float*)d_in[13];
    const float* proj_b    = (const float*)d_in[14];
    float* out = (float*)d_out;

    float *xn, *xz, *xb, *xdbl, *dt, *y, *o_out, *comb;
    cudaGetSymbolAddress((void**)&xn,    g_xn);
    cudaGetSymbolAddress((void**)&xz,    g_xz);
    cudaGetSymbolAddress((void**)&xb,    g_xb);
    cudaGetSymbolAddress((void**)&xdbl,  g_xdbl);
    cudaGetSymbolAddress((void**)&dt,    g_dt);
    cudaGetSymbolAddress((void**)&y,     g_y);
    cudaGetSymbolAddress((void**)&o_out, g_out);
    cudaGetSymbolAddress((void**)&comb,  g_comb);

    setup_A_kernel<<<(2 * DI * DS + 255) / 256, 256>>>(A_log);
    check_arith_kernel<<<1, 256>>>();

    rmsnorm_kernel<<<2 * MM, 256>>>(x, norm_w);

    const int MY128 = (MM + 127) / 128;   // 13
    const int MY64  = (MM + 63) / 64;     // 25

    // in_proj: BM=128, 624 CTAs
    gemm_bf16x2<128, EPI_STORE><<<dim3(2 * DI / 128, MY128, 2), 256>>>(
        xn, CM, (size_t)MM * CM,
        in_proj_w, (size_t)2 * DI * CM,
        xz, 2 * DI, (size_t)MM * 2 * DI,
        MM, 2 * DI, CM, nullptr, 0, nullptr);

    conv_silu_kernel<<<(2 * MM * DI + 255) / 256, 256>>>(conv_w, conv_b);

    // x_proj: split-K=8 SIMT
    cudaMemsetAsync(xdbl, 0, sizeof(float) * 2 * MM * 80);
    gemm_splitk<128, 80, 16, 8><<<dim3(1, MY128, 2 * 8), 256>>>(
        xb, DI, (size_t)MM * DI,
        x_proj_w, (size_t)80 * DI,
        xdbl, 80, (size_t)MM * 80,
        MM, 80, DI);

    // dt_proj + softplus
    gemm_bf16x2<128, EPI_SOFTPLUS><<<dim3(DI / 128, MY128, 2), 256>>>(
        xdbl, 80, (size_t)MM * 80,
        dt_proj_w, (size_t)DI * DR,
        dt, DI, (size_t)MM * DI,
        MM, DI, DR, dt_proj_b, DI, nullptr);

    // chunked parallel scan (CH=49, CLEN=16)
    scan_p1<<<dim3(DI / 128, BB, 2 * CH), 128>>>();
    scan_p2<<<(2 * BB * DI + 255) / 256, 256>>>();
    scan_p3<<<dim3(DI / 128, BB, 2 * CH), 128>>>(Dp);

    // out_proj + residual + flip-scatter — BM=64
    gemm_bf16x2<64, EPI_RESID><<<dim3(CM / 128, MY64, 2), 256>>>(
        y, DI, (size_t)MM * DI,
        mix_out_w, (size_t)CM * DI,
        o_out, 0, 0,
        MM, CM, DI, nullptr, 0, x);

    // gate GEMM + sigmoid combine — BM=64
    gemm_bf16x2<64, EPI_GATE><<<dim3(CM / 128, MY64, 1), 256>>>(
        o_out, 2 * CM, 0,
        gate_w, 0,
        comb, CM, 0,
        MM, CM, 2 * CM, gate_b, 0, o_out);

    // final projection + bias — BM=64
    gemm_bf16x2<64, EPI_BIAS><<<dim3(CM / 128, MY64, 1), 256>>>(
        comb, CM, 0,
        proj_w, 0,
        out, CM, 0,
        MM, CM, CM, proj_b, 0, nullptr);

    (void)in_sizes; (void)n_in; (void)out_size;
}

// round 13
// speedup vs baseline: 2.0453x; 1.0257x over previous
#include <cuda_runtime.h>
#include <cuda_bf16.h>
#include <cstdint>

// ---------------------------------------------------------------------------
// BiMamba refiner block, round 12: balanced split-K tail GEMMs (atomic
// epilogues, pre-initialized outputs), x_proj on the MMA path. Scan CH=49.
// ---------------------------------------------------------------------------

#define BB      2
#define TT      4
#define NP      196
#define LL      784
#define MM      1568
#define CM      768
#define DI      1536
#define DS      16
#define DR      48
#define DCONV   4
#define CH      49
#define CLEN    16      // LL / CH

// ---------------- scratch ---------------------------------------------------
__device__ float g_xn  [2 * MM * CM];     // rmsnorm out; later reused as comb
__device__ float g_xz  [2 * MM * 2 * DI];
__device__ float g_xb  [2 * MM * DI];
__device__ float g_xdbl[2 * MM * 80];
__device__ float g_dt  [2 * MM * DI];
__device__ float g_y   [2 * MM * DI];
__device__ float g_out [MM * 2 * CM];
__device__ float g_comb[MM * CM];         // gate GEMM raw accumulator
__device__ float g_A   [2 * DI * DS];
__device__ int   g_arith;
// scan chunk scratch
__device__ float g_S    [2 * BB * CH * DI * DS];
__device__ float g_h0   [2 * BB * CH * DI * DS];
__device__ float g_sumdt[2 * BB * CH * DI];

__device__ __forceinline__ int map_row(int l, int dir) {
    if (dir == 0) return l;
    int t = l / NP, n = l - t * NP;
    return (TT - 1 - t) * NP + n;
}
__device__ __forceinline__ float sigmoidf_(float v) { return 1.0f / (1.0f + __expf(-v)); }
__device__ __forceinline__ float siluf_(float v)    { return v * sigmoidf_(v); }

// pack two floats into bf16x2 hi and lo residual
__device__ __forceinline__ void split2(float x, float y, uint32_t& hi, uint32_t& lo) {
    __nv_bfloat16 hx = __float2bfloat16(x);
    __nv_bfloat16 hy = __float2bfloat16(y);
    __nv_bfloat16 lx = __float2bfloat16(x - __bfloat162float(hx));
    __nv_bfloat16 ly = __float2bfloat16(y - __bfloat162float(hy));
    __nv_bfloat162 h2 = __halves2bfloat162(hx, hy);
    __nv_bfloat162 l2 = __halves2bfloat162(lx, ly);
    hi = *reinterpret_cast<uint32_t*>(&h2);
    lo = *reinterpret_cast<uint32_t*>(&l2);
}

__device__ __forceinline__ void mma_bf16(float c[4],
                                         uint32_t a0, uint32_t a1, uint32_t a2, uint32_t a3,
                                         uint32_t b0, uint32_t b1) {
    asm volatile(
        "mma.sync.aligned.m16n8k16.row.col.f32.bf16.bf16.f32 "
        "{%0,%1,%2,%3},{%4,%5,%6,%7},{%8,%9},{%0,%1,%2,%3};"
        : "+f"(c[0]), "+f"(c[1]), "+f"(c[2]), "+f"(c[3])
        : "r"(a0), "r"(a1), "r"(a2), "r"(a3), "r"(b0), "r"(b1));
}

__device__ __forceinline__ void ldsm_x4(uint32_t& r0, uint32_t& r1, uint32_t& r2,
                                        uint32_t& r3, uint32_t addr) {
    asm volatile("ldmatrix.sync.aligned.m8n8.x4.shared.b16 {%0,%1,%2,%3}, [%4];"
                 : "=r"(r0), "=r"(r1), "=r"(r2), "=r"(r3) : "r"(addr));
}

__device__ __forceinline__ int swz(int row, int chunk) {
    return row * 2 + (chunk ^ ((row >> 2) & 1));
}

// ---------------------------------------------------------------------------
__global__ void setup_A_kernel(const float* __restrict__ A_log) {
    int i = blockIdx.x * blockDim.x + threadIdx.x;
    if (i < 2 * DI * DS) g_A[i] = -expf(A_log[i]);
}

__global__ void check_arith_kernel() {
    __shared__ int bad;
    if (threadIdx.x == 0) bad = 0;
    __syncthreads();
    for (int row = threadIdx.x; row < 2 * DI; row += blockDim.x) {
        const float* a = &g_A[row * DS];
        float a0 = a[0], da = a[1] - a[0];
        for (int n = 2; n < DS; n++) {
            float expect = a0 + n * da;
            if (fabsf(a[n] - expect) > 1e-4f * (1.0f + fabsf(a[n]))) { bad = 1; break; }
        }
    }
    __syncthreads();
    if (threadIdx.x == 0) g_arith = bad ? 0 : 1;
}

__global__ void rmsnorm_kernel(const float* __restrict__ x,
                               const float* __restrict__ norm_w) {
    int gid = blockIdx.x;
    int dir = gid / MM;
    int rem = gid - dir * MM;
    int b   = rem / LL, l = rem - b * LL;
    int lo  = map_row(l, dir);
    const float* row = x + (size_t)(b * LL + lo) * CM;

    float s = 0.f;
    for (int c = threadIdx.x; c < CM; c += blockDim.x) {
        float v = row[c];
        s += v * v;
    }
    __shared__ float warp_s[8];
    for (int off = 16; off > 0; off >>= 1) s += __shfl_down_sync(0xffffffffu, s, off);
    if ((threadIdx.x & 31) == 0) warp_s[threadIdx.x >> 5] = s;
    __syncthreads();
    if (threadIdx.x < 8) {
        float t = warp_s[threadIdx.x];
        for (int off = 4; off > 0; off >>= 1) t += __shfl_down_sync(0xffu, t, off);
        if (threadIdx.x == 0) warp_s[0] = t;
    }
    __syncthreads();
    float scale = rsqrtf(warp_s[0] / (float)CM + 1e-5f);

    float* dst = g_xn + (size_t)gid * CM;
    const float* nw = norm_w + dir * CM;
    for (int c = threadIdx.x; c < CM; c += blockDim.x)
        dst[c] = row[c] * scale * nw[c];
}

// o_out[(row,dir,:)] = x[row,:]  (residual pre-init for atomic out_proj)
__global__ void init_oout_kernel(const float* __restrict__ x) {
    int idx = blockIdx.x * blockDim.x + threadIdx.x;
    if (idx >= MM * CM) return;
    int row = idx / CM, n = idx % CM;
    float v = x[idx];
    g_out[((size_t)row * 2 + 0) * CM + n] = v;
    g_out[((size_t)row * 2 + 1) * CM + n] = v;
}

// out pre-init with bias (for atomic final GEMM)
__global__ void init_bias_kernel(float* __restrict__ C, const float* __restrict__ bias,
                                 int M, int N) {
    int idx = blockIdx.x * blockDim.x + threadIdx.x;
    if (idx >= M * N) return;
    C[idx] = bias[idx % N];
}

// gate combine: comb_final(g_xn) = sigmoid(raw + gate_b) * of + (1-g) * ob
__global__ void gate_combine_kernel(const float* __restrict__ gate_b) {
    int idx = blockIdx.x * blockDim.x + threadIdx.x;
    if (idx >= MM * CM) return;
    int m = idx / CM, n = idx % CM;
    float g = sigmoidf_(g_comb[idx] + gate_b[n]);
    float of = g_out[(size_t)m * (2 * CM) + n];
    float ob = g_out[(size_t)m * (2 * CM) + CM + n];
    g_xn[idx] = g * of + (1.f - g) * ob;
}

// ---------------------------------------------------------------------------
// bf16x2 MMA GEMM; KS-way split-K via gridDim.z = dirs*KS.
// ---------------------------------------------------------------------------
#define EPI_STORE      0
#define EPI_SOFTPLUS   1
#define EPI_ATOM       2   // atomicAdd into C[m*ldc+n]
#define EPI_ATOM_RESID 3   // atomicAdd into g_out with flip-scatter

template <int BM, int EPI, int KS>
__global__ void __launch_bounds__(256)
gemm_bf16x2(const float* __restrict__ Ab, int lda, size_t sA,
            const float* __restrict__ Wb, size_t sW,
            float* __restrict__ Cb, int ldc, size_t sC,
            int M, int N, int K,
            const float* __restrict__ biasb, size_t sBias) {
    constexpr int BN = 128;
    constexpr int NF = 4;
    constexpr int MI = BM / 32;

    __shared__ uint4 AhS[2][BM * 2], AlS[2][BM * 2];
    __shared__ uint4 BhS[2][BN * 2], BlS[2][BN * 2];

    const int t    = threadIdx.x;
    const int lane = t & 31;
    const int w    = t >> 5;
    const int wm   = (w & 1) * (BM / 2);
    const int wn   = (w >> 1) * 32;
    const int g    = lane >> 2;
    const int tg   = lane & 3;

    const int m0   = blockIdx.y * BM;
    const int n0   = blockIdx.x * BN;
    const int z    = blockIdx.z;
    const int dir  = z / KS;
    const int split = z % KS;
    const int Kpart = K / KS;
    const int kbeg  = split * Kpart;

    const float* A = Ab + (size_t)dir * sA;
    const float* W = Wb + (size_t)dir * sW;
    float*       C = Cb + (size_t)dir * sC;
    const float* bias = biasb ? biasb + (size_t)dir * sBias : nullptr;

    const int srow = t >> 1;
    const int skh  = (t & 1) * 8;
    const bool doA = (t < BM * 2);

    float4 ra0, ra1, rb0, rb1;
    auto gload = [&](int k0) {
        if (doA) {
            int gm = m0 + srow;
            if (gm < M) {
                ra0 = *(const float4*)&A[(size_t)gm * lda + k0 + skh];
                ra1 = *(const float4*)&A[(size_t)gm * lda + k0 + skh + 4];
            } else {
                ra0 = make_float4(0.f, 0.f, 0.f, 0.f); ra1 = ra0;
            }
        }
        int gn = n0 + srow;
        if (gn < N) {
            rb0 = *(const float4*)&W[(size_t)gn * K + k0 + skh];
            rb1 = *(const float4*)&W[(size_t)gn * K + k0 + skh + 4];
        } else {
            rb0 = make_float4(0.f, 0.f, 0.f, 0.f); rb1 = rb0;
        }
    };
    auto sstore = [&](int s) {
        uint4 h4, l4;
        if (doA) {
            split2(ra0.x, ra0.y, h4.x, l4.x);
            split2(ra0.z, ra0.w, h4.y, l4.y);
            split2(ra1.x, ra1.y, h4.z, l4.z);
            split2(ra1.z, ra1.w, h4.w, l4.w);
            int ai = swz(srow, t & 1);
            AhS[s][ai] = h4; AlS[s][ai] = l4;
        }
        split2(rb0.x, rb0.y, h4.x, l4.x);
        split2(rb0.z, rb0.w, h4.y, l4.y);
        split2(rb1.x, rb1.y, h4.z, l4.z);
        split2(rb1.z, rb1.w, h4.w, l4.w);
        int bi = swz(srow, t & 1);
        BhS[s][bi] = h4; BlS[s][bi] = l4;
    };

    const int a_r = lane & 15;
    const int a_c = lane >> 4;
    const int b_r = (lane & 7) + ((lane & 16) ? 8 : 0);
    const int b_c = (lane >> 3) & 1;

    const uint32_t baseAh = (uint32_t)__cvta_generic_to_shared(&AhS[0][0]);
    const uint32_t baseAl = (uint32_t)__cvta_generic_to_shared(&AlS[0][0]);
    const uint32_t baseBh = (uint32_t)__cvta_generic_to_shared(&BhS[0][0]);
    const uint32_t baseBl = (uint32_t)__cvta_generic_to_shared(&BlS[0][0]);
    const uint32_t strideA = BM * 2 * 16;
    const uint32_t strideB = BN * 2 * 16;

    float acc[MI][NF][4];
#pragma unroll
    for (int i = 0; i < MI; i++)
#pragma unroll
        for (int j = 0; j < NF; j++)
#pragma unroll
            for (int r = 0; r < 4; r++) acc[i][j][r] = 0.f;

    const int nk = Kpart / 16;
    gload(kbeg);
    sstore(0);
    __syncthreads();

    int cur = 0;
    for (int kt = 0; kt < nk; kt++) {
        if (kt + 1 < nk) gload(kbeg + (kt + 1) * 16);

        uint32_t ah[MI][4], al[MI][4];
        uint32_t bh[8], bl[8];
        {
            uint32_t off0 = (uint32_t)(swz(wn + b_r,      b_c) * 16);
            uint32_t off1 = (uint32_t)(swz(wn + 16 + b_r, b_c) * 16);
            ldsm_x4(bh[0], bh[1], bh[2], bh[3], baseBh + cur * strideB + off0);
            ldsm_x4(bh[4], bh[5], bh[6], bh[7], baseBh + cur * strideB + off1);
            ldsm_x4(bl[0], bl[1], bl[2], bl[3], baseBl + cur * strideB + off0);
            ldsm_x4(bl[4], bl[5], bl[6], bl[7], baseBl + cur * strideB + off1);
        }
#pragma unroll
        for (int i = 0; i < MI; i++) {
            int row = wm + i * 16 + a_r;
            uint32_t off = (uint32_t)(swz(row, a_c) * 16);
            ldsm_x4(ah[i][0], ah[i][1], ah[i][2], ah[i][3], baseAh + cur * strideA + off);
            ldsm_x4(al[i][0], al[i][1], al[i][2], al[i][3], baseAl + cur * strideA + off);
        }

#pragma unroll
        for (int j = 0; j < NF; j++) {
            uint32_t b0h = bh[j * 2], b1h = bh[j * 2 + 1];
            uint32_t b0l = bl[j * 2], b1l = bl[j * 2 + 1];
#pragma unroll
            for (int i = 0; i < MI; i++) {
                mma_bf16(acc[i][j], ah[i][0], ah[i][1], ah[i][2], ah[i][3], b0h, b1h);
                mma_bf16(acc[i][j], ah[i][0], ah[i][1], ah[i][2], ah[i][3], b0l, b1l);
                mma_bf16(acc[i][j], al[i][0], al[i][1], al[i][2], al[i][3], b0h, b1h);
            }
        }

        if (kt + 1 < nk) sstore(cur ^ 1);
        __syncthreads();
        cur ^= 1;
    }

    auto emit = [&](int m, int n, float v) {
        if (m >= M || n >= N) return;
        if (EPI == EPI_STORE) {
            C[(size_t)m * ldc + n] = v;
        } else if (EPI == EPI_SOFTPLUS) {
            v += bias[n];
            C[(size_t)m * ldc + n] = (v > 20.f) ? v : log1pf(__expf(v));
        } else if (EPI == EPI_ATOM) {
            atomicAdd(&C[(size_t)m * ldc + n], v);
        } else { // EPI_ATOM_RESID
            int b = m / LL, l = m - b * LL;
            int lo = map_row(l, dir);
            int row = b * LL + lo;
            atomicAdd(&g_out[((size_t)row * 2 + dir) * CM + n], v);
        }
    };

#pragma unroll
    for (int i = 0; i < MI; i++) {
        int mr = m0 + wm + i * 16 + g;
#pragma unroll
        for (int j = 0; j < NF; j++) {
            int nc = n0 + wn + j * 8 + 2 * tg;
            emit(mr,     nc,     acc[i][j][0]);
            emit(mr,     nc + 1, acc[i][j][1]);
            emit(mr + 8, nc,     acc[i][j][2]);
            emit(mr + 8, nc + 1, acc[i][j][3]);
        }
    }
}

// ---------------------------------------------------------------------------
__global__ void conv_silu_kernel(const float* __restrict__ conv_w,
                                 const float* __restrict__ conv_b) {
    int idx = blockIdx.x * blockDim.x + threadIdx.x;
    if (idx >= 2 * MM * DI) return;
    int d = idx % DI;
    int r = idx / DI;
    int dir = r / MM;
    int l = r % LL;

    const float* w = conv_w + (size_t)(dir * DI + d) * DCONV;
    float acc = conv_b[dir * DI + d];
#pragma unroll
    for (int j = 0; j < DCONV; j++) {
        int ls = l - (DCONV - 1) + j;
        if (ls >= 0)
            acc = fmaf(w[j], g_xz[(size_t)(r - (DCONV - 1) + j) * (2 * DI) + d], acc);
    }
    g_xb[(size_t)r * DI + d] = siluf_(acc);
}

// ---------------------------------------------------------------------------
// chunked scan (CH=49, CLEN=16), 3 passes
// ---------------------------------------------------------------------------
__global__ void __launch_bounds__(128, 8)
scan_p1() {
    int d   = blockIdx.x * blockDim.x + threadIdx.x;
    int b   = blockIdx.y;
    int z   = blockIdx.z;
    int dir = z / CH;
    int c   = z % CH;

    const float* Arow = &g_A[(dir * DI + d) * DS];
    float a0 = Arow[0];
    float da = Arow[1] - Arow[0];
    float Ar[DS];
    bool arith = (g_arith != 0);
    if (!arith) {
#pragma unroll
        for (int n = 0; n < DS; n++) Ar[n] = Arow[n];
    }

    float h[DS];
#pragma unroll
    for (int n = 0; n < DS; n++) h[n] = 0.f;
    float sdt = 0.f;

    size_t r0 = (size_t)dir * MM + (size_t)b * LL + (size_t)c * CLEN;
    for (int l = 0; l < CLEN; l++) {
        size_t r = r0 + l;
        float u  = g_xb[r * DI + d];
        float dt = g_dt[r * DI + d];
        const float4* Bv = (const float4*)(&g_xdbl[r * 80 + DR]);
        float4 B0 = __ldg(&Bv[0]), B1 = __ldg(&Bv[1]);
        float4 B2 = __ldg(&Bv[2]), B3 = __ldg(&Bv[3]);
        float Bl[DS] = {B0.x, B0.y, B0.z, B0.w, B1.x, B1.y, B1.z, B1.w,
                        B2.x, B2.y, B2.z, B2.w, B3.x, B3.y, B3.z, B3.w};
        float du = dt * u;
        if (arith) {
            float p  = __expf(dt * a0);
            float rr = __expf(dt * da);
#pragma unroll
            for (int n = 0; n < DS; n++) {
                h[n] = fmaf(p, h[n], du * Bl[n]);
                p *= rr;
            }
        } else {
#pragma unroll
            for (int n = 0; n < DS; n++)
                h[n] = fmaf(__expf(dt * Ar[n]), h[n], du * Bl[n]);
        }
        sdt += dt;
    }

    size_t base = (((size_t)(dir * BB + b) * CH + c) * DI + d);
    g_sumdt[base] = sdt;
    float4* Sp = (float4*)&g_S[base * DS];
#pragma unroll
    for (int q = 0; q < 4; q++)
        Sp[q] = make_float4(h[q * 4], h[q * 4 + 1], h[q * 4 + 2], h[q * 4 + 3]);
}

__global__ void scan_p2() {
    int idx = blockIdx.x * blockDim.x + threadIdx.x;
    if (idx >= 2 * BB * DI) return;
    int d  = idx % DI;
    int bd = idx / DI;
    int dir = bd / BB;

    const float* Arow = &g_A[(dir * DI + d) * DS];
    float a0 = Arow[0];
    float da = Arow[1] - Arow[0];
    float Ar[DS];
    bool arith = (g_arith != 0);
    if (!arith) {
#pragma unroll
        for (int n = 0; n < DS; n++) Ar[n] = Arow[n];
    }

    float h[DS];
#pragma unroll
    for (int n = 0; n < DS; n++) h[n] = 0.f;

    for (int c = 0; c < CH; c++) {
        size_t base = (((size_t)bd * CH + c) * DI + d);
        float4* Hp = (float4*)&g_h0[base * DS];
#pragma unroll
        for (int q = 0; q < 4; q++)
            Hp[q] = make_float4(h[q * 4], h[q * 4 + 1], h[q * 4 + 2], h[q * 4 + 3]);

        float sdt = g_sumdt[base];
        const float4* Sp = (const float4*)&g_S[base * DS];
        float4 S0 = Sp[0], S1 = Sp[1], S2 = Sp[2], S3 = Sp[3];
        float Sl[DS] = {S0.x, S0.y, S0.z, S0.w, S1.x, S1.y, S1.z, S1.w,
                        S2.x, S2.y, S2.z, S2.w, S3.x, S3.y, S3.z, S3.w};
        if (arith) {
            float p  = __expf(sdt * a0);
            float rr = __expf(sdt * da);
#pragma unroll
            for (int n = 0; n < DS; n++) {
                h[n] = fmaf(p, h[n], Sl[n]);
                p *= rr;
            }
        } else {
#pragma unroll
            for (int n = 0; n < DS; n++)
                h[n] = fmaf(__expf(sdt * Ar[n]), h[n], Sl[n]);
        }
    }
}

__global__ void __launch_bounds__(128, 8)
scan_p3(const float* __restrict__ Dp) {
    int d   = blockIdx.x * blockDim.x + threadIdx.x;
    int b   = blockIdx.y;
    int z   = blockIdx.z;
    int dir = z / CH;
    int c   = z % CH;

    const float* Arow = &g_A[(dir * DI + d) * DS];
    float a0 = Arow[0];
    float da = Arow[1] - Arow[0];
    float Ar[DS];
    bool arith = (g_arith != 0);
    if (!arith) {
#pragma unroll
        for (int n = 0; n < DS; n++) Ar[n] = Arow[n];
    }

    size_t base = (((size_t)(dir * BB + b) * CH + c) * DI + d);
    float h[DS];
    {
        const float4* Hp = (const float4*)&g_h0[base * DS];
        float4 H0 = Hp[0], H1 = Hp[1], H2 = Hp[2], H3 = Hp[3];
        h[0] = H0.x;  h[1] = H0.y;  h[2] = H0.z;  h[3] = H0.w;
        h[4] = H1.x;  h[5] = H1.y;  h[6] = H1.z;  h[7] = H1.w;
        h[8] = H2.x;  h[9] = H2.y;  h[10] = H2.z; h[11] = H2.w;
        h[12] = H3.x; h[13] = H3.y; h[14] = H3.z; h[15] = H3.w;
    }

    float Dd = Dp[dir * DI + d];
    size_t r0 = (size_t)dir * MM + (size_t)b * LL + (size_t)c * CLEN;

    for (int l = 0; l < CLEN; l++) {
        size_t r = r0 + l;
        float u  = g_xb[r * DI + d];
        float dt = g_dt[r * DI + d];
        const float4* BC = (const float4*)(&g_xdbl[r * 80 + DR]);
        float4 Bv0 = __ldg(&BC[0]), Bv1 = __ldg(&BC[1]);
        float4 Bv2 = __ldg(&BC[2]), Bv3 = __ldg(&BC[3]);
        float4 Cv0 = __ldg(&BC[4]), Cv1 = __ldg(&BC[5]);
        float4 Cv2 = __ldg(&BC[6]), Cv3 = __ldg(&BC[7]);
        float Bl[DS] = {Bv0.x, Bv0.y, Bv0.z, Bv0.w, Bv1.x, Bv1.y, Bv1.z, Bv1.w,
                        Bv2.x, Bv2.y, Bv2.z, Bv2.w, Bv3.x, Bv3.y, Bv3.z, Bv3.w};
        float Cl[DS] = {Cv0.x, Cv0.y, Cv0.z, Cv0.w, Cv1.x, Cv1.y, Cv1.z, Cv1.w,
                        Cv2.x, Cv2.y, Cv2.z, Cv2.w, Cv3.x, Cv3.y, Cv3.z, Cv3.w};

        float du = dt * u;
        float yv = 0.f;
        if (arith) {
            float p  = __expf(dt * a0);
            float rr = __expf(dt * da);
#pragma unroll
            for (int n = 0; n < DS; n++) {
                h[n] = fmaf(p, h[n], du * Bl[n]);
                yv   = fmaf(h[n], Cl[n], yv);
                p *= rr;
            }
        } else {
#pragma unroll
            for (int n = 0; n < DS; n++) {
                float p = __expf(dt * Ar[n]);
                h[n] = fmaf(p, h[n], du * Bl[n]);
                yv   = fmaf(h[n], Cl[n], yv);
            }
        }
        yv = fmaf(u, Dd, yv);
        float zz = g_xz[r * (2 * DI) + DI + d];
        g_y[r * DI + d] = yv * siluf_(zz);
    }
}

// ---------------------------------------------------------------------------
extern "C" void kernel_launch(void* const* d_in, const int* in_sizes, int n_in,
                              void* d_out, int out_size) {
    const float* x         = (const float*)d_in[0];
    const float* norm_w    = (const float*)d_in[1];
    const float* in_proj_w = (const float*)d_in[2];
    const float* conv_w    = (const float*)d_in[3];
    const float* conv_b    = (const float*)d_in[4];
    const float* x_proj_w  = (const float*)d_in[5];
    const float* dt_proj_w = (const float*)d_in[6];
    const float* dt_proj_b = (const float*)d_in[7];
    const float* A_log     = (const float*)d_in[8];
    const float* Dp        = (const float*)d_in[9];
    const float* mix_out_w = (const float*)d_in[10];
    const float* gate_w    = (const float*)d_in[11];
    const float* gate_b    = (const float*)d_in[12];
    const float* proj_w    = (const float*)d_in[13];
    const float* proj_b    = (const float*)d_in[14];
    float* out = (float*)d_out;

    float *xn, *xz, *xb, *xdbl, *dt, *y, *o_out, *comb;
    cudaGetSymbolAddress((void**)&xn,    g_xn);
    cudaGetSymbolAddress((void**)&xz,    g_xz);
    cudaGetSymbolAddress((void**)&xb,    g_xb);
    cudaGetSymbolAddress((void**)&xdbl,  g_xdbl);
    cudaGetSymbolAddress((void**)&dt,    g_dt);
    cudaGetSymbolAddress((void**)&y,     g_y);
    cudaGetSymbolAddress((void**)&o_out, g_out);
    cudaGetSymbolAddress((void**)&comb,  g_comb);

    setup_A_kernel<<<(2 * DI * DS + 255) / 256, 256>>>(A_log);
    check_arith_kernel<<<1, 256>>>();

    rmsnorm_kernel<<<2 * MM, 256>>>(x, norm_w);

    const int MY128 = (MM + 127) / 128;   // 13

    // in_proj: BM=128, 624 CTAs
    gemm_bf16x2<128, EPI_STORE, 1><<<dim3(2 * DI / 128, MY128, 2), 256>>>(
        xn, CM, (size_t)MM * CM,
        in_proj_w, (size_t)2 * DI * CM,
        xz, 2 * DI, (size_t)MM * 2 * DI,
        MM, 2 * DI, CM, nullptr, 0);

    conv_silu_kernel<<<(2 * MM * DI + 255) / 256, 256>>>(conv_w, conv_b);

    // x_proj: MMA split-K=8, 208 CTAs, atomic accumulate into zeroed xdbl
    cudaMemsetAsync(xdbl, 0, sizeof(float) * 2 * MM * 80);
    gemm_bf16x2<128, EPI_ATOM, 8><<<dim3(1, MY128, 2 * 8), 256>>>(
        xb, DI, (size_t)MM * DI,
        x_proj_w, (size_t)80 * DI,
        xdbl, 80, (size_t)MM * 80,
        MM, 80, DI, nullptr, 0);

    // dt_proj + softplus: 312 CTAs
    gemm_bf16x2<128, EPI_SOFTPLUS, 1><<<dim3(DI / 128, MY128, 2), 256>>>(
        xdbl, 80, (size_t)MM * 80,
        dt_proj_w, (size_t)DI * DR,
        dt, DI, (size_t)MM * DI,
        MM, DI, DR, dt_proj_b, DI);

    // chunked parallel scan
    scan_p1<<<dim3(DI / 128, BB, 2 * CH), 128>>>();
    scan_p2<<<(2 * BB * DI + 255) / 256, 256>>>();
    scan_p3<<<dim3(DI / 128, BB, 2 * CH), 128>>>(Dp);

    // out_proj: residual pre-init, then atomic flip-scatter split-K=2 (312 CTAs)
    init_oout_kernel<<<(MM * CM + 255) / 256, 256>>>(x);
    gemm_bf16x2<128, EPI_ATOM_RESID, 2><<<dim3(CM / 128, MY128, 2 * 2), 256>>>(
        y, DI, (size_t)MM * DI,
        mix_out_w, (size_t)CM * DI,
        o_out, 0, 0,
        MM, CM, DI, nullptr, 0);

    // gate GEMM raw accum: split-K=4 (312 CTAs) into zeroed comb
    cudaMemsetAsync(comb, 0, sizeof(float) * MM * CM);
    gemm_bf16x2<128, EPI_ATOM, 4><<<dim3(CM / 128, MY128, 4), 256>>>(
        o_out, 2 * CM, 0,
        gate_w, 0,
        comb, CM, 0,
        MM, CM, 2 * CM, nullptr, 0);

    // sigmoid combine -> xn (reused)
    gate_combine_kernel<<<(MM * CM + 255) / 256, 256>>>(gate_b);

    // final projection: bias pre-init, atomic split-K=4 (312 CTAs)
    init_bias_kernel<<<(MM * CM + 255) / 256, 256>>>(out, proj_b, MM, CM);
    gemm_bf16x2<128, EPI_ATOM, 4><<<dim3(CM / 128, MY128, 4), 256>>>(
        xn, CM, 0,
        proj_w, 0,
        out, CM, 0,
        MM, CM, CM, nullptr, 0);

    (void)in_sizes; (void)n_in; (void)out_size;
}

// round 14
// speedup vs baseline: 2.4762x; 1.2107x over previous
#include <cuda_runtime.h>
#include <cuda_bf16.h>
#include <cstdint>

// ---------------------------------------------------------------------------
// BiMamba refiner block, round 13: pre-split bf16 hi/lo operands (produced by
// producer kernels + one-shot weight splits) feeding cp.async 3-stage BK=32
// MMA GEMMs with a single sync per ktile. Split-K grids from round 12.
// ---------------------------------------------------------------------------

#define BB      2
#define TT      4
#define NP      196
#define LL      784
#define MM      1568
#define CM      768
#define DI      1536
#define DS      16
#define DR      48
#define DCONV   4
#define CH      49
#define CLEN    16

// weight segment offsets in the packed bf16 weight buffers
#define WOFF_IN   0L
#define WOFF_XP   4718592L
#define WOFF_DT   4964352L
#define WOFF_OUT  5111808L
#define WOFF_GATE 7471104L
#define WOFF_PROJ 8650752L
#define WTOTAL    9240576L

// ---------------- scratch ---------------------------------------------------
__device__ float g_xz  [2 * MM * 2 * DI];
__device__ float g_xb  [2 * MM * DI];
__device__ float g_xdbl[2 * MM * 80];
__device__ float g_dt  [2 * MM * DI];
__device__ float g_out [MM * 2 * CM];
__device__ float g_comb[MM * CM];
__device__ float g_A   [2 * DI * DS];
__device__ int   g_arith;
// scan chunk scratch
__device__ float g_S    [2 * BB * CH * DI * DS];
__device__ float g_h0   [2 * BB * CH * DI * DS];
__device__ float g_sumdt[2 * BB * CH * DI];

// bf16 hi/lo operand buffers (16B aligned for cp.async)
__device__ __align__(256) __nv_bfloat16 g_xnhi [2 * MM * CM];
__device__ __align__(256) __nv_bfloat16 g_xnlo [2 * MM * CM];
__device__ __align__(256) __nv_bfloat16 g_xbhi [2 * MM * DI];
__device__ __align__(256) __nv_bfloat16 g_xblo [2 * MM * DI];
__device__ __align__(256) __nv_bfloat16 g_x48hi[2 * MM * DR];
__device__ __align__(256) __nv_bfloat16 g_x48lo[2 * MM * DR];
__device__ __align__(256) __nv_bfloat16 g_yhi  [2 * MM * DI];
__device__ __align__(256) __nv_bfloat16 g_ylo  [2 * MM * DI];
__device__ __align__(256) __nv_bfloat16 g_oohi [MM * 2 * CM];
__device__ __align__(256) __nv_bfloat16 g_oolo [MM * 2 * CM];
__device__ __align__(256) __nv_bfloat16 g_cbhi [MM * CM];
__device__ __align__(256) __nv_bfloat16 g_cblo [MM * CM];
__device__ __align__(256) __nv_bfloat16 g_whi  [WTOTAL];
__device__ __align__(256) __nv_bfloat16 g_wlo  [WTOTAL];

__device__ __forceinline__ int map_row(int l, int dir) {
    if (dir == 0) return l;
    int t = l / NP, n = l - t * NP;
    return (TT - 1 - t) * NP + n;
}
__device__ __forceinline__ float sigmoidf_(float v) { return 1.0f / (1.0f + __expf(-v)); }
__device__ __forceinline__ float siluf_(float v)    { return v * sigmoidf_(v); }

__device__ __forceinline__ void split1(float v, __nv_bfloat16& h, __nv_bfloat16& l) {
    h = __float2bfloat16(v);
    l = __float2bfloat16(v - __bfloat162float(h));
}

__device__ __forceinline__ void mma_bf16(float c[4],
                                         uint32_t a0, uint32_t a1, uint32_t a2, uint32_t a3,
                                         uint32_t b0, uint32_t b1) {
    asm volatile(
        "mma.sync.aligned.m16n8k16.row.col.f32.bf16.bf16.f32 "
        "{%0,%1,%2,%3},{%4,%5,%6,%7},{%8,%9},{%0,%1,%2,%3};"
        : "+f"(c[0]), "+f"(c[1]), "+f"(c[2]), "+f"(c[3])
        : "r"(a0), "r"(a1), "r"(a2), "r"(a3), "r"(b0), "r"(b1));
}
__device__ __forceinline__ void ldsm_x4(uint32_t& r0, uint32_t& r1, uint32_t& r2,
                                        uint32_t& r3, uint32_t addr) {
    asm volatile("ldmatrix.sync.aligned.m8n8.x4.shared.b16 {%0,%1,%2,%3}, [%4];"
                 : "=r"(r0), "=r"(r1), "=r"(r2), "=r"(r3) : "r"(addr));
}
__device__ __forceinline__ void cp16(uint32_t dst, const void* src, int sz) {
    asm volatile("cp.async.cg.shared.global [%0], [%1], 16, %2;"
                 :: "r"(dst), "l"(src), "r"(sz) : "memory");
}
#define CP_COMMIT() asm volatile("cp.async.commit_group;" ::: "memory")

__device__ __forceinline__ int swz(int row, int chunk) {
    return row * 2 + (chunk ^ ((row >> 2) & 1));
}

// ---------------------------------------------------------------------------
__global__ void setup_A_kernel(const float* __restrict__ A_log) {
    int i = blockIdx.x * blockDim.x + threadIdx.x;
    if (i < 2 * DI * DS) g_A[i] = -expf(A_log[i]);
}

__global__ void check_arith_kernel() {
    __shared__ int bad;
    if (threadIdx.x == 0) bad = 0;
    __syncthreads();
    for (int row = threadIdx.x; row < 2 * DI; row += blockDim.x) {
        const float* a = &g_A[row * DS];
        float a0 = a[0], da = a[1] - a[0];
        for (int n = 2; n < DS; n++) {
            float expect = a0 + n * da;
            if (fabsf(a[n] - expect) > 1e-4f * (1.0f + fabsf(a[n]))) { bad = 1; break; }
        }
    }
    __syncthreads();
    if (threadIdx.x == 0) g_arith = bad ? 0 : 1;
}

// vectorized fp32 -> bf16 hi/lo split of a contiguous array (n % 4 == 0)
__global__ void split_f4(const float* __restrict__ src,
                         __nv_bfloat16* __restrict__ hi,
                         __nv_bfloat16* __restrict__ lo, long n4) {
    long i = (long)blockIdx.x * blockDim.x + threadIdx.x;
    if (i >= n4) return;
    float4 v = ((const float4*)src)[i];
    __nv_bfloat16 h0, h1, h2, h3, l0, l1, l2, l3;
    split1(v.x, h0, l0); split1(v.y, h1, l1);
    split1(v.z, h2, l2); split1(v.w, h3, l3);
    __nv_bfloat162 hv0 = __halves2bfloat162(h0, h1);
    __nv_bfloat162 hv1 = __halves2bfloat162(h2, h3);
    __nv_bfloat162 lv0 = __halves2bfloat162(l0, l1);
    __nv_bfloat162 lv1 = __halves2bfloat162(l2, l3);
    ((uint2*)hi)[i] = make_uint2(*(uint32_t*)&hv0, *(uint32_t*)&hv1);
    ((uint2*)lo)[i] = make_uint2(*(uint32_t*)&lv0, *(uint32_t*)&lv1);
}

// split first 48 cols of xdbl (stride 80) into x48 hi/lo (stride 48)
__global__ void split_x48() {
    long i = (long)blockIdx.x * blockDim.x + threadIdx.x;   // over 2*MM*48/4
    if (i >= 2L * MM * DR / 4) return;
    long row = i / (DR / 4);
    int  c4  = (int)(i - row * (DR / 4));
    float4 v = *(const float4*)&g_xdbl[row * 80 + c4 * 4];
    __nv_bfloat16 h0, h1, h2, h3, l0, l1, l2, l3;
    split1(v.x, h0, l0); split1(v.y, h1, l1);
    split1(v.z, h2, l2); split1(v.w, h3, l3);
    __nv_bfloat162 hv0 = __halves2bfloat162(h0, h1);
    __nv_bfloat162 hv1 = __halves2bfloat162(h2, h3);
    __nv_bfloat162 lv0 = __halves2bfloat162(l0, l1);
    __nv_bfloat162 lv1 = __halves2bfloat162(l2, l3);
    ((uint2*)g_x48hi)[i] = make_uint2(*(uint32_t*)&hv0, *(uint32_t*)&hv1);
    ((uint2*)g_x48lo)[i] = make_uint2(*(uint32_t*)&lv0, *(uint32_t*)&lv1);
}

// RMSNorm -> bf16 hi/lo
__global__ void rmsnorm_kernel(const float* __restrict__ x,
                               const float* __restrict__ norm_w) {
    int gid = blockIdx.x;
    int dir = gid / MM;
    int rem = gid - dir * MM;
    int b   = rem / LL, l = rem - b * LL;
    int lo_ = map_row(l, dir);
    const float* row = x + (size_t)(b * LL + lo_) * CM;

    float s = 0.f;
    for (int c = threadIdx.x; c < CM; c += blockDim.x) {
        float v = row[c];
        s += v * v;
    }
    __shared__ float warp_s[8];
    for (int off = 16; off > 0; off >>= 1) s += __shfl_down_sync(0xffffffffu, s, off);
    if ((threadIdx.x & 31) == 0) warp_s[threadIdx.x >> 5] = s;
    __syncthreads();
    if (threadIdx.x < 8) {
        float t = warp_s[threadIdx.x];
        for (int off = 4; off > 0; off >>= 1) t += __shfl_down_sync(0xffu, t, off);
        if (threadIdx.x == 0) warp_s[0] = t;
    }
    __syncthreads();
    float scale = rsqrtf(warp_s[0] / (float)CM + 1e-5f);

    const float* nw = norm_w + dir * CM;
    for (int c = threadIdx.x; c < CM; c += blockDim.x) {
        float v = row[c] * scale * nw[c];
        __nv_bfloat16 h, l2;
        split1(v, h, l2);
        g_xnhi[(size_t)gid * CM + c] = h;
        g_xnlo[(size_t)gid * CM + c] = l2;
    }
}

__global__ void init_oout_kernel(const float* __restrict__ x) {
    int idx = blockIdx.x * blockDim.x + threadIdx.x;
    if (idx >= MM * CM) return;
    int row = idx / CM, n = idx % CM;
    float v = x[idx];
    g_out[((size_t)row * 2 + 0) * CM + n] = v;
    g_out[((size_t)row * 2 + 1) * CM + n] = v;
}

__global__ void init_bias_kernel(float* __restrict__ C, const float* __restrict__ bias,
                                 int M, int N) {
    int idx = blockIdx.x * blockDim.x + threadIdx.x;
    if (idx >= M * N) return;
    C[idx] = bias[idx % N];
}

// gate combine -> comb bf16 hi/lo
__global__ void gate_combine_kernel(const float* __restrict__ gate_b) {
    int idx = blockIdx.x * blockDim.x + threadIdx.x;
    if (idx >= MM * CM) return;
    int m = idx / CM, n = idx % CM;
    float g = sigmoidf_(g_comb[idx] + gate_b[n]);
    float of = g_out[(size_t)m * (2 * CM) + n];
    float ob = g_out[(size_t)m * (2 * CM) + CM + n];
    float v = g * of + (1.f - g) * ob;
    __nv_bfloat16 h, l;
    split1(v, h, l);
    g_cbhi[idx] = h;
    g_cblo[idx] = l;
}

// ---------------------------------------------------------------------------
// cp.async 3-stage bf16 hi/lo MMA GEMM. BM=BN=128, BK in {16,32}.
// gridDim.z = dirs*KS. One __syncthreads per ktile.
// ---------------------------------------------------------------------------
#define EPI_STORE      0
#define EPI_SOFTPLUS   1
#define EPI_ATOM       2
#define EPI_ATOM_RESID 3

template <int BK, int EPI, int KS>
__global__ void __launch_bounds__(256, 2)
gemm_as(const __nv_bfloat16* __restrict__ Ahib, const __nv_bfloat16* __restrict__ Alob,
        int lda, size_t sA,
        const __nv_bfloat16* __restrict__ Whib, const __nv_bfloat16* __restrict__ Wlob,
        int ldw, size_t sW,
        float* __restrict__ Cb, int ldc, size_t sC,
        int M, int N, int K,
        const float* __restrict__ biasb, size_t sBias) {
    constexpr int KH = BK / 16;
    constexpr int ST = 3;
    constexpr uint32_t STAGE = 128 * 32 * KH;          // bytes per array per stage
    extern __shared__ char sm[];

    const int t    = threadIdx.x;
    const int lane = t & 31;
    const int w    = t >> 5;
    const int wm   = (w & 1) * 64;
    const int wn   = (w >> 1) * 32;
    const int g    = lane >> 2;
    const int tg   = lane & 3;

    const int m0    = blockIdx.y * 128;
    const int n0    = blockIdx.x * 128;
    const int z     = blockIdx.z;
    const int dir   = z / KS;
    const int split = z % KS;
    const int Kpart = K / KS;
    const int kbeg  = split * Kpart;

    const __nv_bfloat16* Ahi = Ahib + (size_t)dir * sA;
    const __nv_bfloat16* Alo = Alob + (size_t)dir * sA;
    const __nv_bfloat16* Whi = Whib + (size_t)dir * sW;
    const __nv_bfloat16* Wlo = Wlob + (size_t)dir * sW;
    float* C = Cb + (size_t)dir * sC;
    const float* bias = biasb ? biasb + (size_t)dir * sBias : nullptr;

    const uint32_t sbase = (uint32_t)__cvta_generic_to_shared(sm);
    const uint32_t bAh = sbase;
    const uint32_t bAl = sbase + ST * STAGE;
    const uint32_t bBh = sbase + 2 * ST * STAGE;
    const uint32_t bBl = sbase + 3 * ST * STAGE;

    // cp.async chunk map (per array): chunks/tile = 128*2*KH; per thread = KH
    int crow[KH], ckc[KH];
    uint32_t cdoff[KH];
#pragma unroll
    for (int i = 0; i < KH; i++) {
        int cid = t + i * 256;
        crow[i] = cid / (2 * KH);
        ckc[i]  = cid % (2 * KH);
        int h  = ckc[i] >> 1, ch = ckc[i] & 1;
        cdoff[i] = (uint32_t)(h * 4096 + swz(crow[i], ch) * 16);
    }

    auto issue = [&](int kt) {
        int s = kt % ST;
        int kglob = kbeg + kt * BK;
#pragma unroll
        for (int i = 0; i < KH; i++) {
            int row = crow[i];
            int h = ckc[i] >> 1, ch = ckc[i] & 1;
            int ke = kglob + h * 16 + ch * 8;
            uint32_t doff = (uint32_t)(s * STAGE) + cdoff[i];
            int gm = m0 + row;
            int gmc = (gm < M) ? gm : 0;
            int szA = (gm < M) ? 16 : 0;
            cp16(bAh + doff, Ahi + (size_t)gmc * lda + ke, szA);
            cp16(bAl + doff, Alo + (size_t)gmc * lda + ke, szA);
            int gn = n0 + row;
            int gnc = (gn < N) ? gn : 0;
            int szB = (gn < N) ? 16 : 0;
            cp16(bBh + doff, Whi + (size_t)gnc * ldw + ke, szB);
            cp16(bBl + doff, Wlo + (size_t)gnc * ldw + ke, szB);
        }
        CP_COMMIT();
    };

    // ldmatrix lane maps
    const int a_r = lane & 15;
    const int a_c = lane >> 4;
    const int b_r = (lane & 7) + ((lane & 16) ? 8 : 0);
    const int b_c = (lane >> 3) & 1;
    uint32_t offA[4];
#pragma unroll
    for (int i = 0; i < 4; i++)
        offA[i] = (uint32_t)(swz(wm + i * 16 + a_r, a_c) * 16);
    const uint32_t offB0 = (uint32_t)(swz(wn + b_r,      b_c) * 16);
    const uint32_t offB1 = (uint32_t)(swz(wn + 16 + b_r, b_c) * 16);

    float acc[4][4][4];
#pragma unroll
    for (int i = 0; i < 4; i++)
#pragma unroll
        for (int j = 0; j < 4; j++)
#pragma unroll
            for (int r = 0; r < 4; r++) acc[i][j][r] = 0.f;

    const int nk = Kpart / BK;
    issue(0);
    if (nk > 1) issue(1);

    for (int kt = 0; kt < nk; kt++) {
        if (kt == nk - 1)
            asm volatile("cp.async.wait_group 0;" ::: "memory");
        else
            asm volatile("cp.async.wait_group 1;" ::: "memory");
        __syncthreads();

        const uint32_t stg = (uint32_t)((kt % ST) * STAGE);
#pragma unroll
        for (int h = 0; h < KH; h++) {
            const uint32_t hb = stg + (uint32_t)(h * 4096);
            uint32_t ah[4][4], al[4][4], bh[8], bl[8];
            ldsm_x4(bh[0], bh[1], bh[2], bh[3], bBh + hb + offB0);
            ldsm_x4(bh[4], bh[5], bh[6], bh[7], bBh + hb + offB1);
            ldsm_x4(bl[0], bl[1], bl[2], bl[3], bBl + hb + offB0);
            ldsm_x4(bl[4], bl[5], bl[6], bl[7], bBl + hb + offB1);
#pragma unroll
            for (int i = 0; i < 4; i++) {
                ldsm_x4(ah[i][0], ah[i][1], ah[i][2], ah[i][3], bAh + hb + offA[i]);
                ldsm_x4(al[i][0], al[i][1], al[i][2], al[i][3], bAl + hb + offA[i]);
            }
#pragma unroll
            for (int j = 0; j < 4; j++) {
                uint32_t b0h = bh[j * 2], b1h = bh[j * 2 + 1];
                uint32_t b0l = bl[j * 2], b1l = bl[j * 2 + 1];
#pragma unroll
                for (int i = 0; i < 4; i++) {
                    mma_bf16(acc[i][j], ah[i][0], ah[i][1], ah[i][2], ah[i][3], b0h, b1h);
                    mma_bf16(acc[i][j], ah[i][0], ah[i][1], ah[i][2], ah[i][3], b0l, b1l);
                    mma_bf16(acc[i][j], al[i][0], al[i][1], al[i][2], al[i][3], b0h, b1h);
                }
            }
        }
        if (kt + 2 < nk) issue(kt + 2);
    }

    auto emit = [&](int m, int n, float v) {
        if (m >= M || n >= N) return;
        if (EPI == EPI_STORE) {
            C[(size_t)m * ldc + n] = v;
        } else if (EPI == EPI_SOFTPLUS) {
            v += bias[n];
            C[(size_t)m * ldc + n] = (v > 20.f) ? v : log1pf(__expf(v));
        } else if (EPI == EPI_ATOM) {
            atomicAdd(&C[(size_t)m * ldc + n], v);
        } else { // EPI_ATOM_RESID
            int b = m / LL, l = m - b * LL;
            int lo = map_row(l, dir);
            int row = b * LL + lo;
            atomicAdd(&g_out[((size_t)row * 2 + dir) * CM + n], v);
        }
    };

#pragma unroll
    for (int i = 0; i < 4; i++) {
        int mr = m0 + wm + i * 16 + g;
#pragma unroll
        for (int j = 0; j < 4; j++) {
            int nc = n0 + wn + j * 8 + 2 * tg;
            emit(mr,     nc,     acc[i][j][0]);
            emit(mr,     nc + 1, acc[i][j][1]);
            emit(mr + 8, nc,     acc[i][j][2]);
            emit(mr + 8, nc + 1, acc[i][j][3]);
        }
    }
}

// ---------------------------------------------------------------------------
// conv + silu -> xb fp32 and bf16 hi/lo
// ---------------------------------------------------------------------------
__global__ void conv_silu_kernel(const float* __restrict__ conv_w,
                                 const float* __restrict__ conv_b) {
    int idx = blockIdx.x * blockDim.x + threadIdx.x;
    if (idx >= 2 * MM * DI) return;
    int d = idx % DI;
    int r = idx / DI;
    int dir = r / MM;
    int l = r % LL;

    const float* w = conv_w + (size_t)(dir * DI + d) * DCONV;
    float acc = conv_b[dir * DI + d];
#pragma unroll
    for (int j = 0; j < DCONV; j++) {
        int ls = l - (DCONV - 1) + j;
        if (ls >= 0)
            acc = fmaf(w[j], g_xz[(size_t)(r - (DCONV - 1) + j) * (2 * DI) + d], acc);
    }
    float v = siluf_(acc);
    g_xb[(size_t)r * DI + d] = v;
    __nv_bfloat16 h, lo;
    split1(v, h, lo);
    g_xbhi[(size_t)r * DI + d] = h;
    g_xblo[(size_t)r * DI + d] = lo;
}

// ---------------------------------------------------------------------------
// chunked scan (CH=49)
// ---------------------------------------------------------------------------
__global__ void __launch_bounds__(128, 8)
scan_p1() {
    int d   = blockIdx.x * blockDim.x + threadIdx.x;
    int b   = blockIdx.y;
    int z   = blockIdx.z;
    int dir = z / CH;
    int c   = z % CH;

    const float* Arow = &g_A[(dir * DI + d) * DS];
    float a0 = Arow[0];
    float da = Arow[1] - Arow[0];
    float Ar[DS];
    bool arith = (g_arith != 0);
    if (!arith) {
#pragma unroll
        for (int n = 0; n < DS; n++) Ar[n] = Arow[n];
    }

    float h[DS];
#pragma unroll
    for (int n = 0; n < DS; n++) h[n] = 0.f;
    float sdt = 0.f;

    size_t r0 = (size_t)dir * MM + (size_t)b * LL + (size_t)c * CLEN;
    for (int l = 0; l < CLEN; l++) {
        size_t r = r0 + l;
        float u  = g_xb[r * DI + d];
        float dt = g_dt[r * DI + d];
        const float4* Bv = (const float4*)(&g_xdbl[r * 80 + DR]);
        float4 B0 = __ldg(&Bv[0]), B1 = __ldg(&Bv[1]);
        float4 B2 = __ldg(&Bv[2]), B3 = __ldg(&Bv[3]);
        float Bl[DS] = {B0.x, B0.y, B0.z, B0.w, B1.x, B1.y, B1.z, B1.w,
                        B2.x, B2.y, B2.z, B2.w, B3.x, B3.y, B3.z, B3.w};
        float du = dt * u;
        if (arith) {
            float p  = __expf(dt * a0);
            float rr = __expf(dt * da);
#pragma unroll
            for (int n = 0; n < DS; n++) {
                h[n] = fmaf(p, h[n], du * Bl[n]);
                p *= rr;
            }
        } else {
#pragma unroll
            for (int n = 0; n < DS; n++)
                h[n] = fmaf(__expf(dt * Ar[n]), h[n], du * Bl[n]);
        }
        sdt += dt;
    }

    size_t base = (((size_t)(dir * BB + b) * CH + c) * DI + d);
    g_sumdt[base] = sdt;
    float4* Sp = (float4*)&g_S[base * DS];
#pragma unroll
    for (int q = 0; q < 4; q++)
        Sp[q] = make_float4(h[q * 4], h[q * 4 + 1], h[q * 4 + 2], h[q * 4 + 3]);
}

__global__ void scan_p2() {
    int idx = blockIdx.x * blockDim.x + threadIdx.x;
    if (idx >= 2 * BB * DI) return;
    int d  = idx % DI;
    int bd = idx / DI;
    int dir = bd / BB;

    const float* Arow = &g_A[(dir * DI + d) * DS];
    float a0 = Arow[0];
    float da = Arow[1] - Arow[0];
    float Ar[DS];
    bool arith = (g_arith != 0);
    if (!arith) {
#pragma unroll
        for (int n = 0; n < DS; n++) Ar[n] = Arow[n];
    }

    float h[DS];
#pragma unroll
    for (int n = 0; n < DS; n++) h[n] = 0.f;

    for (int c = 0; c < CH; c++) {
        size_t base = (((size_t)bd * CH + c) * DI + d);
        float4* Hp = (float4*)&g_h0[base * DS];
#pragma unroll
        for (int q = 0; q < 4; q++)
            Hp[q] = make_float4(h[q * 4], h[q * 4 + 1], h[q * 4 + 2], h[q * 4 + 3]);

        float sdt = g_sumdt[base];
        const float4* Sp = (const float4*)&g_S[base * DS];
        float4 S0 = Sp[0], S1 = Sp[1], S2 = Sp[2], S3 = Sp[3];
        float Sl[DS] = {S0.x, S0.y, S0.z, S0.w, S1.x, S1.y, S1.z, S1.w,
                        S2.x, S2.y, S2.z, S2.w, S3.x, S3.y, S3.z, S3.w};
        if (arith) {
            float p  = __expf(sdt * a0);
            float rr = __expf(sdt * da);
#pragma unroll
            for (int n = 0; n < DS; n++) {
                h[n] = fmaf(p, h[n], Sl[n]);
                p *= rr;
            }
        } else {
#pragma unroll
            for (int n = 0; n < DS; n++)
                h[n] = fmaf(__expf(sdt * Ar[n]), h[n], Sl[n]);
        }
    }
}

__global__ void __launch_bounds__(128, 8)
scan_p3(const float* __restrict__ Dp) {
    int d   = blockIdx.x * blockDim.x + threadIdx.x;
    int b   = blockIdx.y;
    int z   = blockIdx.z;
    int dir = z / CH;
    int c   = z % CH;

    const float* Arow = &g_A[(dir * DI + d) * DS];
    float a0 = Arow[0];
    float da = Arow[1] - Arow[0];
    float Ar[DS];
    bool arith = (g_arith != 0);
    if (!arith) {
#pragma unroll
        for (int n = 0; n < DS; n++) Ar[n] = Arow[n];
    }

    size_t base = (((size_t)(dir * BB + b) * CH + c) * DI + d);
    float h[DS];
    {
        const float4* Hp = (const float4*)&g_h0[base * DS];
        float4 H0 = Hp[0], H1 = Hp[1], H2 = Hp[2], H3 = Hp[3];
        h[0] = H0.x;  h[1] = H0.y;  h[2] = H0.z;  h[3] = H0.w;
        h[4] = H1.x;  h[5] = H1.y;  h[6] = H1.z;  h[7] = H1.w;
        h[8] = H2.x;  h[9] = H2.y;  h[10] = H2.z; h[11] = H2.w;
        h[12] = H3.x; h[13] = H3.y; h[14] = H3.z; h[15] = H3.w;
    }

    float Dd = Dp[dir * DI + d];
    size_t r0 = (size_t)dir * MM + (size_t)b * LL + (size_t)c * CLEN;

    for (int l = 0; l < CLEN; l++) {
        size_t r = r0 + l;
        float u  = g_xb[r * DI + d];
        float dt = g_dt[r * DI + d];
        const float4* BC = (const float4*)(&g_xdbl[r * 80 + DR]);
        float4 Bv0 = __ldg(&BC[0]), Bv1 = __ldg(&BC[1]);
        float4 Bv2 = __ldg(&BC[2]), Bv3 = __ldg(&BC[3]);
        float4 Cv0 = __ldg(&BC[4]), Cv1 = __ldg(&BC[5]);
        float4 Cv2 = __ldg(&BC[6]), Cv3 = __ldg(&BC[7]);
        float Bl[DS] = {Bv0.x, Bv0.y, Bv0.z, Bv0.w, Bv1.x, Bv1.y, Bv1.z, Bv1.w,
                        Bv2.x, Bv2.y, Bv2.z, Bv2.w, Bv3.x, Bv3.y, Bv3.z, Bv3.w};
        float Cl[DS] = {Cv0.x, Cv0.y, Cv0.z, Cv0.w, Cv1.x, Cv1.y, Cv1.z, Cv1.w,
                        Cv2.x, Cv2.y, Cv2.z, Cv2.w, Cv3.x, Cv3.y, Cv3.z, Cv3.w};

        float du = dt * u;
        float yv = 0.f;
        if (arith) {
            float p  = __expf(dt * a0);
            float rr = __expf(dt * da);
#pragma unroll
            for (int n = 0; n < DS; n++) {
                h[n] = fmaf(p, h[n], du * Bl[n]);
                yv   = fmaf(h[n], Cl[n], yv);
                p *= rr;
            }
        } else {
#pragma unroll
            for (int n = 0; n < DS; n++) {
                float p = __expf(dt * Ar[n]);
                h[n] = fmaf(p, h[n], du * Bl[n]);
                yv   = fmaf(h[n], Cl[n], yv);
            }
        }
        yv = fmaf(u, Dd, yv);
        float zz = g_xz[r * (2 * DI) + DI + d];
        float val = yv * siluf_(zz);
        __nv_bfloat16 hh, ll;
        split1(val, hh, ll);
        g_yhi[r * DI + d] = hh;
        g_ylo[r * DI + d] = ll;
    }
}

// ---------------------------------------------------------------------------
extern "C" void kernel_launch(void* const* d_in, const int* in_sizes, int n_in,
                              void* d_out, int out_size) {
    const float* x         = (const float*)d_in[0];
    const float* norm_w    = (const float*)d_in[1];
    const float* in_proj_w = (const float*)d_in[2];
    const float* conv_w    = (const float*)d_in[3];
    const float* conv_b    = (const float*)d_in[4];
    const float* x_proj_w  = (const float*)d_in[5];
    const float* dt_proj_w = (const float*)d_in[6];
    const float* dt_proj_b = (const float*)d_in[7];
    const float* A_log     = (const float*)d_in[8];
    const float* Dp        = (const float*)d_in[9];
    const float* mix_out_w = (const float*)d_in[10];
    const float* gate_w    = (const float*)d_in[11];
    const float* gate_b    = (const float*)d_in[12];
    const float* proj_w    = (const float*)d_in[13];
    const float* proj_b    = (const float*)d_in[14];
    float* out = (float*)d_out;

    float *xz, *xb, *xdbl, *dt, *o_out, *comb;
    __nv_bfloat16 *xnhi, *xnlo, *xbhi, *xblo, *x48hi, *x48lo;
    __nv_bfloat16 *yhi, *ylo, *oohi, *oolo, *cbhi, *cblo, *whi, *wlo;
    cudaGetSymbolAddress((void**)&xz,    g_xz);
    cudaGetSymbolAddress((void**)&xb,    g_xb);
    cudaGetSymbolAddress((void**)&xdbl,  g_xdbl);
    cudaGetSymbolAddress((void**)&dt,    g_dt);
    cudaGetSymbolAddress((void**)&o_out, g_out);
    cudaGetSymbolAddress((void**)&comb,  g_comb);
    cudaGetSymbolAddress((void**)&xnhi,  g_xnhi);
    cudaGetSymbolAddress((void**)&xnlo,  g_xnlo);
    cudaGetSymbolAddress((void**)&xbhi,  g_xbhi);
    cudaGetSymbolAddress((void**)&xblo,  g_xblo);
    cudaGetSymbolAddress((void**)&x48hi, g_x48hi);
    cudaGetSymbolAddress((void**)&x48lo, g_x48lo);
    cudaGetSymbolAddress((void**)&yhi,   g_yhi);
    cudaGetSymbolAddress((void**)&ylo,   g_ylo);
    cudaGetSymbolAddress((void**)&oohi,  g_oohi);
    cudaGetSymbolAddress((void**)&oolo,  g_oolo);
    cudaGetSymbolAddress((void**)&cbhi,  g_cbhi);
    cudaGetSymbolAddress((void**)&cblo,  g_cblo);
    cudaGetSymbolAddress((void**)&whi,   g_whi);
    cudaGetSymbolAddress((void**)&wlo,   g_wlo);

    const int SMEM32 = 4 * 3 * 128 * 32 * 2;   // 98304
    const int SMEM16 = 4 * 3 * 128 * 32 * 1;   // 49152
    cudaFuncSetAttribute(gemm_as<32, EPI_STORE, 1>,      cudaFuncAttributeMaxDynamicSharedMemorySize, SMEM32);
    cudaFuncSetAttribute(gemm_as<32, EPI_ATOM, 8>,       cudaFuncAttributeMaxDynamicSharedMemorySize, SMEM32);
    cudaFuncSetAttribute(gemm_as<16, EPI_SOFTPLUS, 1>,   cudaFuncAttributeMaxDynamicSharedMemorySize, SMEM16);
    cudaFuncSetAttribute(gemm_as<32, EPI_ATOM_RESID, 2>, cudaFuncAttributeMaxDynamicSharedMemorySize, SMEM32);
    cudaFuncSetAttribute(gemm_as<32, EPI_ATOM, 4>,       cudaFuncAttributeMaxDynamicSharedMemorySize, SMEM32);

    setup_A_kernel<<<(2 * DI * DS + 255) / 256, 256>>>(A_log);
    check_arith_kernel<<<1, 256>>>();

    // weight splits (packed segments)
    auto sp = [&](const float* src, long off, long cnt) {
        split_f4<<<(unsigned)((cnt / 4 + 255) / 256), 256>>>(src, whi + off, wlo + off, cnt / 4);
    };
    sp(in_proj_w, WOFF_IN,   2L * 2 * DI * CM);
    sp(x_proj_w,  WOFF_XP,   2L * 80 * DI);
    sp(dt_proj_w, WOFF_DT,   2L * DI * DR);
    sp(mix_out_w, WOFF_OUT,  2L * CM * DI);
    sp(gate_w,    WOFF_GATE, (long)CM * 2 * CM);
    sp(proj_w,    WOFF_PROJ, (long)CM * CM);

    rmsnorm_kernel<<<2 * MM, 256>>>(x, norm_w);

    const int MY = (MM + 127) / 128;   // 13

    // in_proj: 624 CTAs
    gemm_as<32, EPI_STORE, 1><<<dim3(2 * DI / 128, MY, 2), 256, SMEM32>>>(
        xnhi, xnlo, CM, (size_t)MM * CM,
        whi + WOFF_IN, wlo + WOFF_IN, CM, (size_t)2 * DI * CM,
        xz, 2 * DI, (size_t)MM * 2 * DI,
        MM, 2 * DI, CM, nullptr, 0);

    conv_silu_kernel<<<(2 * MM * DI + 255) / 256, 256>>>(conv_w, conv_b);

    // x_proj: split-K=8, atomic into zeroed xdbl (208 CTAs)
    cudaMemsetAsync(xdbl, 0, sizeof(float) * 2 * MM * 80);
    gemm_as<32, EPI_ATOM, 8><<<dim3(1, MY, 2 * 8), 256, SMEM32>>>(
        xbhi, xblo, DI, (size_t)MM * DI,
        whi + WOFF_XP, wlo + WOFF_XP, DI, (size_t)80 * DI,
        xdbl, 80, (size_t)MM * 80,
        MM, 80, DI, nullptr, 0);

    split_x48<<<(unsigned)((2L * MM * DR / 4 + 255) / 256), 256>>>();

    // dt_proj + softplus (312 CTAs)
    gemm_as<16, EPI_SOFTPLUS, 1><<<dim3(DI / 128, MY, 2), 256, SMEM16>>>(
        x48hi, x48lo, DR, (size_t)MM * DR,
        whi + WOFF_DT, wlo + WOFF_DT, DR, (size_t)DI * DR,
        dt, DI, (size_t)MM * DI,
        MM, DI, DR, dt_proj_b, DI);

    // chunked scan
    scan_p1<<<dim3(DI / 128, BB, 2 * CH), 128>>>();
    scan_p2<<<(2 * BB * DI + 255) / 256, 256>>>();
    scan_p3<<<dim3(DI / 128, BB, 2 * CH), 128>>>(Dp);

    // out_proj: residual pre-init, atomic flip-scatter split-K=2 (312 CTAs)
    init_oout_kernel<<<(MM * CM + 255) / 256, 256>>>(x);
    gemm_as<32, EPI_ATOM_RESID, 2><<<dim3(CM / 128, MY, 2 * 2), 256, SMEM32>>>(
        yhi, ylo, DI, (size_t)MM * DI,
        whi + WOFF_OUT, wlo + WOFF_OUT, DI, (size_t)CM * DI,
        o_out, 0, 0,
        MM, CM, DI, nullptr, 0);

    // split o_out for gate's A
    split_f4<<<(unsigned)(((long)MM * 2 * CM / 4 + 255) / 256), 256>>>(
        o_out, oohi, oolo, (long)MM * 2 * CM / 4);

    // gate raw accum: split-K=4 (312 CTAs)
    cudaMemsetAsync(comb, 0, sizeof(float) * MM * CM);
    gemm_as<32, EPI_ATOM, 4><<<dim3(CM / 128, MY, 4), 256, SMEM32>>>(
        oohi, oolo, 2 * CM, 0,
        whi + WOFF_GATE, wlo + WOFF_GATE, 2 * CM, 0,
        comb, CM, 0,
        MM, CM, 2 * CM, nullptr, 0);

    gate_combine_kernel<<<(MM * CM + 255) / 256, 256>>>(gate_b);

    // final: bias pre-init, atomic split-K=4 (312 CTAs)
    init_bias_kernel<<<(MM * CM + 255) / 256, 256>>>(out, proj_b, MM, CM);
    gemm_as<32, EPI_ATOM, 4><<<dim3(CM / 128, MY, 4), 256, SMEM32>>>(
        cbhi, cblo, CM, 0,
        whi + WOFF_PROJ, wlo + WOFF_PROJ, CM, 0,
        out, CM, 0,
        MM, CM, CM, nullptr, 0);

    (void)in_sizes; (void)n_in; (void)out_size;
}

// round 15
// speedup vs baseline: 2.5178x; 1.0168x over previous
#include <cuda_runtime.h>
#include <cuda_bf16.h>
#include <cstdint>

// ---------------------------------------------------------------------------
// BiMamba refiner block, round 14: R13 GEMMs + fused weight split (1 launch),
// non-atomic out_proj partials + single combine pass (kills init/atomic/split).
// ---------------------------------------------------------------------------

#define BB      2
#define TT      4
#define NP      196
#define LL      784
#define MM      1568
#define CM      768
#define DI      1536
#define DS      16
#define DR      48
#define DCONV   4
#define CH      49
#define CLEN    16

#define WOFF_IN   0L
#define WOFF_XP   4718592L
#define WOFF_DT   4964352L
#define WOFF_OUT  5111808L
#define WOFF_GATE 7471104L
#define WOFF_PROJ 8650752L
#define WTOTAL    9240576L

// ---------------- scratch ---------------------------------------------------
__device__ float g_xz  [2 * MM * 2 * DI];   // in_proj out; later out_proj partials
__device__ float g_xb  [2 * MM * DI];
__device__ float g_xdbl[2 * MM * 80];
__device__ float g_dt  [2 * MM * DI];
__device__ float g_out [MM * 2 * CM];
__device__ float g_comb[MM * CM];
__device__ float g_A   [2 * DI * DS];
__device__ int   g_arith;
__device__ float g_S    [2 * BB * CH * DI * DS];
__device__ float g_h0   [2 * BB * CH * DI * DS];
__device__ float g_sumdt[2 * BB * CH * DI];

__device__ __align__(256) __nv_bfloat16 g_xnhi [2 * MM * CM];
__device__ __align__(256) __nv_bfloat16 g_xnlo [2 * MM * CM];
__device__ __align__(256) __nv_bfloat16 g_xbhi [2 * MM * DI];
__device__ __align__(256) __nv_bfloat16 g_xblo [2 * MM * DI];
__device__ __align__(256) __nv_bfloat16 g_x48hi[2 * MM * DR];
__device__ __align__(256) __nv_bfloat16 g_x48lo[2 * MM * DR];
__device__ __align__(256) __nv_bfloat16 g_yhi  [2 * MM * DI];
__device__ __align__(256) __nv_bfloat16 g_ylo  [2 * MM * DI];
__device__ __align__(256) __nv_bfloat16 g_oohi [MM * 2 * CM];
__device__ __align__(256) __nv_bfloat16 g_oolo [MM * 2 * CM];
__device__ __align__(256) __nv_bfloat16 g_cbhi [MM * CM];
__device__ __align__(256) __nv_bfloat16 g_cblo [MM * CM];
__device__ __align__(256) __nv_bfloat16 g_whi  [WTOTAL];
__device__ __align__(256) __nv_bfloat16 g_wlo  [WTOTAL];

__device__ __forceinline__ int map_row(int l, int dir) {
    if (dir == 0) return l;
    int t = l / NP, n = l - t * NP;
    return (TT - 1 - t) * NP + n;
}
__device__ __forceinline__ float sigmoidf_(float v) { return 1.0f / (1.0f + __expf(-v)); }
__device__ __forceinline__ float siluf_(float v)    { return v * sigmoidf_(v); }

__device__ __forceinline__ void split1(float v, __nv_bfloat16& h, __nv_bfloat16& l) {
    h = __float2bfloat16(v);
    l = __float2bfloat16(v - __bfloat162float(h));
}

__device__ __forceinline__ void mma_bf16(float c[4],
                                         uint32_t a0, uint32_t a1, uint32_t a2, uint32_t a3,
                                         uint32_t b0, uint32_t b1) {
    asm volatile(
        "mma.sync.aligned.m16n8k16.row.col.f32.bf16.bf16.f32 "
        "{%0,%1,%2,%3},{%4,%5,%6,%7},{%8,%9},{%0,%1,%2,%3};"
        : "+f"(c[0]), "+f"(c[1]), "+f"(c[2]), "+f"(c[3])
        : "r"(a0), "r"(a1), "r"(a2), "r"(a3), "r"(b0), "r"(b1));
}
__device__ __forceinline__ void ldsm_x4(uint32_t& r0, uint32_t& r1, uint32_t& r2,
                                        uint32_t& r3, uint32_t addr) {
    asm volatile("ldmatrix.sync.aligned.m8n8.x4.shared.b16 {%0,%1,%2,%3}, [%4];"
                 : "=r"(r0), "=r"(r1), "=r"(r2), "=r"(r3) : "r"(addr));
}
__device__ __forceinline__ void cp16(uint32_t dst, const void* src, int sz) {
    asm volatile("cp.async.cg.shared.global [%0], [%1], 16, %2;"
                 :: "r"(dst), "l"(src), "r"(sz) : "memory");
}
#define CP_COMMIT() asm volatile("cp.async.commit_group;" ::: "memory")

__device__ __forceinline__ int swz(int row, int chunk) {
    return row * 2 + (chunk ^ ((row >> 2) & 1));
}

// ---------------------------------------------------------------------------
__global__ void setup_A_kernel(const float* __restrict__ A_log) {
    int i = blockIdx.x * blockDim.x + threadIdx.x;
    if (i < 2 * DI * DS) g_A[i] = -expf(A_log[i]);
}

__global__ void check_arith_kernel() {
    __shared__ int bad;
    if (threadIdx.x == 0) bad = 0;
    __syncthreads();
    for (int row = threadIdx.x; row < 2 * DI; row += blockDim.x) {
        const float* a = &g_A[row * DS];
        float a0 = a[0], da = a[1] - a[0];
        for (int n = 2; n < DS; n++) {
            float expect = a0 + n * da;
            if (fabsf(a[n] - expect) > 1e-4f * (1.0f + fabsf(a[n]))) { bad = 1; break; }
        }
    }
    __syncthreads();
    if (threadIdx.x == 0) g_arith = bad ? 0 : 1;
}

// fused weight split: one launch over all packed segments
__global__ void split_weights_kernel(const float* __restrict__ w_in,
                                     const float* __restrict__ w_xp,
                                     const float* __restrict__ w_dt,
                                     const float* __restrict__ w_out,
                                     const float* __restrict__ w_gate,
                                     const float* __restrict__ w_proj) {
    long i4 = (long)blockIdx.x * blockDim.x + threadIdx.x;
    if (i4 >= WTOTAL / 4) return;
    long e = i4 * 4;
    const float* src;
    long loc;
    if (e < WOFF_XP)        { src = w_in;   loc = e - WOFF_IN; }
    else if (e < WOFF_DT)   { src = w_xp;   loc = e - WOFF_XP; }
    else if (e < WOFF_OUT)  { src = w_dt;   loc = e - WOFF_DT; }
    else if (e < WOFF_GATE) { src = w_out;  loc = e - WOFF_OUT; }
    else if (e < WOFF_PROJ) { src = w_gate; loc = e - WOFF_GATE; }
    else                    { src = w_proj; loc = e - WOFF_PROJ; }
    float4 v = *(const float4*)(src + loc);
    __nv_bfloat16 h0, h1, h2, h3, l0, l1, l2, l3;
    split1(v.x, h0, l0); split1(v.y, h1, l1);
    split1(v.z, h2, l2); split1(v.w, h3, l3);
    __nv_bfloat162 hv0 = __halves2bfloat162(h0, h1);
    __nv_bfloat162 hv1 = __halves2bfloat162(h2, h3);
    __nv_bfloat162 lv0 = __halves2bfloat162(l0, l1);
    __nv_bfloat162 lv1 = __halves2bfloat162(l2, l3);
    ((uint2*)g_whi)[i4] = make_uint2(*(uint32_t*)&hv0, *(uint32_t*)&hv1);
    ((uint2*)g_wlo)[i4] = make_uint2(*(uint32_t*)&lv0, *(uint32_t*)&lv1);
}

// split first 48 cols of xdbl (stride 80) into x48 hi/lo (stride 48)
__global__ void split_x48() {
    long i = (long)blockIdx.x * blockDim.x + threadIdx.x;
    if (i >= 2L * MM * DR / 4) return;
    long row = i / (DR / 4);
    int  c4  = (int)(i - row * (DR / 4));
    float4 v = *(const float4*)&g_xdbl[row * 80 + c4 * 4];
    __nv_bfloat16 h0, h1, h2, h3, l0, l1, l2, l3;
    split1(v.x, h0, l0); split1(v.y, h1, l1);
    split1(v.z, h2, l2); split1(v.w, h3, l3);
    __nv_bfloat162 hv0 = __halves2bfloat162(h0, h1);
    __nv_bfloat162 hv1 = __halves2bfloat162(h2, h3);
    __nv_bfloat162 lv0 = __halves2bfloat162(l0, l1);
    __nv_bfloat162 lv1 = __halves2bfloat162(l2, l3);
    ((uint2*)g_x48hi)[i] = make_uint2(*(uint32_t*)&hv0, *(uint32_t*)&hv1);
    ((uint2*)g_x48lo)[i] = make_uint2(*(uint32_t*)&lv0, *(uint32_t*)&lv1);
}

__global__ void rmsnorm_kernel(const float* __restrict__ x,
                               const float* __restrict__ norm_w) {
    int gid = blockIdx.x;
    int dir = gid / MM;
    int rem = gid - dir * MM;
    int b   = rem / LL, l = rem - b * LL;
    int lo_ = map_row(l, dir);
    const float* row = x + (size_t)(b * LL + lo_) * CM;

    float s = 0.f;
    for (int c = threadIdx.x; c < CM; c += blockDim.x) {
        float v = row[c];
        s += v * v;
    }
    __shared__ float warp_s[8];
    for (int off = 16; off > 0; off >>= 1) s += __shfl_down_sync(0xffffffffu, s, off);
    if ((threadIdx.x & 31) == 0) warp_s[threadIdx.x >> 5] = s;
    __syncthreads();
    if (threadIdx.x < 8) {
        float t = warp_s[threadIdx.x];
        for (int off = 4; off > 0; off >>= 1) t += __shfl_down_sync(0xffu, t, off);
        if (threadIdx.x == 0) warp_s[0] = t;
    }
    __syncthreads();
    float scale = rsqrtf(warp_s[0] / (float)CM + 1e-5f);

    const float* nw = norm_w + dir * CM;
    for (int c = threadIdx.x; c < CM; c += blockDim.x) {
        float v = row[c] * scale * nw[c];
        __nv_bfloat16 h, l2;
        split1(v, h, l2);
        g_xnhi[(size_t)gid * CM + c] = h;
        g_xnlo[(size_t)gid * CM + c] = l2;
    }
}

// out_proj combine: o_out = x + P0 + P1 (flip scatter), emit fp32 + bf16 hi/lo
__global__ void oout_combine_kernel(const float* __restrict__ x) {
    int idx = blockIdx.x * blockDim.x + threadIdx.x;
    if (idx >= 2 * MM * CM) return;
    int dir = idx / (MM * CM);
    int rem = idx - dir * (MM * CM);
    int m = rem / CM, n = rem - (rem / CM) * CM;
    int b = m / LL, l = m - b * LL;
    int lo_ = map_row(l, dir);
    int row = b * LL + lo_;
    const float* P = g_xz + (size_t)dir * 2 * MM * CM;
    float val = x[(size_t)row * CM + n] + P[rem] + P[(size_t)MM * CM + rem];
    size_t o = ((size_t)row * 2 + dir) * CM + n;
    g_out[o] = val;
    __nv_bfloat16 h, lo2;
    split1(val, h, lo2);
    g_oohi[o] = h;
    g_oolo[o] = lo2;
}

__global__ void init_bias_kernel(float* __restrict__ C, const float* __restrict__ bias,
                                 int M, int N) {
    int idx = blockIdx.x * blockDim.x + threadIdx.x;
    if (idx >= M * N) return;
    C[idx] = bias[idx % N];
}

__global__ void gate_combine_kernel(const float* __restrict__ gate_b) {
    int idx = blockIdx.x * blockDim.x + threadIdx.x;
    if (idx >= MM * CM) return;
    int m = idx / CM, n = idx % CM;
    float g = sigmoidf_(g_comb[idx] + gate_b[n]);
    float of = g_out[(size_t)m * (2 * CM) + n];
    float ob = g_out[(size_t)m * (2 * CM) + CM + n];
    float v = g * of + (1.f - g) * ob;
    __nv_bfloat16 h, l;
    split1(v, h, l);
    g_cbhi[idx] = h;
    g_cblo[idx] = l;
}

// ---------------------------------------------------------------------------
// cp.async 3-stage bf16 hi/lo MMA GEMM. BM=BN=128, BK in {16,32}.
// gridDim.z = dirs*KS. EPI_STORE with KS>1 writes per-split partial buffers.
// ---------------------------------------------------------------------------
#define EPI_STORE      0
#define EPI_SOFTPLUS   1
#define EPI_ATOM       2

template <int BK, int EPI, int KS>
__global__ void __launch_bounds__(256, 2)
gemm_as(const __nv_bfloat16* __restrict__ Ahib, const __nv_bfloat16* __restrict__ Alob,
        int lda, size_t sA,
        const __nv_bfloat16* __restrict__ Whib, const __nv_bfloat16* __restrict__ Wlob,
        int ldw, size_t sW,
        float* __restrict__ Cb, int ldc, size_t sC,
        int M, int N, int K,
        const float* __restrict__ biasb, size_t sBias) {
    constexpr int KH = BK / 16;
    constexpr int ST = 3;
    constexpr uint32_t STAGE = 128 * 32 * KH;
    extern __shared__ char sm[];

    const int t    = threadIdx.x;
    const int lane = t & 31;
    const int w    = t >> 5;
    const int wm   = (w & 1) * 64;
    const int wn   = (w >> 1) * 32;
    const int g    = lane >> 2;
    const int tg   = lane & 3;

    const int m0    = blockIdx.y * 128;
    const int n0    = blockIdx.x * 128;
    const int z     = blockIdx.z;
    const int dir   = z / KS;
    const int split = z % KS;
    const int Kpart = K / KS;
    const int kbeg  = split * Kpart;

    const __nv_bfloat16* Ahi = Ahib + (size_t)dir * sA;
    const __nv_bfloat16* Alo = Alob + (size_t)dir * sA;
    const __nv_bfloat16* Whi = Whib + (size_t)dir * sW;
    const __nv_bfloat16* Wlo = Wlob + (size_t)dir * sW;
    float* C = Cb + (size_t)dir * sC;
    if (EPI == EPI_STORE && KS > 1) C += (size_t)split * (size_t)M * ldc;
    const float* bias = biasb ? biasb + (size_t)dir * sBias : nullptr;

    const uint32_t sbase = (uint32_t)__cvta_generic_to_shared(sm);
    const uint32_t bAh = sbase;
    const uint32_t bAl = sbase + ST * STAGE;
    const uint32_t bBh = sbase + 2 * ST * STAGE;
    const uint32_t bBl = sbase + 3 * ST * STAGE;

    int crow[KH], ckc[KH];
    uint32_t cdoff[KH];
#pragma unroll
    for (int i = 0; i < KH; i++) {
        int cid = t + i * 256;
        crow[i] = cid / (2 * KH);
        ckc[i]  = cid % (2 * KH);
        int h  = ckc[i] >> 1, ch = ckc[i] & 1;
        cdoff[i] = (uint32_t)(h * 4096 + swz(crow[i], ch) * 16);
    }

    auto issue = [&](int kt) {
        int s = kt % ST;
        int kglob = kbeg + kt * BK;
#pragma unroll
        for (int i = 0; i < KH; i++) {
            int row = crow[i];
            int h = ckc[i] >> 1, ch = ckc[i] & 1;
            int ke = kglob + h * 16 + ch * 8;
            uint32_t doff = (uint32_t)(s * STAGE) + cdoff[i];
            int gm = m0 + row;
            int gmc = (gm < M) ? gm : 0;
            int szA = (gm < M) ? 16 : 0;
            cp16(bAh + doff, Ahi + (size_t)gmc * lda + ke, szA);
            cp16(bAl + doff, Alo + (size_t)gmc * lda + ke, szA);
            int gn = n0 + row;
            int gnc = (gn < N) ? gn : 0;
            int szB = (gn < N) ? 16 : 0;
            cp16(bBh + doff, Whi + (size_t)gnc * ldw + ke, szB);
            cp16(bBl + doff, Wlo + (size_t)gnc * ldw + ke, szB);
        }
        CP_COMMIT();
    };

    const int a_r = lane & 15;
    const int a_c = lane >> 4;
    const int b_r = (lane & 7) + ((lane & 16) ? 8 : 0);
    const int b_c = (lane >> 3) & 1;
    uint32_t offA[4];
#pragma unroll
    for (int i = 0; i < 4; i++)
        offA[i] = (uint32_t)(swz(wm + i * 16 + a_r, a_c) * 16);
    const uint32_t offB0 = (uint32_t)(swz(wn + b_r,      b_c) * 16);
    const uint32_t offB1 = (uint32_t)(swz(wn + 16 + b_r, b_c) * 16);

    float acc[4][4][4];
#pragma unroll
    for (int i = 0; i < 4; i++)
#pragma unroll
        for (int j = 0; j < 4; j++)
#pragma unroll
            for (int r = 0; r < 4; r++) acc[i][j][r] = 0.f;

    const int nk = Kpart / BK;
    issue(0);
    if (nk > 1) issue(1);

    for (int kt = 0; kt < nk; kt++) {
        if (kt == nk - 1)
            asm volatile("cp.async.wait_group 0;" ::: "memory");
        else
            asm volatile("cp.async.wait_group 1;" ::: "memory");
        __syncthreads();

        const uint32_t stg = (uint32_t)((kt % ST) * STAGE);
#pragma unroll
        for (int h = 0; h < KH; h++) {
            const uint32_t hb = stg + (uint32_t)(h * 4096);
            uint32_t ah[4][4], al[4][4], bh[8], bl[8];
            ldsm_x4(bh[0], bh[1], bh[2], bh[3], bBh + hb + offB0);
            ldsm_x4(bh[4], bh[5], bh[6], bh[7], bBh + hb + offB1);
            ldsm_x4(bl[0], bl[1], bl[2], bl[3], bBl + hb + offB0);
            ldsm_x4(bl[4], bl[5], bl[6], bl[7], bBl + hb + offB1);
#pragma unroll
            for (int i = 0; i < 4; i++) {
                ldsm_x4(ah[i][0], ah[i][1], ah[i][2], ah[i][3], bAh + hb + offA[i]);
                ldsm_x4(al[i][0], al[i][1], al[i][2], al[i][3], bAl + hb + offA[i]);
            }
#pragma unroll
            for (int j = 0; j < 4; j++) {
                uint32_t b0h = bh[j * 2], b1h = bh[j * 2 + 1];
                uint32_t b0l = bl[j * 2], b1l = bl[j * 2 + 1];
#pragma unroll
                for (int i = 0; i < 4; i++) {
                    mma_bf16(acc[i][j], ah[i][0], ah[i][1], ah[i][2], ah[i][3], b0h, b1h);
                    mma_bf16(acc[i][j], ah[i][0], ah[i][1], ah[i][2], ah[i][3], b0l, b1l);
                    mma_bf16(acc[i][j], al[i][0], al[i][1], al[i][2], al[i][3], b0h, b1h);
                }
            }
        }
        if (kt + 2 < nk) issue(kt + 2);
    }

    auto emit = [&](int m, int n, float v) {
        if (m >= M || n >= N) return;
        if (EPI == EPI_STORE) {
            C[(size_t)m * ldc + n] = v;
        } else if (EPI == EPI_SOFTPLUS) {
            v += bias[n];
            C[(size_t)m * ldc + n] = (v > 20.f) ? v : log1pf(__expf(v));
        } else { // EPI_ATOM
            atomicAdd(&C[(size_t)m * ldc + n], v);
        }
    };

#pragma unroll
    for (int i = 0; i < 4; i++) {
        int mr = m0 + wm + i * 16 + g;
#pragma unroll
        for (int j = 0; j < 4; j++) {
            int nc = n0 + wn + j * 8 + 2 * tg;
            emit(mr,     nc,     acc[i][j][0]);
            emit(mr,     nc + 1, acc[i][j][1]);
            emit(mr + 8, nc,     acc[i][j][2]);
            emit(mr + 8, nc + 1, acc[i][j][3]);
        }
    }
}

// ---------------------------------------------------------------------------
__global__ void conv_silu_kernel(const float* __restrict__ conv_w,
                                 const float* __restrict__ conv_b) {
    int idx = blockIdx.x * blockDim.x + threadIdx.x;
    if (idx >= 2 * MM * DI) return;
    int d = idx % DI;
    int r = idx / DI;
    int dir = r / MM;
    int l = r % LL;

    const float* w = conv_w + (size_t)(dir * DI + d) * DCONV;
    float acc = conv_b[dir * DI + d];
#pragma unroll
    for (int j = 0; j < DCONV; j++) {
        int ls = l - (DCONV - 1) + j;
        if (ls >= 0)
            acc = fmaf(w[j], g_xz[(size_t)(r - (DCONV - 1) + j) * (2 * DI) + d], acc);
    }
    float v = siluf_(acc);
    g_xb[(size_t)r * DI + d] = v;
    __nv_bfloat16 h, lo;
    split1(v, h, lo);
    g_xbhi[(size_t)r * DI + d] = h;
    g_xblo[(size_t)r * DI + d] = lo;
}

// ---------------------------------------------------------------------------
// chunked scan (CH=49)
// ---------------------------------------------------------------------------
__global__ void __launch_bounds__(128, 8)
scan_p1() {
    int d   = blockIdx.x * blockDim.x + threadIdx.x;
    int b   = blockIdx.y;
    int z   = blockIdx.z;
    int dir = z / CH;
    int c   = z % CH;

    const float* Arow = &g_A[(dir * DI + d) * DS];
    float a0 = Arow[0];
    float da = Arow[1] - Arow[0];
    float Ar[DS];
    bool arith = (g_arith != 0);
    if (!arith) {
#pragma unroll
        for (int n = 0; n < DS; n++) Ar[n] = Arow[n];
    }

    float h[DS];
#pragma unroll
    for (int n = 0; n < DS; n++) h[n] = 0.f;
    float sdt = 0.f;

    size_t r0 = (size_t)dir * MM + (size_t)b * LL + (size_t)c * CLEN;
    for (int l = 0; l < CLEN; l++) {
        size_t r = r0 + l;
        float u  = g_xb[r * DI + d];
        float dt = g_dt[r * DI + d];
        const float4* Bv = (const float4*)(&g_xdbl[r * 80 + DR]);
        float4 B0 = __ldg(&Bv[0]), B1 = __ldg(&Bv[1]);
        float4 B2 = __ldg(&Bv[2]), B3 = __ldg(&Bv[3]);
        float Bl[DS] = {B0.x, B0.y, B0.z, B0.w, B1.x, B1.y, B1.z, B1.w,
                        B2.x, B2.y, B2.z, B2.w, B3.x, B3.y, B3.z, B3.w};
        float du = dt * u;
        if (arith) {
            float p  = __expf(dt * a0);
            float rr = __expf(dt * da);
#pragma unroll
            for (int n = 0; n < DS; n++) {
                h[n] = fmaf(p, h[n], du * Bl[n]);
                p *= rr;
            }
        } else {
#pragma unroll
            for (int n = 0; n < DS; n++)
                h[n] = fmaf(__expf(dt * Ar[n]), h[n], du * Bl[n]);
        }
        sdt += dt;
    }

    size_t base = (((size_t)(dir * BB + b) * CH + c) * DI + d);
    g_sumdt[base] = sdt;
    float4* Sp = (float4*)&g_S[base * DS];
#pragma unroll
    for (int q = 0; q < 4; q++)
        Sp[q] = make_float4(h[q * 4], h[q * 4 + 1], h[q * 4 + 2], h[q * 4 + 3]);
}

__global__ void scan_p2() {
    int idx = blockIdx.x * blockDim.x + threadIdx.x;
    if (idx >= 2 * BB * DI) return;
    int d  = idx % DI;
    int bd = idx / DI;
    int dir = bd / BB;

    const float* Arow = &g_A[(dir * DI + d) * DS];
    float a0 = Arow[0];
    float da = Arow[1] - Arow[0];
    float Ar[DS];
    bool arith = (g_arith != 0);
    if (!arith) {
#pragma unroll
        for (int n = 0; n < DS; n++) Ar[n] = Arow[n];
    }

    float h[DS];
#pragma unroll
    for (int n = 0; n < DS; n++) h[n] = 0.f;

    for (int c = 0; c < CH; c++) {
        size_t base = (((size_t)bd * CH + c) * DI + d);
        float4* Hp = (float4*)&g_h0[base * DS];
#pragma unroll
        for (int q = 0; q < 4; q++)
            Hp[q] = make_float4(h[q * 4], h[q * 4 + 1], h[q * 4 + 2], h[q * 4 + 3]);

        float sdt = g_sumdt[base];
        const float4* Sp = (const float4*)&g_S[base * DS];
        float4 S0 = Sp[0], S1 = Sp[1], S2 = Sp[2], S3 = Sp[3];
        float Sl[DS] = {S0.x, S0.y, S0.z, S0.w, S1.x, S1.y, S1.z, S1.w,
                        S2.x, S2.y, S2.z, S2.w, S3.x, S3.y, S3.z, S3.w};
        if (arith) {
            float p  = __expf(sdt * a0);
            float rr = __expf(sdt * da);
#pragma unroll
            for (int n = 0; n < DS; n++) {
                h[n] = fmaf(p, h[n], Sl[n]);
                p *= rr;
            }
        } else {
#pragma unroll
            for (int n = 0; n < DS; n++)
                h[n] = fmaf(__expf(sdt * Ar[n]), h[n], Sl[n]);
        }
    }
}

__global__ void __launch_bounds__(128, 8)
scan_p3(const float* __restrict__ Dp) {
    int d   = blockIdx.x * blockDim.x + threadIdx.x;
    int b   = blockIdx.y;
    int z   = blockIdx.z;
    int dir = z / CH;
    int c   = z % CH;

    const float* Arow = &g_A[(dir * DI + d) * DS];
    float a0 = Arow[0];
    float da = Arow[1] - Arow[0];
    float Ar[DS];
    bool arith = (g_arith != 0);
    if (!arith) {
#pragma unroll
        for (int n = 0; n < DS; n++) Ar[n] = Arow[n];
    }

    size_t base = (((size_t)(dir * BB + b) * CH + c) * DI + d);
    float h[DS];
    {
        const float4* Hp = (const float4*)&g_h0[base * DS];
        float4 H0 = Hp[0], H1 = Hp[1], H2 = Hp[2], H3 = Hp[3];
        h[0] = H0.x;  h[1] = H0.y;  h[2] = H0.z;  h[3] = H0.w;
        h[4] = H1.x;  h[5] = H1.y;  h[6] = H1.z;  h[7] = H1.w;
        h[8] = H2.x;  h[9] = H2.y;  h[10] = H2.z; h[11] = H2.w;
        h[12] = H3.x; h[13] = H3.y; h[14] = H3.z; h[15] = H3.w;
    }

    float Dd = Dp[dir * DI + d];
    size_t r0 = (size_t)dir * MM + (size_t)b * LL + (size_t)c * CLEN;

    for (int l = 0; l < CLEN; l++) {
        size_t r = r0 + l;
        float u  = g_xb[r * DI + d];
        float dt = g_dt[r * DI + d];
        const float4* BC = (const float4*)(&g_xdbl[r * 80 + DR]);
        float4 Bv0 = __ldg(&BC[0]), Bv1 = __ldg(&BC[1]);
        float4 Bv2 = __ldg(&BC[2]), Bv3 = __ldg(&BC[3]);
        float4 Cv0 = __ldg(&BC[4]), Cv1 = __ldg(&BC[5]);
        float4 Cv2 = __ldg(&BC[6]), Cv3 = __ldg(&BC[7]);
        float Bl[DS] = {Bv0.x, Bv0.y, Bv0.z, Bv0.w, Bv1.x, Bv1.y, Bv1.z, Bv1.w,
                        Bv2.x, Bv2.y, Bv2.z, Bv2.w, Bv3.x, Bv3.y, Bv3.z, Bv3.w};
        float Cl[DS] = {Cv0.x, Cv0.y, Cv0.z, Cv0.w, Cv1.x, Cv1.y, Cv1.z, Cv1.w,
                        Cv2.x, Cv2.y, Cv2.z, Cv2.w, Cv3.x, Cv3.y, Cv3.z, Cv3.w};

        float du = dt * u;
        float yv = 0.f;
        if (arith) {
            float p  = __expf(dt * a0);
            float rr = __expf(dt * da);
#pragma unroll
            for (int n = 0; n < DS; n++) {
                h[n] = fmaf(p, h[n], du * Bl[n]);
                yv   = fmaf(h[n], Cl[n], yv);
                p *= rr;
            }
        } else {
#pragma unroll
            for (int n = 0; n < DS; n++) {
                float p = __expf(dt * Ar[n]);
                h[n] = fmaf(p, h[n], du * Bl[n]);
                yv   = fmaf(h[n], Cl[n], yv);
            }
        }
        yv = fmaf(u, Dd, yv);
        float zz = g_xz[r * (2 * DI) + DI + d];
        float val = yv * siluf_(zz);
        __nv_bfloat16 hh, ll;
        split1(val, hh, ll);
        g_yhi[r * DI + d] = hh;
        g_ylo[r * DI + d] = ll;
    }
}

// ---------------------------------------------------------------------------
extern "C" void kernel_launch(void* const* d_in, const int* in_sizes, int n_in,
                              void* d_out, int out_size) {
    const float* x         = (const float*)d_in[0];
    const float* norm_w    = (const float*)d_in[1];
    const float* in_proj_w = (const float*)d_in[2];
    const float* conv_w    = (const float*)d_in[3];
    const float* conv_b    = (const float*)d_in[4];
    const float* x_proj_w  = (const float*)d_in[5];
    const float* dt_proj_w = (const float*)d_in[6];
    const float* dt_proj_b = (const float*)d_in[7];
    const float* A_log     = (const float*)d_in[8];
    const float* Dp        = (const float*)d_in[9];
    const float* mix_out_w = (const float*)d_in[10];
    const float* gate_w    = (const float*)d_in[11];
    const float* gate_b    = (const float*)d_in[12];
    const float* proj_w    = (const float*)d_in[13];
    const float* proj_b    = (const float*)d_in[14];
    float* out = (float*)d_out;

    float *xz, *xdbl, *dt, *comb;
    __nv_bfloat16 *xnhi, *xnlo, *xbhi, *xblo, *x48hi, *x48lo;
    __nv_bfloat16 *yhi, *ylo, *oohi, *oolo, *cbhi, *cblo, *whi, *wlo;
    cudaGetSymbolAddress((void**)&xz,    g_xz);
    cudaGetSymbolAddress((void**)&xdbl,  g_xdbl);
    cudaGetSymbolAddress((void**)&dt,    g_dt);
    cudaGetSymbolAddress((void**)&comb,  g_comb);
    cudaGetSymbolAddress((void**)&xnhi,  g_xnhi);
    cudaGetSymbolAddress((void**)&xnlo,  g_xnlo);
    cudaGetSymbolAddress((void**)&xbhi,  g_xbhi);
    cudaGetSymbolAddress((void**)&xblo,  g_xblo);
    cudaGetSymbolAddress((void**)&x48hi, g_x48hi);
    cudaGetSymbolAddress((void**)&x48lo, g_x48lo);
    cudaGetSymbolAddress((void**)&yhi,   g_yhi);
    cudaGetSymbolAddress((void**)&ylo,   g_ylo);
    cudaGetSymbolAddress((void**)&oohi,  g_oohi);
    cudaGetSymbolAddress((void**)&oolo,  g_oolo);
    cudaGetSymbolAddress((void**)&cbhi,  g_cbhi);
    cudaGetSymbolAddress((void**)&cblo,  g_cblo);
    cudaGetSymbolAddress((void**)&whi,   g_whi);
    cudaGetSymbolAddress((void**)&wlo,   g_wlo);

    const int SMEM32 = 4 * 3 * 128 * 32 * 2;   // 98304
    const int SMEM16 = 4 * 3 * 128 * 32 * 1;   // 49152
    cudaFuncSetAttribute(gemm_as<32, EPI_STORE, 1>,    cudaFuncAttributeMaxDynamicSharedMemorySize, SMEM32);
    cudaFuncSetAttribute(gemm_as<32, EPI_ATOM, 8>,     cudaFuncAttributeMaxDynamicSharedMemorySize, SMEM32);
    cudaFuncSetAttribute(gemm_as<16, EPI_SOFTPLUS, 1>, cudaFuncAttributeMaxDynamicSharedMemorySize, SMEM16);
    cudaFuncSetAttribute(gemm_as<32, EPI_STORE, 2>,    cudaFuncAttributeMaxDynamicSharedMemorySize, SMEM32);
    cudaFuncSetAttribute(gemm_as<32, EPI_ATOM, 4>,     cudaFuncAttributeMaxDynamicSharedMemorySize, SMEM32);

    setup_A_kernel<<<(2 * DI * DS + 255) / 256, 256>>>(A_log);
    check_arith_kernel<<<1, 256>>>();

    // all weight splits in one launch
    split_weights_kernel<<<(unsigned)((WTOTAL / 4 + 255) / 256), 256>>>(
        in_proj_w, x_proj_w, dt_proj_w, mix_out_w, gate_w, proj_w);

    rmsnorm_kernel<<<2 * MM, 256>>>(x, norm_w);

    const int MY = (MM + 127) / 128;   // 13

    // in_proj: 624 CTAs
    gemm_as<32, EPI_STORE, 1><<<dim3(2 * DI / 128, MY, 2), 256, SMEM32>>>(
        xnhi, xnlo, CM, (size_t)MM * CM,
        whi + WOFF_IN, wlo + WOFF_IN, CM, (size_t)2 * DI * CM,
        xz, 2 * DI, (size_t)MM * 2 * DI,
        MM, 2 * DI, CM, nullptr, 0);

    conv_silu_kernel<<<(2 * MM * DI + 255) / 256, 256>>>(conv_w, conv_b);

    // x_proj: split-K=8, atomic into zeroed xdbl (208 CTAs)
    cudaMemsetAsync(xdbl, 0, sizeof(float) * 2 * MM * 80);
    gemm_as<32, EPI_ATOM, 8><<<dim3(1, MY, 2 * 8), 256, SMEM32>>>(
        xbhi, xblo, DI, (size_t)MM * DI,
        whi + WOFF_XP, wlo + WOFF_XP, DI, (size_t)80 * DI,
        xdbl, 80, (size_t)MM * 80,
        MM, 80, DI, nullptr, 0);

    split_x48<<<(unsigned)((2L * MM * DR / 4 + 255) / 256), 256>>>();

    // dt_proj + softplus (312 CTAs)
    gemm_as<16, EPI_SOFTPLUS, 1><<<dim3(DI / 128, MY, 2), 256, SMEM16>>>(
        x48hi, x48lo, DR, (size_t)MM * DR,
        whi + WOFF_DT, wlo + WOFF_DT, DR, (size_t)DI * DR,
        dt, DI, (size_t)MM * DI,
        MM, DI, DR, dt_proj_b, DI);

    // chunked scan
    scan_p1<<<dim3(DI / 128, BB, 2 * CH), 128>>>();
    scan_p2<<<(2 * BB * DI + 255) / 256, 256>>>();
    scan_p3<<<dim3(DI / 128, BB, 2 * CH), 128>>>(Dp);

    // out_proj: KS=2 partial stores into xz (reused), then single combine
    gemm_as<32, EPI_STORE, 2><<<dim3(CM / 128, MY, 2 * 2), 256, SMEM32>>>(
        yhi, ylo, DI, (size_t)MM * DI,
        whi + WOFF_OUT, wlo + WOFF_OUT, DI, (size_t)CM * DI,
        xz, CM, (size_t)2 * MM * CM,
        MM, CM, DI, nullptr, 0);
    oout_combine_kernel<<<(2 * MM * CM + 255) / 256, 256>>>(x);

    // gate raw accum: split-K=4 (312 CTAs)
    cudaMemsetAsync(comb, 0, sizeof(float) * MM * CM);
    gemm_as<32, EPI_ATOM, 4><<<dim3(CM / 128, MY, 4), 256, SMEM32>>>(
        oohi, oolo, 2 * CM, 0,
        whi + WOFF_GATE, wlo + WOFF_GATE, 2 * CM, 0,
        comb, CM, 0,
        MM, CM, 2 * CM, nullptr, 0);

    gate_combine_kernel<<<(MM * CM + 255) / 256, 256>>>(gate_b);

    // final: bias pre-init, atomic split-K=4 (312 CTAs)
    init_bias_kernel<<<(MM * CM + 255) / 256, 256>>>(out, proj_b, MM, CM);
    gemm_as<32, EPI_ATOM, 4><<<dim3(CM / 128, MY, 4), 256, SMEM32>>>(
        cbhi, cblo, CM, 0,
        whi + WOFF_PROJ, wlo + WOFF_PROJ, CM, 0,
        out, CM, 0,
        MM, CM, CM, nullptr, 0);

    (void)in_sizes; (void)n_in; (void)out_size;
}

// round 16
// speedup vs baseline: 2.5657x; 1.0190x over previous
#include <cuda_runtime.h>
#include <cuda_bf16.h>
#include <cstdint>

// ---------------------------------------------------------------------------
// BiMamba refiner block, round 15: R14 + gate GEMM via partial stores (no
// atomics/memset), bias-init folded into gate_combine, parallel check_arith.
// ---------------------------------------------------------------------------

#define BB      2
#define TT      4
#define NP      196
#define LL      784
#define MM      1568
#define CM      768
#define DI      1536
#define DS      16
#define DR      48
#define DCONV   4
#define CH      49
#define CLEN    16

#define WOFF_IN   0L
#define WOFF_XP   4718592L
#define WOFF_DT   4964352L
#define WOFF_OUT  5111808L
#define WOFF_GATE 7471104L
#define WOFF_PROJ 8650752L
#define WTOTAL    9240576L

// ---------------- scratch ---------------------------------------------------
__device__ float g_xz  [2 * MM * 2 * DI];   // in_proj out; later partial buffers
__device__ float g_xb  [2 * MM * DI];
__device__ float g_xdbl[2 * MM * 80];
__device__ float g_dt  [2 * MM * DI];
__device__ float g_out [MM * 2 * CM];
__device__ float g_A   [2 * DI * DS];
__device__ int   g_arith;
__device__ float g_S    [2 * BB * CH * DI * DS];
__device__ float g_h0   [2 * BB * CH * DI * DS];
__device__ float g_sumdt[2 * BB * CH * DI];

__device__ __align__(256) __nv_bfloat16 g_xnhi [2 * MM * CM];
__device__ __align__(256) __nv_bfloat16 g_xnlo [2 * MM * CM];
__device__ __align__(256) __nv_bfloat16 g_xbhi [2 * MM * DI];
__device__ __align__(256) __nv_bfloat16 g_xblo [2 * MM * DI];
__device__ __align__(256) __nv_bfloat16 g_x48hi[2 * MM * DR];
__device__ __align__(256) __nv_bfloat16 g_x48lo[2 * MM * DR];
__device__ __align__(256) __nv_bfloat16 g_yhi  [2 * MM * DI];
__device__ __align__(256) __nv_bfloat16 g_ylo  [2 * MM * DI];
__device__ __align__(256) __nv_bfloat16 g_oohi [MM * 2 * CM];
__device__ __align__(256) __nv_bfloat16 g_oolo [MM * 2 * CM];
__device__ __align__(256) __nv_bfloat16 g_cbhi [MM * CM];
__device__ __align__(256) __nv_bfloat16 g_cblo [MM * CM];
__device__ __align__(256) __nv_bfloat16 g_whi  [WTOTAL];
__device__ __align__(256) __nv_bfloat16 g_wlo  [WTOTAL];

__device__ __forceinline__ int map_row(int l, int dir) {
    if (dir == 0) return l;
    int t = l / NP, n = l - t * NP;
    return (TT - 1 - t) * NP + n;
}
__device__ __forceinline__ float sigmoidf_(float v) { return 1.0f / (1.0f + __expf(-v)); }
__device__ __forceinline__ float siluf_(float v)    { return v * sigmoidf_(v); }

__device__ __forceinline__ void split1(float v, __nv_bfloat16& h, __nv_bfloat16& l) {
    h = __float2bfloat16(v);
    l = __float2bfloat16(v - __bfloat162float(h));
}

__device__ __forceinline__ void mma_bf16(float c[4],
                                         uint32_t a0, uint32_t a1, uint32_t a2, uint32_t a3,
                                         uint32_t b0, uint32_t b1) {
    asm volatile(
        "mma.sync.aligned.m16n8k16.row.col.f32.bf16.bf16.f32 "
        "{%0,%1,%2,%3},{%4,%5,%6,%7},{%8,%9},{%0,%1,%2,%3};"
        : "+f"(c[0]), "+f"(c[1]), "+f"(c[2]), "+f"(c[3])
        : "r"(a0), "r"(a1), "r"(a2), "r"(a3), "r"(b0), "r"(b1));
}
__device__ __forceinline__ void ldsm_x4(uint32_t& r0, uint32_t& r1, uint32_t& r2,
                                        uint32_t& r3, uint32_t addr) {
    asm volatile("ldmatrix.sync.aligned.m8n8.x4.shared.b16 {%0,%1,%2,%3}, [%4];"
                 : "=r"(r0), "=r"(r1), "=r"(r2), "=r"(r3) : "r"(addr));
}
__device__ __forceinline__ void cp16(uint32_t dst, const void* src, int sz) {
    asm volatile("cp.async.cg.shared.global [%0], [%1], 16, %2;"
                 :: "r"(dst), "l"(src), "r"(sz) : "memory");
}
#define CP_COMMIT() asm volatile("cp.async.commit_group;" ::: "memory")

__device__ __forceinline__ int swz(int row, int chunk) {
    return row * 2 + (chunk ^ ((row >> 2) & 1));
}

// ---------------------------------------------------------------------------
__global__ void setup_A_kernel(const float* __restrict__ A_log) {
    int i = blockIdx.x * blockDim.x + threadIdx.x;
    if (i == 0) g_arith = 1;
    if (i < 2 * DI * DS) g_A[i] = -expf(A_log[i]);
}

__global__ void check_arith_kernel() {
    int row = blockIdx.x * blockDim.x + threadIdx.x;
    if (row >= 2 * DI) return;
    const float* a = &g_A[row * DS];
    float a0 = a[0], da = a[1] - a[0];
    for (int n = 2; n < DS; n++) {
        float expect = a0 + n * da;
        if (fabsf(a[n] - expect) > 1e-4f * (1.0f + fabsf(a[n]))) {
            g_arith = 0;
            return;
        }
    }
}

// fused weight split: one launch over all packed segments
__global__ void split_weights_kernel(const float* __restrict__ w_in,
                                     const float* __restrict__ w_xp,
                                     const float* __restrict__ w_dt,
                                     const float* __restrict__ w_out,
                                     const float* __restrict__ w_gate,
                                     const float* __restrict__ w_proj) {
    long i4 = (long)blockIdx.x * blockDim.x + threadIdx.x;
    if (i4 >= WTOTAL / 4) return;
    long e = i4 * 4;
    const float* src;
    long loc;
    if (e < WOFF_XP)        { src = w_in;   loc = e - WOFF_IN; }
    else if (e < WOFF_DT)   { src = w_xp;   loc = e - WOFF_XP; }
    else if (e < WOFF_OUT)  { src = w_dt;   loc = e - WOFF_DT; }
    else if (e < WOFF_GATE) { src = w_out;  loc = e - WOFF_OUT; }
    else if (e < WOFF_PROJ) { src = w_gate; loc = e - WOFF_GATE; }
    else                    { src = w_proj; loc = e - WOFF_PROJ; }
    float4 v = *(const float4*)(src + loc);
    __nv_bfloat16 h0, h1, h2, h3, l0, l1, l2, l3;
    split1(v.x, h0, l0); split1(v.y, h1, l1);
    split1(v.z, h2, l2); split1(v.w, h3, l3);
    __nv_bfloat162 hv0 = __halves2bfloat162(h0, h1);
    __nv_bfloat162 hv1 = __halves2bfloat162(h2, h3);
    __nv_bfloat162 lv0 = __halves2bfloat162(l0, l1);
    __nv_bfloat162 lv1 = __halves2bfloat162(l2, l3);
    ((uint2*)g_whi)[i4] = make_uint2(*(uint32_t*)&hv0, *(uint32_t*)&hv1);
    ((uint2*)g_wlo)[i4] = make_uint2(*(uint32_t*)&lv0, *(uint32_t*)&lv1);
}

// split first 48 cols of xdbl (stride 80) into x48 hi/lo (stride 48)
__global__ void split_x48() {
    long i = (long)blockIdx.x * blockDim.x + threadIdx.x;
    if (i >= 2L * MM * DR / 4) return;
    long row = i / (DR / 4);
    int  c4  = (int)(i - row * (DR / 4));
    float4 v = *(const float4*)&g_xdbl[row * 80 + c4 * 4];
    __nv_bfloat16 h0, h1, h2, h3, l0, l1, l2, l3;
    split1(v.x, h0, l0); split1(v.y, h1, l1);
    split1(v.z, h2, l2); split1(v.w, h3, l3);
    __nv_bfloat162 hv0 = __halves2bfloat162(h0, h1);
    __nv_bfloat162 hv1 = __halves2bfloat162(h2, h3);
    __nv_bfloat162 lv0 = __halves2bfloat162(l0, l1);
    __nv_bfloat162 lv1 = __halves2bfloat162(l2, l3);
    ((uint2*)g_x48hi)[i] = make_uint2(*(uint32_t*)&hv0, *(uint32_t*)&hv1);
    ((uint2*)g_x48lo)[i] = make_uint2(*(uint32_t*)&lv0, *(uint32_t*)&lv1);
}

__global__ void rmsnorm_kernel(const float* __restrict__ x,
                               const float* __restrict__ norm_w) {
    int gid = blockIdx.x;
    int dir = gid / MM;
    int rem = gid - dir * MM;
    int b   = rem / LL, l = rem - b * LL;
    int lo_ = map_row(l, dir);
    const float* row = x + (size_t)(b * LL + lo_) * CM;

    float s = 0.f;
    for (int c = threadIdx.x; c < CM; c += blockDim.x) {
        float v = row[c];
        s += v * v;
    }
    __shared__ float warp_s[8];
    for (int off = 16; off > 0; off >>= 1) s += __shfl_down_sync(0xffffffffu, s, off);
    if ((threadIdx.x & 31) == 0) warp_s[threadIdx.x >> 5] = s;
    __syncthreads();
    if (threadIdx.x < 8) {
        float t = warp_s[threadIdx.x];
        for (int off = 4; off > 0; off >>= 1) t += __shfl_down_sync(0xffu, t, off);
        if (threadIdx.x == 0) warp_s[0] = t;
    }
    __syncthreads();
    float scale = rsqrtf(warp_s[0] / (float)CM + 1e-5f);

    const float* nw = norm_w + dir * CM;
    for (int c = threadIdx.x; c < CM; c += blockDim.x) {
        float v = row[c] * scale * nw[c];
        __nv_bfloat16 h, l2;
        split1(v, h, l2);
        g_xnhi[(size_t)gid * CM + c] = h;
        g_xnlo[(size_t)gid * CM + c] = l2;
    }
}

// out_proj combine: o_out = x + P0 + P1 (flip scatter), emit fp32 + bf16 hi/lo
__global__ void oout_combine_kernel(const float* __restrict__ x) {
    int idx = blockIdx.x * blockDim.x + threadIdx.x;
    if (idx >= 2 * MM * CM) return;
    int dir = idx / (MM * CM);
    int rem = idx - dir * (MM * CM);
    int m = rem / CM, n = rem - (rem / CM) * CM;
    int b = m / LL, l = m - b * LL;
    int lo_ = map_row(l, dir);
    int row = b * LL + lo_;
    const float* P = g_xz + (size_t)dir * 2 * MM * CM;
    float val = x[(size_t)row * CM + n] + P[rem] + P[(size_t)MM * CM + rem];
    size_t o = ((size_t)row * 2 + dir) * CM + n;
    g_out[o] = val;
    __nv_bfloat16 h, lo2;
    split1(val, h, lo2);
    g_oohi[o] = h;
    g_oolo[o] = lo2;
}

// gate combine: sum 4 gate partials (in g_xz), sigmoid-combine, emit cb hi/lo;
// also pre-initializes final output with proj_b.
__global__ void gate_combine_kernel(const float* __restrict__ gate_b,
                                    const float* __restrict__ proj_b,
                                    float* __restrict__ out) {
    int idx = blockIdx.x * blockDim.x + threadIdx.x;
    if (idx >= MM * CM) return;
    int m = idx / CM, n = idx % CM;
    float raw = g_xz[idx] + g_xz[(size_t)MM * CM + idx]
              + g_xz[2 * (size_t)MM * CM + idx] + g_xz[3 * (size_t)MM * CM + idx];
    float g = sigmoidf_(raw + gate_b[n]);
    float of = g_out[(size_t)m * (2 * CM) + n];
    float ob = g_out[(size_t)m * (2 * CM) + CM + n];
    float v = g * of + (1.f - g) * ob;
    __nv_bfloat16 h, l;
    split1(v, h, l);
    g_cbhi[idx] = h;
    g_cblo[idx] = l;
    out[idx] = proj_b[n];
}

// ---------------------------------------------------------------------------
// cp.async 3-stage bf16 hi/lo MMA GEMM. BM=BN=128, BK in {16,32}.
// gridDim.z = dirs*KS. EPI_STORE with KS>1 writes per-split partial buffers.
// ---------------------------------------------------------------------------
#define EPI_STORE      0
#define EPI_SOFTPLUS   1
#define EPI_ATOM       2

template <int BK, int EPI, int KS>
__global__ void __launch_bounds__(256, 2)
gemm_as(const __nv_bfloat16* __restrict__ Ahib, const __nv_bfloat16* __restrict__ Alob,
        int lda, size_t sA,
        const __nv_bfloat16* __restrict__ Whib, const __nv_bfloat16* __restrict__ Wlob,
        int ldw, size_t sW,
        float* __restrict__ Cb, int ldc, size_t sC,
        int M, int N, int K,
        const float* __restrict__ biasb, size_t sBias) {
    constexpr int KH = BK / 16;
    constexpr int ST = 3;
    constexpr uint32_t STAGE = 128 * 32 * KH;
    extern __shared__ char sm[];

    const int t    = threadIdx.x;
    const int lane = t & 31;
    const int w    = t >> 5;
    const int wm   = (w & 1) * 64;
    const int wn   = (w >> 1) * 32;
    const int g    = lane >> 2;
    const int tg   = lane & 3;

    const int m0    = blockIdx.y * 128;
    const int n0    = blockIdx.x * 128;
    const int z     = blockIdx.z;
    const int dir   = z / KS;
    const int split = z % KS;
    const int Kpart = K / KS;
    const int kbeg  = split * Kpart;

    const __nv_bfloat16* Ahi = Ahib + (size_t)dir * sA;
    const __nv_bfloat16* Alo = Alob + (size_t)dir * sA;
    const __nv_bfloat16* Whi = Whib + (size_t)dir * sW;
    const __nv_bfloat16* Wlo = Wlob + (size_t)dir * sW;
    float* C = Cb + (size_t)dir * sC;
    if (EPI == EPI_STORE && KS > 1) C += (size_t)split * (size_t)M * ldc;
    const float* bias = biasb ? biasb + (size_t)dir * sBias : nullptr;

    const uint32_t sbase = (uint32_t)__cvta_generic_to_shared(sm);
    const uint32_t bAh = sbase;
    const uint32_t bAl = sbase + ST * STAGE;
    const uint32_t bBh = sbase + 2 * ST * STAGE;
    const uint32_t bBl = sbase + 3 * ST * STAGE;

    int crow[KH], ckc[KH];
    uint32_t cdoff[KH];
#pragma unroll
    for (int i = 0; i < KH; i++) {
        int cid = t + i * 256;
        crow[i] = cid / (2 * KH);
        ckc[i]  = cid % (2 * KH);
        int h  = ckc[i] >> 1, ch = ckc[i] & 1;
        cdoff[i] = (uint32_t)(h * 4096 + swz(crow[i], ch) * 16);
    }

    auto issue = [&](int kt) {
        int s = kt % ST;
        int kglob = kbeg + kt * BK;
#pragma unroll
        for (int i = 0; i < KH; i++) {
            int row = crow[i];
            int h = ckc[i] >> 1, ch = ckc[i] & 1;
            int ke = kglob + h * 16 + ch * 8;
            uint32_t doff = (uint32_t)(s * STAGE) + cdoff[i];
            int gm = m0 + row;
            int gmc = (gm < M) ? gm : 0;
            int szA = (gm < M) ? 16 : 0;
            cp16(bAh + doff, Ahi + (size_t)gmc * lda + ke, szA);
            cp16(bAl + doff, Alo + (size_t)gmc * lda + ke, szA);
            int gn = n0 + row;
            int gnc = (gn < N) ? gn : 0;
            int szB = (gn < N) ? 16 : 0;
            cp16(bBh + doff, Whi + (size_t)gnc * ldw + ke, szB);
            cp16(bBl + doff, Wlo + (size_t)gnc * ldw + ke, szB);
        }
        CP_COMMIT();
    };

    const int a_r = lane & 15;
    const int a_c = lane >> 4;
    const int b_r = (lane & 7) + ((lane & 16) ? 8 : 0);
    const int b_c = (lane >> 3) & 1;
    uint32_t offA[4];
#pragma unroll
    for (int i = 0; i < 4; i++)
        offA[i] = (uint32_t)(swz(wm + i * 16 + a_r, a_c) * 16);
    const uint32_t offB0 = (uint32_t)(swz(wn + b_r,      b_c) * 16);
    const uint32_t offB1 = (uint32_t)(swz(wn + 16 + b_r, b_c) * 16);

    float acc[4][4][4];
#pragma unroll
    for (int i = 0; i < 4; i++)
#pragma unroll
        for (int j = 0; j < 4; j++)
#pragma unroll
            for (int r = 0; r < 4; r++) acc[i][j][r] = 0.f;

    const int nk = Kpart / BK;
    issue(0);
    if (nk > 1) issue(1);

    for (int kt = 0; kt < nk; kt++) {
        if (kt == nk - 1)
            asm volatile("cp.async.wait_group 0;" ::: "memory");
        else
            asm volatile("cp.async.wait_group 1;" ::: "memory");
        __syncthreads();

        const uint32_t stg = (uint32_t)((kt % ST) * STAGE);
#pragma unroll
        for (int h = 0; h < KH; h++) {
            const uint32_t hb = stg + (uint32_t)(h * 4096);
            uint32_t ah[4][4], al[4][4], bh[8], bl[8];
            ldsm_x4(bh[0], bh[1], bh[2], bh[3], bBh + hb + offB0);
            ldsm_x4(bh[4], bh[5], bh[6], bh[7], bBh + hb + offB1);
            ldsm_x4(bl[0], bl[1], bl[2], bl[3], bBl + hb + offB0);
            ldsm_x4(bl[4], bl[5], bl[6], bl[7], bBl + hb + offB1);
#pragma unroll
            for (int i = 0; i < 4; i++) {
                ldsm_x4(ah[i][0], ah[i][1], ah[i][2], ah[i][3], bAh + hb + offA[i]);
                ldsm_x4(al[i][0], al[i][1], al[i][2], al[i][3], bAl + hb + offA[i]);
            }
#pragma unroll
            for (int j = 0; j < 4; j++) {
                uint32_t b0h = bh[j * 2], b1h = bh[j * 2 + 1];
                uint32_t b0l = bl[j * 2], b1l = bl[j * 2 + 1];
#pragma unroll
                for (int i = 0; i < 4; i++) {
                    mma_bf16(acc[i][j], ah[i][0], ah[i][1], ah[i][2], ah[i][3], b0h, b1h);
                    mma_bf16(acc[i][j], ah[i][0], ah[i][1], ah[i][2], ah[i][3], b0l, b1l);
                    mma_bf16(acc[i][j], al[i][0], al[i][1], al[i][2], al[i][3], b0h, b1h);
                }
            }
        }
        if (kt + 2 < nk) issue(kt + 2);
    }

    auto emit = [&](int m, int n, float v) {
        if (m >= M || n >= N) return;
        if (EPI == EPI_STORE) {
            C[(size_t)m * ldc + n] = v;
        } else if (EPI == EPI_SOFTPLUS) {
            v += bias[n];
            C[(size_t)m * ldc + n] = (v > 20.f) ? v : log1pf(__expf(v));
        } else { // EPI_ATOM
            atomicAdd(&C[(size_t)m * ldc + n], v);
        }
    };

#pragma unroll
    for (int i = 0; i < 4; i++) {
        int mr = m0 + wm + i * 16 + g;
#pragma unroll
        for (int j = 0; j < 4; j++) {
            int nc = n0 + wn + j * 8 + 2 * tg;
            emit(mr,     nc,     acc[i][j][0]);
            emit(mr,     nc + 1, acc[i][j][1]);
            emit(mr + 8, nc,     acc[i][j][2]);
            emit(mr + 8, nc + 1, acc[i][j][3]);
        }
    }
}

// ---------------------------------------------------------------------------
__global__ void conv_silu_kernel(const float* __restrict__ conv_w,
                                 const float* __restrict__ conv_b) {
    int idx = blockIdx.x * blockDim.x + threadIdx.x;
    if (idx >= 2 * MM * DI) return;
    int d = idx % DI;
    int r = idx / DI;
    int dir = r / MM;
    int l = r % LL;

    const float* w = conv_w + (size_t)(dir * DI + d) * DCONV;
    float acc = conv_b[dir * DI + d];
#pragma unroll
    for (int j = 0; j < DCONV; j++) {
        int ls = l - (DCONV - 1) + j;
        if (ls >= 0)
            acc = fmaf(w[j], g_xz[(size_t)(r - (DCONV - 1) + j) * (2 * DI) + d], acc);
    }
    float v = siluf_(acc);
    g_xb[(size_t)r * DI + d] = v;
    __nv_bfloat16 h, lo;
    split1(v, h, lo);
    g_xbhi[(size_t)r * DI + d] = h;
    g_xblo[(size_t)r * DI + d] = lo;
}

// ---------------------------------------------------------------------------
// chunked scan (CH=49)
// ---------------------------------------------------------------------------
__global__ void __launch_bounds__(128, 8)
scan_p1() {
    int d   = blockIdx.x * blockDim.x + threadIdx.x;
    int b   = blockIdx.y;
    int z   = blockIdx.z;
    int dir = z / CH;
    int c   = z % CH;

    const float* Arow = &g_A[(dir * DI + d) * DS];
    float a0 = Arow[0];
    float da = Arow[1] - Arow[0];
    float Ar[DS];
    bool arith = (g_arith != 0);
    if (!arith) {
#pragma unroll
        for (int n = 0; n < DS; n++) Ar[n] = Arow[n];
    }

    float h[DS];
#pragma unroll
    for (int n = 0; n < DS; n++) h[n] = 0.f;
    float sdt = 0.f;

    size_t r0 = (size_t)dir * MM + (size_t)b * LL + (size_t)c * CLEN;
    for (int l = 0; l < CLEN; l++) {
        size_t r = r0 + l;
        float u  = g_xb[r * DI + d];
        float dt = g_dt[r * DI + d];
        const float4* Bv = (const float4*)(&g_xdbl[r * 80 + DR]);
        float4 B0 = __ldg(&Bv[0]), B1 = __ldg(&Bv[1]);
        float4 B2 = __ldg(&Bv[2]), B3 = __ldg(&Bv[3]);
        float Bl[DS] = {B0.x, B0.y, B0.z, B0.w, B1.x, B1.y, B1.z, B1.w,
                        B2.x, B2.y, B2.z, B2.w, B3.x, B3.y, B3.z, B3.w};
        float du = dt * u;
        if (arith) {
            float p  = __expf(dt * a0);
            float rr = __expf(dt * da);
#pragma unroll
            for (int n = 0; n < DS; n++) {
                h[n] = fmaf(p, h[n], du * Bl[n]);
                p *= rr;
            }
        } else {
#pragma unroll
            for (int n = 0; n < DS; n++)
                h[n] = fmaf(__expf(dt * Ar[n]), h[n], du * Bl[n]);
        }
        sdt += dt;
    }

    size_t base = (((size_t)(dir * BB + b) * CH + c) * DI + d);
    g_sumdt[base] = sdt;
    float4* Sp = (float4*)&g_S[base * DS];
#pragma unroll
    for (int q = 0; q < 4; q++)
        Sp[q] = make_float4(h[q * 4], h[q * 4 + 1], h[q * 4 + 2], h[q * 4 + 3]);
}

__global__ void scan_p2() {
    int idx = blockIdx.x * blockDim.x + threadIdx.x;
    if (idx >= 2 * BB * DI) return;
    int d  = idx % DI;
    int bd = idx / DI;
    int dir = bd / BB;

    const float* Arow = &g_A[(dir * DI + d) * DS];
    float a0 = Arow[0];
    float da = Arow[1] - Arow[0];
    float Ar[DS];
    bool arith = (g_arith != 0);
    if (!arith) {
#pragma unroll
        for (int n = 0; n < DS; n++) Ar[n] = Arow[n];
    }

    float h[DS];
#pragma unroll
    for (int n = 0; n < DS; n++) h[n] = 0.f;

    for (int c = 0; c < CH; c++) {
        size_t base = (((size_t)bd * CH + c) * DI + d);
        float4* Hp = (float4*)&g_h0[base * DS];
#pragma unroll
        for (int q = 0; q < 4; q++)
            Hp[q] = make_float4(h[q * 4], h[q * 4 + 1], h[q * 4 + 2], h[q * 4 + 3]);

        float sdt = g_sumdt[base];
        const float4* Sp = (const float4*)&g_S[base * DS];
        float4 S0 = Sp[0], S1 = Sp[1], S2 = Sp[2], S3 = Sp[3];
        float Sl[DS] = {S0.x, S0.y, S0.z, S0.w, S1.x, S1.y, S1.z, S1.w,
                        S2.x, S2.y, S2.z, S2.w, S3.x, S3.y, S3.z, S3.w};
        if (arith) {
            float p  = __expf(sdt * a0);
            float rr = __expf(sdt * da);
#pragma unroll
            for (int n = 0; n < DS; n++) {
                h[n] = fmaf(p, h[n], Sl[n]);
                p *= rr;
            }
        } else {
#pragma unroll
            for (int n = 0; n < DS; n++)
                h[n] = fmaf(__expf(sdt * Ar[n]), h[n], Sl[n]);
        }
    }
}

__global__ void __launch_bounds__(128, 8)
scan_p3(const float* __restrict__ Dp) {
    int d   = blockIdx.x * blockDim.x + threadIdx.x;
    int b   = blockIdx.y;
    int z   = blockIdx.z;
    int dir = z / CH;
    int c   = z % CH;

    const float* Arow = &g_A[(dir * DI + d) * DS];
    float a0 = Arow[0];
    float da = Arow[1] - Arow[0];
    float Ar[DS];
    bool arith = (g_arith != 0);
    if (!arith) {
#pragma unroll
        for (int n = 0; n < DS; n++) Ar[n] = Arow[n];
    }

    size_t base = (((size_t)(dir * BB + b) * CH + c) * DI + d);
    float h[DS];
    {
        const float4* Hp = (const float4*)&g_h0[base * DS];
        float4 H0 = Hp[0], H1 = Hp[1], H2 = Hp[2], H3 = Hp[3];
        h[0] = H0.x;  h[1] = H0.y;  h[2] = H0.z;  h[3] = H0.w;
        h[4] = H1.x;  h[5] = H1.y;  h[6] = H1.z;  h[7] = H1.w;
        h[8] = H2.x;  h[9] = H2.y;  h[10] = H2.z; h[11] = H2.w;
        h[12] = H3.x; h[13] = H3.y; h[14] = H3.z; h[15] = H3.w;
    }

    float Dd = Dp[dir * DI + d];
    size_t r0 = (size_t)dir * MM + (size_t)b * LL + (size_t)c * CLEN;

    for (int l = 0; l < CLEN; l++) {
        size_t r = r0 + l;
        float u  = g_xb[r * DI + d];
        float dt = g_dt[r * DI + d];
        const float4* BC = (const float4*)(&g_xdbl[r * 80 + DR]);
        float4 Bv0 = __ldg(&BC[0]), Bv1 = __ldg(&BC[1]);
        float4 Bv2 = __ldg(&BC[2]), Bv3 = __ldg(&BC[3]);
        float4 Cv0 = __ldg(&BC[4]), Cv1 = __ldg(&BC[5]);
        float4 Cv2 = __ldg(&BC[6]), Cv3 = __ldg(&BC[7]);
        float Bl[DS] = {Bv0.x, Bv0.y, Bv0.z, Bv0.w, Bv1.x, Bv1.y, Bv1.z, Bv1.w,
                        Bv2.x, Bv2.y, Bv2.z, Bv2.w, Bv3.x, Bv3.y, Bv3.z, Bv3.w};
        float Cl[DS] = {Cv0.x, Cv0.y, Cv0.z, Cv0.w, Cv1.x, Cv1.y, Cv1.z, Cv1.w,
                        Cv2.x, Cv2.y, Cv2.z, Cv2.w, Cv3.x, Cv3.y, Cv3.z, Cv3.w};

        float du = dt * u;
        float yv = 0.f;
        if (arith) {
            float p  = __expf(dt * a0);
            float rr = __expf(dt * da);
#pragma unroll
            for (int n = 0; n < DS; n++) {
                h[n] = fmaf(p, h[n], du * Bl[n]);
                yv   = fmaf(h[n], Cl[n], yv);
                p *= rr;
            }
        } else {
#pragma unroll
            for (int n = 0; n < DS; n++) {
                float p = __expf(dt * Ar[n]);
                h[n] = fmaf(p, h[n], du * Bl[n]);
                yv   = fmaf(h[n], Cl[n], yv);
            }
        }
        yv = fmaf(u, Dd, yv);
        float zz = g_xz[r * (2 * DI) + DI + d];
        float val = yv * siluf_(zz);
        __nv_bfloat16 hh, ll;
        split1(val, hh, ll);
        g_yhi[r * DI + d] = hh;
        g_ylo[r * DI + d] = ll;
    }
}

// ---------------------------------------------------------------------------
extern "C" void kernel_launch(void* const* d_in, const int* in_sizes, int n_in,
                              void* d_out, int out_size) {
    const float* x         = (const float*)d_in[0];
    const float* norm_w    = (const float*)d_in[1];
    const float* in_proj_w = (const float*)d_in[2];
    const float* conv_w    = (const float*)d_in[3];
    const float* conv_b    = (const float*)d_in[4];
    const float* x_proj_w  = (const float*)d_in[5];
    const float* dt_proj_w = (const float*)d_in[6];
    const float* dt_proj_b = (const float*)d_in[7];
    const float* A_log     = (const float*)d_in[8];
    const float* Dp        = (const float*)d_in[9];
    const float* mix_out_w = (const float*)d_in[10];
    const float* gate_w    = (const float*)d_in[11];
    const float* gate_b    = (const float*)d_in[12];
    const float* proj_w    = (const float*)d_in[13];
    const float* proj_b    = (const float*)d_in[14];
    float* out = (float*)d_out;

    float *xz, *xdbl, *dt;
    __nv_bfloat16 *xnhi, *xnlo, *xbhi, *xblo, *x48hi, *x48lo;
    __nv_bfloat16 *yhi, *ylo, *oohi, *oolo, *cbhi, *cblo, *whi, *wlo;
    cudaGetSymbolAddress((void**)&xz,    g_xz);
    cudaGetSymbolAddress((void**)&xdbl,  g_xdbl);
    cudaGetSymbolAddress((void**)&dt,    g_dt);
    cudaGetSymbolAddress((void**)&xnhi,  g_xnhi);
    cudaGetSymbolAddress((void**)&xnlo,  g_xnlo);
    cudaGetSymbolAddress((void**)&xbhi,  g_xbhi);
    cudaGetSymbolAddress((void**)&xblo,  g_xblo);
    cudaGetSymbolAddress((void**)&x48hi, g_x48hi);
    cudaGetSymbolAddress((void**)&x48lo, g_x48lo);
    cudaGetSymbolAddress((void**)&yhi,   g_yhi);
    cudaGetSymbolAddress((void**)&ylo,   g_ylo);
    cudaGetSymbolAddress((void**)&oohi,  g_oohi);
    cudaGetSymbolAddress((void**)&oolo,  g_oolo);
    cudaGetSymbolAddress((void**)&cbhi,  g_cbhi);
    cudaGetSymbolAddress((void**)&cblo,  g_cblo);
    cudaGetSymbolAddress((void**)&whi,   g_whi);
    cudaGetSymbolAddress((void**)&wlo,   g_wlo);

    const int SMEM32 = 4 * 3 * 128 * 32 * 2;   // 98304
    const int SMEM16 = 4 * 3 * 128 * 32 * 1;   // 49152
    cudaFuncSetAttribute(gemm_as<32, EPI_STORE, 1>,    cudaFuncAttributeMaxDynamicSharedMemorySize, SMEM32);
    cudaFuncSetAttribute(gemm_as<32, EPI_ATOM, 8>,     cudaFuncAttributeMaxDynamicSharedMemorySize, SMEM32);
    cudaFuncSetAttribute(gemm_as<16, EPI_SOFTPLUS, 1>, cudaFuncAttributeMaxDynamicSharedMemorySize, SMEM16);
    cudaFuncSetAttribute(gemm_as<32, EPI_STORE, 2>,    cudaFuncAttributeMaxDynamicSharedMemorySize, SMEM32);
    cudaFuncSetAttribute(gemm_as<32, EPI_STORE, 4>,    cudaFuncAttributeMaxDynamicSharedMemorySize, SMEM32);
    cudaFuncSetAttribute(gemm_as<32, EPI_ATOM, 4>,     cudaFuncAttributeMaxDynamicSharedMemorySize, SMEM32);

    setup_A_kernel<<<(2 * DI * DS + 255) / 256, 256>>>(A_log);
    check_arith_kernel<<<(2 * DI + 127) / 128, 128>>>();

    split_weights_kernel<<<(unsigned)((WTOTAL / 4 + 255) / 256), 256>>>(
        in_proj_w, x_proj_w, dt_proj_w, mix_out_w, gate_w, proj_w);

    rmsnorm_kernel<<<2 * MM, 256>>>(x, norm_w);

    const int MY = (MM + 127) / 128;   // 13

    // in_proj: 624 CTAs
    gemm_as<32, EPI_STORE, 1><<<dim3(2 * DI / 128, MY, 2), 256, SMEM32>>>(
        xnhi, xnlo, CM, (size_t)MM * CM,
        whi + WOFF_IN, wlo + WOFF_IN, CM, (size_t)2 * DI * CM,
        xz, 2 * DI, (size_t)MM * 2 * DI,
        MM, 2 * DI, CM, nullptr, 0);

    conv_silu_kernel<<<(2 * MM * DI + 255) / 256, 256>>>(conv_w, conv_b);

    // x_proj: split-K=8, atomic into zeroed xdbl (208 CTAs)
    cudaMemsetAsync(xdbl, 0, sizeof(float) * 2 * MM * 80);
    gemm_as<32, EPI_ATOM, 8><<<dim3(1, MY, 2 * 8), 256, SMEM32>>>(
        xbhi, xblo, DI, (size_t)MM * DI,
        whi + WOFF_XP, wlo + WOFF_XP, DI, (size_t)80 * DI,
        xdbl, 80, (size_t)MM * 80,
        MM, 80, DI, nullptr, 0);

    split_x48<<<(unsigned)((2L * MM * DR / 4 + 255) / 256), 256>>>();

    // dt_proj + softplus (312 CTAs)
    gemm_as<16, EPI_SOFTPLUS, 1><<<dim3(DI / 128, MY, 2), 256, SMEM16>>>(
        x48hi, x48lo, DR, (size_t)MM * DR,
        whi + WOFF_DT, wlo + WOFF_DT, DR, (size_t)DI * DR,
        dt, DI, (size_t)MM * DI,
        MM, DI, DR, dt_proj_b, DI);

    // chunked scan
    scan_p1<<<dim3(DI / 128, BB, 2 * CH), 128>>>();
    scan_p2<<<(2 * BB * DI + 255) / 256, 256>>>();
    scan_p3<<<dim3(DI / 128, BB, 2 * CH), 128>>>(Dp);

    // out_proj: KS=2 partial stores into xz, then single combine
    gemm_as<32, EPI_STORE, 2><<<dim3(CM / 128, MY, 2 * 2), 256, SMEM32>>>(
        yhi, ylo, DI, (size_t)MM * DI,
        whi + WOFF_OUT, wlo + WOFF_OUT, DI, (size_t)CM * DI,
        xz, CM, (size_t)2 * MM * CM,
        MM, CM, DI, nullptr, 0);
    oout_combine_kernel<<<(2 * MM * CM + 255) / 256, 256>>>(x);

    // gate: KS=4 partial stores into xz (312 CTAs, no atomics/memset)
    gemm_as<32, EPI_STORE, 4><<<dim3(CM / 128, MY, 4), 256, SMEM32>>>(
        oohi, oolo, 2 * CM, 0,
        whi + WOFF_GATE, wlo + WOFF_GATE, 2 * CM, 0,
        xz, CM, 0,
        MM, CM, 2 * CM, nullptr, 0);

    // sigmoid combine (+ bias pre-init of out)
    gate_combine_kernel<<<(MM * CM + 255) / 256, 256>>>(gate_b, proj_b, out);

    // final: atomic split-K=4 on bias-preinitialized out (312 CTAs)
    gemm_as<32, EPI_ATOM, 4><<<dim3(CM / 128, MY, 4), 256, SMEM32>>>(
        cbhi, cblo, CM, 0,
        whi + WOFF_PROJ, wlo + WOFF_PROJ, CM, 0,
        out, CM, 0,
        MM, CM, CM, nullptr, 0);

    (void)in_sizes; (void)n_in; (void)out_size;
}

// round 17
// speedup vs baseline: 2.6173x; 1.0201x over previous
#include <cuda_runtime.h>
#include <cuda_bf16.h>
#include <cstdint>

// ---------------------------------------------------------------------------
// BiMamba refiner block, round 16: R15 + x_proj partial stores w/ fused
// combine (no memset/atomics/split_x48), float4-vectorized glue kernels.
// ---------------------------------------------------------------------------

#define BB      2
#define TT      4
#define NP      196
#define LL      784
#define MM      1568
#define CM      768
#define DI      1536
#define DS      16
#define DR      48
#define DCONV   4
#define CH      49
#define CLEN    16

#define WOFF_IN   0L
#define WOFF_XP   4718592L
#define WOFF_DT   4964352L
#define WOFF_OUT  5111808L
#define WOFF_GATE 7471104L
#define WOFF_PROJ 8650752L
#define WTOTAL    9240576L

// ---------------- scratch ---------------------------------------------------
__device__ float g_xz  [2 * MM * 2 * DI];   // in_proj out; later partial buffers
__device__ float g_xb  [2 * MM * DI];
__device__ float g_xdbl[2 * MM * 80];
__device__ float g_dt  [2 * MM * DI];
__device__ float g_out [MM * 2 * CM];
__device__ float g_A   [2 * DI * DS];
__device__ int   g_arith;
__device__ float g_S    [2 * BB * CH * DI * DS];   // scan S; also x_proj partials
__device__ float g_h0   [2 * BB * CH * DI * DS];
__device__ float g_sumdt[2 * BB * CH * DI];

__device__ __align__(256) __nv_bfloat16 g_xnhi [2 * MM * CM];
__device__ __align__(256) __nv_bfloat16 g_xnlo [2 * MM * CM];
__device__ __align__(256) __nv_bfloat16 g_xbhi [2 * MM * DI];
__device__ __align__(256) __nv_bfloat16 g_xblo [2 * MM * DI];
__device__ __align__(256) __nv_bfloat16 g_x48hi[2 * MM * DR];
__device__ __align__(256) __nv_bfloat16 g_x48lo[2 * MM * DR];
__device__ __align__(256) __nv_bfloat16 g_yhi  [2 * MM * DI];
__device__ __align__(256) __nv_bfloat16 g_ylo  [2 * MM * DI];
__device__ __align__(256) __nv_bfloat16 g_oohi [MM * 2 * CM];
__device__ __align__(256) __nv_bfloat16 g_oolo [MM * 2 * CM];
__device__ __align__(256) __nv_bfloat16 g_cbhi [MM * CM];
__device__ __align__(256) __nv_bfloat16 g_cblo [MM * CM];
__device__ __align__(256) __nv_bfloat16 g_whi  [WTOTAL];
__device__ __align__(256) __nv_bfloat16 g_wlo  [WTOTAL];

__device__ __forceinline__ int map_row(int l, int dir) {
    if (dir == 0) return l;
    int t = l / NP, n = l - t * NP;
    return (TT - 1 - t) * NP + n;
}
__device__ __forceinline__ float sigmoidf_(float v) { return 1.0f / (1.0f + __expf(-v)); }
__device__ __forceinline__ float siluf_(float v)    { return v * sigmoidf_(v); }

__device__ __forceinline__ void split1(float v, __nv_bfloat16& h, __nv_bfloat16& l) {
    h = __float2bfloat16(v);
    l = __float2bfloat16(v - __bfloat162float(h));
}

// split float4 -> hi uint2 / lo uint2 (4 packed bf16 each)
__device__ __forceinline__ void split4(float4 v, uint2& hi, uint2& lo) {
    __nv_bfloat16 h0, h1, h2, h3, l0, l1, l2, l3;
    split1(v.x, h0, l0); split1(v.y, h1, l1);
    split1(v.z, h2, l2); split1(v.w, h3, l3);
    __nv_bfloat162 hv0 = __halves2bfloat162(h0, h1);
    __nv_bfloat162 hv1 = __halves2bfloat162(h2, h3);
    __nv_bfloat162 lv0 = __halves2bfloat162(l0, l1);
    __nv_bfloat162 lv1 = __halves2bfloat162(l2, l3);
    hi = make_uint2(*(uint32_t*)&hv0, *(uint32_t*)&hv1);
    lo = make_uint2(*(uint32_t*)&lv0, *(uint32_t*)&lv1);
}

__device__ __forceinline__ void mma_bf16(float c[4],
                                         uint32_t a0, uint32_t a1, uint32_t a2, uint32_t a3,
                                         uint32_t b0, uint32_t b1) {
    asm volatile(
        "mma.sync.aligned.m16n8k16.row.col.f32.bf16.bf16.f32 "
        "{%0,%1,%2,%3},{%4,%5,%6,%7},{%8,%9},{%0,%1,%2,%3};"
        : "+f"(c[0]), "+f"(c[1]), "+f"(c[2]), "+f"(c[3])
        : "r"(a0), "r"(a1), "r"(a2), "r"(a3), "r"(b0), "r"(b1));
}
__device__ __forceinline__ void ldsm_x4(uint32_t& r0, uint32_t& r1, uint32_t& r2,
                                        uint32_t& r3, uint32_t addr) {
    asm volatile("ldmatrix.sync.aligned.m8n8.x4.shared.b16 {%0,%1,%2,%3}, [%4];"
                 : "=r"(r0), "=r"(r1), "=r"(r2), "=r"(r3) : "r"(addr));
}
__device__ __forceinline__ void cp16(uint32_t dst, const void* src, int sz) {
    asm volatile("cp.async.cg.shared.global [%0], [%1], 16, %2;"
                 :: "r"(dst), "l"(src), "r"(sz) : "memory");
}
#define CP_COMMIT() asm volatile("cp.async.commit_group;" ::: "memory")

__device__ __forceinline__ int swz(int row, int chunk) {
    return row * 2 + (chunk ^ ((row >> 2) & 1));
}

// ---------------------------------------------------------------------------
__global__ void setup_A_kernel(const float* __restrict__ A_log) {
    int i = blockIdx.x * blockDim.x + threadIdx.x;
    if (i == 0) g_arith = 1;
    if (i < 2 * DI * DS) g_A[i] = -expf(A_log[i]);
}

__global__ void check_arith_kernel() {
    int row = blockIdx.x * blockDim.x + threadIdx.x;
    if (row >= 2 * DI) return;
    const float* a = &g_A[row * DS];
    float a0 = a[0], da = a[1] - a[0];
    for (int n = 2; n < DS; n++) {
        float expect = a0 + n * da;
        if (fabsf(a[n] - expect) > 1e-4f * (1.0f + fabsf(a[n]))) {
            g_arith = 0;
            return;
        }
    }
}

__global__ void split_weights_kernel(const float* __restrict__ w_in,
                                     const float* __restrict__ w_xp,
                                     const float* __restrict__ w_dt,
                                     const float* __restrict__ w_out,
                                     const float* __restrict__ w_gate,
                                     const float* __restrict__ w_proj) {
    long i4 = (long)blockIdx.x * blockDim.x + threadIdx.x;
    if (i4 >= WTOTAL / 4) return;
    long e = i4 * 4;
    const float* src;
    long loc;
    if (e < WOFF_XP)        { src = w_in;   loc = e - WOFF_IN; }
    else if (e < WOFF_OUT)  {
        if (e < WOFF_DT)    { src = w_xp;   loc = e - WOFF_XP; }
        else                { src = w_dt;   loc = e - WOFF_DT; }
    }
    else if (e < WOFF_GATE) { src = w_out;  loc = e - WOFF_OUT; }
    else if (e < WOFF_PROJ) { src = w_gate; loc = e - WOFF_GATE; }
    else                    { src = w_proj; loc = e - WOFF_PROJ; }
    float4 v = *(const float4*)(src + loc);
    uint2 hi, lo;
    split4(v, hi, lo);
    ((uint2*)g_whi)[i4] = hi;
    ((uint2*)g_wlo)[i4] = lo;
}

// rmsnorm, float4 vectorized
__global__ void rmsnorm_kernel(const float* __restrict__ x,
                               const float* __restrict__ norm_w) {
    int gid = blockIdx.x;
    int dir = gid / MM;
    int rem = gid - dir * MM;
    int b   = rem / LL, l = rem - b * LL;
    int lo_ = map_row(l, dir);
    const float4* row = (const float4*)(x + (size_t)(b * LL + lo_) * CM);

    float s = 0.f;
    for (int c = threadIdx.x; c < CM / 4; c += blockDim.x) {
        float4 v = row[c];
        s += v.x * v.x + v.y * v.y + v.z * v.z + v.w * v.w;
    }
    __shared__ float warp_s[8];
    for (int off = 16; off > 0; off >>= 1) s += __shfl_down_sync(0xffffffffu, s, off);
    if ((threadIdx.x & 31) == 0) warp_s[threadIdx.x >> 5] = s;
    __syncthreads();
    if (threadIdx.x < 8) {
        float t = warp_s[threadIdx.x];
        for (int off = 4; off > 0; off >>= 1) t += __shfl_down_sync(0xffu, t, off);
        if (threadIdx.x == 0) warp_s[0] = t;
    }
    __syncthreads();
    float scale = rsqrtf(warp_s[0] / (float)CM + 1e-5f);

    const float4* nw = (const float4*)(norm_w + dir * CM);
    for (int c = threadIdx.x; c < CM / 4; c += blockDim.x) {
        float4 v = row[c], w = nw[c];
        v.x *= scale * w.x; v.y *= scale * w.y;
        v.z *= scale * w.z; v.w *= scale * w.w;
        uint2 hi, lo2;
        split4(v, hi, lo2);
        ((uint2*)g_xnhi)[(size_t)gid * (CM / 4) + c] = hi;
        ((uint2*)g_xnlo)[(size_t)gid * (CM / 4) + c] = lo2;
    }
}

// x_proj combine: sum 8 partials (in g_S), write xdbl fp32 + x48 hi/lo
__global__ void xproj_combine_kernel() {
    int idx = blockIdx.x * blockDim.x + threadIdx.x;   // over 2*MM*20
    if (idx >= 2 * MM * 20) return;
    int row = idx / 20;          // dir*MM + r
    int c4  = idx - row * 20;
    int dir = row / MM;
    int r   = row - dir * MM;
    const float4* P = (const float4*)g_S + ((size_t)dir * 8 * MM * 20 + (size_t)r * 20 + c4);
    float4 s = make_float4(0.f, 0.f, 0.f, 0.f);
#pragma unroll
    for (int p = 0; p < 8; p++) {
        float4 v = P[(size_t)p * MM * 20];
        s.x += v.x; s.y += v.y; s.z += v.z; s.w += v.w;
    }
    ((float4*)g_xdbl)[idx] = s;
    if (c4 < 12) {
        uint2 hi, lo;
        split4(s, hi, lo);
        ((uint2*)g_x48hi)[(size_t)row * 12 + c4] = hi;
        ((uint2*)g_x48lo)[(size_t)row * 12 + c4] = lo;
    }
}

// out_proj combine (float4): o_out = x + P0 + P1, flip scatter, fp32 + hi/lo
__global__ void oout_combine_kernel(const float* __restrict__ x) {
    int idx = blockIdx.x * blockDim.x + threadIdx.x;   // over 2*MM*192
    if (idx >= 2 * MM * 192) return;
    int dir = idx / (MM * 192);
    int rem = idx - dir * (MM * 192);
    int m = rem / 192, c4 = rem - m * 192;
    int b = m / LL, l = m - b * LL;
    int lo_ = map_row(l, dir);
    int row = b * LL + lo_;
    const float4* P = (const float4*)g_xz + (size_t)dir * 2 * MM * 192;
    float4 p0 = P[rem], p1 = P[(size_t)MM * 192 + rem];
    float4 xv = ((const float4*)x)[(size_t)row * 192 + c4];
    float4 val = make_float4(xv.x + p0.x + p1.x, xv.y + p0.y + p1.y,
                             xv.z + p0.z + p1.z, xv.w + p0.w + p1.w);
    size_t o = ((size_t)row * 2 + dir) * 192 + c4;
    ((float4*)g_out)[o] = val;
    uint2 hi, lo2;
    split4(val, hi, lo2);
    ((uint2*)g_oohi)[o] = hi;
    ((uint2*)g_oolo)[o] = lo2;
}

// gate combine (float4): sum 4 partials, sigmoid blend, emit cb hi/lo + bias init
__global__ void gate_combine_kernel(const float* __restrict__ gate_b,
                                    const float* __restrict__ proj_b,
                                    float* __restrict__ out) {
    int idx = blockIdx.x * blockDim.x + threadIdx.x;   // over MM*192
    if (idx >= MM * 192) return;
    int m = idx / 192, c4 = idx - m * 192;
    const float4* P = (const float4*)g_xz;
    float4 r0 = P[idx];
    float4 r1 = P[(size_t)MM * 192 + idx];
    float4 r2 = P[2 * (size_t)MM * 192 + idx];
    float4 r3 = P[3 * (size_t)MM * 192 + idx];
    float4 gb = ((const float4*)gate_b)[c4];
    float4 of = ((const float4*)g_out)[(size_t)m * 384 + c4];
    float4 ob = ((const float4*)g_out)[(size_t)m * 384 + 192 + c4];
    float4 v;
    {
        float g0 = sigmoidf_(r0.x + r1.x + r2.x + r3.x + gb.x);
        float g1 = sigmoidf_(r0.y + r1.y + r2.y + r3.y + gb.y);
        float g2 = sigmoidf_(r0.z + r1.z + r2.z + r3.z + gb.z);
        float g3 = sigmoidf_(r0.w + r1.w + r2.w + r3.w + gb.w);
        v = make_float4(g0 * of.x + (1.f - g0) * ob.x,
                        g1 * of.y + (1.f - g1) * ob.y,
                        g2 * of.z + (1.f - g2) * ob.z,
                        g3 * of.w + (1.f - g3) * ob.w);
    }
    uint2 hi, lo;
    split4(v, hi, lo);
    ((uint2*)g_cbhi)[idx] = hi;
    ((uint2*)g_cblo)[idx] = lo;
    ((float4*)out)[idx] = ((const float4*)proj_b)[c4];
}

// ---------------------------------------------------------------------------
// cp.async 3-stage bf16 hi/lo MMA GEMM (unchanged inner loop)
// ---------------------------------------------------------------------------
#define EPI_STORE      0
#define EPI_SOFTPLUS   1
#define EPI_ATOM       2

template <int BK, int EPI, int KS>
__global__ void __launch_bounds__(256, 2)
gemm_as(const __nv_bfloat16* __restrict__ Ahib, const __nv_bfloat16* __restrict__ Alob,
        int lda, size_t sA,
        const __nv_bfloat16* __restrict__ Whib, const __nv_bfloat16* __restrict__ Wlob,
        int ldw, size_t sW,
        float* __restrict__ Cb, int ldc, size_t sC,
        int M, int N, int K,
        const float* __restrict__ biasb, size_t sBias) {
    constexpr int KH = BK / 16;
    constexpr int ST = 3;
    constexpr uint32_t STAGE = 128 * 32 * KH;
    extern __shared__ char sm[];

    const int t    = threadIdx.x;
    const int lane = t & 31;
    const int w    = t >> 5;
    const int wm   = (w & 1) * 64;
    const int wn   = (w >> 1) * 32;
    const int g    = lane >> 2;
    const int tg   = lane & 3;

    const int m0    = blockIdx.y * 128;
    const int n0    = blockIdx.x * 128;
    const int z     = blockIdx.z;
    const int dir   = z / KS;
    const int split = z % KS;
    const int Kpart = K / KS;
    const int kbeg  = split * Kpart;

    const __nv_bfloat16* Ahi = Ahib + (size_t)dir * sA;
    const __nv_bfloat16* Alo = Alob + (size_t)dir * sA;
    const __nv_bfloat16* Whi = Whib + (size_t)dir * sW;
    const __nv_bfloat16* Wlo = Wlob + (size_t)dir * sW;
    float* C = Cb + (size_t)dir * sC;
    if (EPI == EPI_STORE && KS > 1) C += (size_t)split * (size_t)M * ldc;
    const float* bias = biasb ? biasb + (size_t)dir * sBias : nullptr;

    const uint32_t sbase = (uint32_t)__cvta_generic_to_shared(sm);
    const uint32_t bAh = sbase;
    const uint32_t bAl = sbase + ST * STAGE;
    const uint32_t bBh = sbase + 2 * ST * STAGE;
    const uint32_t bBl = sbase + 3 * ST * STAGE;

    int crow[KH], ckc[KH];
    uint32_t cdoff[KH];
#pragma unroll
    for (int i = 0; i < KH; i++) {
        int cid = t + i * 256;
        crow[i] = cid / (2 * KH);
        ckc[i]  = cid % (2 * KH);
        int h  = ckc[i] >> 1, ch = ckc[i] & 1;
        cdoff[i] = (uint32_t)(h * 4096 + swz(crow[i], ch) * 16);
    }

    auto issue = [&](int kt) {
        int s = kt % ST;
        int kglob = kbeg + kt * BK;
#pragma unroll
        for (int i = 0; i < KH; i++) {
            int row = crow[i];
            int h = ckc[i] >> 1, ch = ckc[i] & 1;
            int ke = kglob + h * 16 + ch * 8;
            uint32_t doff = (uint32_t)(s * STAGE) + cdoff[i];
            int gm = m0 + row;
            int gmc = (gm < M) ? gm : 0;
            int szA = (gm < M) ? 16 : 0;
            cp16(bAh + doff, Ahi + (size_t)gmc * lda + ke, szA);
            cp16(bAl + doff, Alo + (size_t)gmc * lda + ke, szA);
            int gn = n0 + row;
            int gnc = (gn < N) ? gn : 0;
            int szB = (gn < N) ? 16 : 0;
            cp16(bBh + doff, Whi + (size_t)gnc * ldw + ke, szB);
            cp16(bBl + doff, Wlo + (size_t)gnc * ldw + ke, szB);
        }
        CP_COMMIT();
    };

    const int a_r = lane & 15;
    const int a_c = lane >> 4;
    const int b_r = (lane & 7) + ((lane & 16) ? 8 : 0);
    const int b_c = (lane >> 3) & 1;
    uint32_t offA[4];
#pragma unroll
    for (int i = 0; i < 4; i++)
        offA[i] = (uint32_t)(swz(wm + i * 16 + a_r, a_c) * 16);
    const uint32_t offB0 = (uint32_t)(swz(wn + b_r,      b_c) * 16);
    const uint32_t offB1 = (uint32_t)(swz(wn + 16 + b_r, b_c) * 16);

    float acc[4][4][4];
#pragma unroll
    for (int i = 0; i < 4; i++)
#pragma unroll
        for (int j = 0; j < 4; j++)
#pragma unroll
            for (int r = 0; r < 4; r++) acc[i][j][r] = 0.f;

    const int nk = Kpart / BK;
    issue(0);
    if (nk > 1) issue(1);

    for (int kt = 0; kt < nk; kt++) {
        if (kt == nk - 1)
            asm volatile("cp.async.wait_group 0;" ::: "memory");
        else
            asm volatile("cp.async.wait_group 1;" ::: "memory");
        __syncthreads();

        const uint32_t stg = (uint32_t)((kt % ST) * STAGE);
#pragma unroll
        for (int h = 0; h < KH; h++) {
            const uint32_t hb = stg + (uint32_t)(h * 4096);
            uint32_t ah[4][4], al[4][4], bh[8], bl[8];
            ldsm_x4(bh[0], bh[1], bh[2], bh[3], bBh + hb + offB0);
            ldsm_x4(bh[4], bh[5], bh[6], bh[7], bBh + hb + offB1);
            ldsm_x4(bl[0], bl[1], bl[2], bl[3], bBl + hb + offB0);
            ldsm_x4(bl[4], bl[5], bl[6], bl[7], bBl + hb + offB1);
#pragma unroll
            for (int i = 0; i < 4; i++) {
                ldsm_x4(ah[i][0], ah[i][1], ah[i][2], ah[i][3], bAh + hb + offA[i]);
                ldsm_x4(al[i][0], al[i][1], al[i][2], al[i][3], bAl + hb + offA[i]);
            }
#pragma unroll
            for (int j = 0; j < 4; j++) {
                uint32_t b0h = bh[j * 2], b1h = bh[j * 2 + 1];
                uint32_t b0l = bl[j * 2], b1l = bl[j * 2 + 1];
#pragma unroll
                for (int i = 0; i < 4; i++) {
                    mma_bf16(acc[i][j], ah[i][0], ah[i][1], ah[i][2], ah[i][3], b0h, b1h);
                    mma_bf16(acc[i][j], ah[i][0], ah[i][1], ah[i][2], ah[i][3], b0l, b1l);
                    mma_bf16(acc[i][j], al[i][0], al[i][1], al[i][2], al[i][3], b0h, b1h);
                }
            }
        }
        if (kt + 2 < nk) issue(kt + 2);
    }

    auto emit = [&](int m, int n, float v) {
        if (m >= M || n >= N) return;
        if (EPI == EPI_STORE) {
            C[(size_t)m * ldc + n] = v;
        } else if (EPI == EPI_SOFTPLUS) {
            v += bias[n];
            C[(size_t)m * ldc + n] = (v > 20.f) ? v : log1pf(__expf(v));
        } else {
            atomicAdd(&C[(size_t)m * ldc + n], v);
        }
    };

#pragma unroll
    for (int i = 0; i < 4; i++) {
        int mr = m0 + wm + i * 16 + g;
#pragma unroll
        for (int j = 0; j < 4; j++) {
            int nc = n0 + wn + j * 8 + 2 * tg;
            emit(mr,     nc,     acc[i][j][0]);
            emit(mr,     nc + 1, acc[i][j][1]);
            emit(mr + 8, nc,     acc[i][j][2]);
            emit(mr + 8, nc + 1, acc[i][j][3]);
        }
    }
}

// ---------------------------------------------------------------------------
// conv + silu, float4 vectorized (4 channels/thread)
// ---------------------------------------------------------------------------
__global__ void conv_silu_kernel(const float* __restrict__ conv_w,
                                 const float* __restrict__ conv_b) {
    int idx = blockIdx.x * blockDim.x + threadIdx.x;   // over 2*MM*(DI/4)
    if (idx >= 2 * MM * (DI / 4)) return;
    int d4 = idx % (DI / 4);
    int r  = idx / (DI / 4);
    int dir = r / MM;
    int l = r % LL;
    int d = d4 * 4;

    const float4* wp = (const float4*)(conv_w + ((size_t)dir * DI + d) * DCONV);
    float4 w0 = wp[0], w1 = wp[1], w2 = wp[2], w3 = wp[3];   // per-channel taps
    float4 acc = *(const float4*)(conv_b + dir * DI + d);

#pragma unroll
    for (int j = 0; j < DCONV; j++) {
        int ls = l - (DCONV - 1) + j;
        if (ls >= 0) {
            float4 xv = *(const float4*)&g_xz[(size_t)(r - (DCONV - 1) + j) * (2 * DI) + d];
            float wj0 = (&w0.x)[j], wj1 = (&w1.x)[j], wj2 = (&w2.x)[j], wj3 = (&w3.x)[j];
            acc.x = fmaf(wj0, xv.x, acc.x);
            acc.y = fmaf(wj1, xv.y, acc.y);
            acc.z = fmaf(wj2, xv.z, acc.z);
            acc.w = fmaf(wj3, xv.w, acc.w);
        }
    }
    float4 v = make_float4(siluf_(acc.x), siluf_(acc.y), siluf_(acc.z), siluf_(acc.w));
    *(float4*)&g_xb[(size_t)r * DI + d] = v;
    uint2 hi, lo;
    split4(v, hi, lo);
    ((uint2*)g_xbhi)[(size_t)r * (DI / 4) + d4] = hi;
    ((uint2*)g_xblo)[(size_t)r * (DI / 4) + d4] = lo;
}

// ---------------------------------------------------------------------------
// chunked scan (CH=49) — unchanged
// ---------------------------------------------------------------------------
__global__ void __launch_bounds__(128, 8)
scan_p1() {
    int d   = blockIdx.x * blockDim.x + threadIdx.x;
    int b   = blockIdx.y;
    int z   = blockIdx.z;
    int dir = z / CH;
    int c   = z % CH;

    const float* Arow = &g_A[(dir * DI + d) * DS];
    float a0 = Arow[0];
    float da = Arow[1] - Arow[0];
    float Ar[DS];
    bool arith = (g_arith != 0);
    if (!arith) {
#pragma unroll
        for (int n = 0; n < DS; n++) Ar[n] = Arow[n];
    }

    float h[DS];
#pragma unroll
    for (int n = 0; n < DS; n++) h[n] = 0.f;
    float sdt = 0.f;

    size_t r0 = (size_t)dir * MM + (size_t)b * LL + (size_t)c * CLEN;
    for (int l = 0; l < CLEN; l++) {
        size_t r = r0 + l;
        float u  = g_xb[r * DI + d];
        float dt = g_dt[r * DI + d];
        const float4* Bv = (const float4*)(&g_xdbl[r * 80 + DR]);
        float4 B0 = __ldg(&Bv[0]), B1 = __ldg(&Bv[1]);
        float4 B2 = __ldg(&Bv[2]), B3 = __ldg(&Bv[3]);
        float Bl[DS] = {B0.x, B0.y, B0.z, B0.w, B1.x, B1.y, B1.z, B1.w,
                        B2.x, B2.y, B2.z, B2.w, B3.x, B3.y, B3.z, B3.w};
        float du = dt * u;
        if (arith) {
            float p  = __expf(dt * a0);
            float rr = __expf(dt * da);
#pragma unroll
            for (int n = 0; n < DS; n++) {
                h[n] = fmaf(p, h[n], du * Bl[n]);
                p *= rr;
            }
        } else {
#pragma unroll
            for (int n = 0; n < DS; n++)
                h[n] = fmaf(__expf(dt * Ar[n]), h[n], du * Bl[n]);
        }
        sdt += dt;
    }

    size_t base = (((size_t)(dir * BB + b) * CH + c) * DI + d);
    g_sumdt[base] = sdt;
    float4* Sp = (float4*)&g_S[base * DS];
#pragma unroll
    for (int q = 0; q < 4; q++)
        Sp[q] = make_float4(h[q * 4], h[q * 4 + 1], h[q * 4 + 2], h[q * 4 + 3]);
}

__global__ void scan_p2() {
    int idx = blockIdx.x * blockDim.x + threadIdx.x;
    if (idx >= 2 * BB * DI) return;
    int d  = idx % DI;
    int bd = idx / DI;
    int dir = bd / BB;

    const float* Arow = &g_A[(dir * DI + d) * DS];
    float a0 = Arow[0];
    float da = Arow[1] - Arow[0];
    float Ar[DS];
    bool arith = (g_arith != 0);
    if (!arith) {
#pragma unroll
        for (int n = 0; n < DS; n++) Ar[n] = Arow[n];
    }

    float h[DS];
#pragma unroll
    for (int n = 0; n < DS; n++) h[n] = 0.f;

    for (int c = 0; c < CH; c++) {
        size_t base = (((size_t)bd * CH + c) * DI + d);
        float4* Hp = (float4*)&g_h0[base * DS];
#pragma unroll
        for (int q = 0; q < 4; q++)
            Hp[q] = make_float4(h[q * 4], h[q * 4 + 1], h[q * 4 + 2], h[q * 4 + 3]);

        float sdt = g_sumdt[base];
        const float4* Sp = (const float4*)&g_S[base * DS];
        float4 S0 = Sp[0], S1 = Sp[1], S2 = Sp[2], S3 = Sp[3];
        float Sl[DS] = {S0.x, S0.y, S0.z, S0.w, S1.x, S1.y, S1.z, S1.w,
                        S2.x, S2.y, S2.z, S2.w, S3.x, S3.y, S3.z, S3.w};
        if (arith) {
            float p  = __expf(sdt * a0);
            float rr = __expf(sdt * da);
#pragma unroll
            for (int n = 0; n < DS; n++) {
                h[n] = fmaf(p, h[n], Sl[n]);
                p *= rr;
            }
        } else {
#pragma unroll
            for (int n = 0; n < DS; n++)
                h[n] = fmaf(__expf(sdt * Ar[n]), h[n], Sl[n]);
        }
    }
}

__global__ void __launch_bounds__(128, 8)
scan_p3(const float* __restrict__ Dp) {
    int d   = blockIdx.x * blockDim.x + threadIdx.x;
    int b   = blockIdx.y;
    int z   = blockIdx.z;
    int dir = z / CH;
    int c   = z % CH;

    const float* Arow = &g_A[(dir * DI + d) * DS];
    float a0 = Arow[0];
    float da = Arow[1] - Arow[0];
    float Ar[DS];
    bool arith = (g_arith != 0);
    if (!arith) {
#pragma unroll
        for (int n = 0; n < DS; n++) Ar[n] = Arow[n];
    }

    size_t base = (((size_t)(dir * BB + b) * CH + c) * DI + d);
    float h[DS];
    {
        const float4* Hp = (const float4*)&g_h0[base * DS];
        float4 H0 = Hp[0], H1 = Hp[1], H2 = Hp[2], H3 = Hp[3];
        h[0] = H0.x;  h[1] = H0.y;  h[2] = H0.z;  h[3] = H0.w;
        h[4] = H1.x;  h[5] = H1.y;  h[6] = H1.z;  h[7] = H1.w;
        h[8] = H2.x;  h[9] = H2.y;  h[10] = H2.z; h[11] = H2.w;
        h[12] = H3.x; h[13] = H3.y; h[14] = H3.z; h[15] = H3.w;
    }

    float Dd = Dp[dir * DI + d];
    size_t r0 = (size_t)dir * MM + (size_t)b * LL + (size_t)c * CLEN;

    for (int l = 0; l < CLEN; l++) {
        size_t r = r0 + l;
        float u  = g_xb[r * DI + d];
        float dt = g_dt[r * DI + d];
        const float4* BC = (const float4*)(&g_xdbl[r * 80 + DR]);
        float4 Bv0 = __ldg(&BC[0]), Bv1 = __ldg(&BC[1]);
        float4 Bv2 = __ldg(&BC[2]), Bv3 = __ldg(&BC[3]);
        float4 Cv0 = __ldg(&BC[4]), Cv1 = __ldg(&BC[5]);
        float4 Cv2 = __ldg(&BC[6]), Cv3 = __ldg(&BC[7]);
        float Bl[DS] = {Bv0.x, Bv0.y, Bv0.z, Bv0.w, Bv1.x, Bv1.y, Bv1.z, Bv1.w,
                        Bv2.x, Bv2.y, Bv2.z, Bv2.w, Bv3.x, Bv3.y, Bv3.z, Bv3.w};
        float Cl[DS] = {Cv0.x, Cv0.y, Cv0.z, Cv0.w, Cv1.x, Cv1.y, Cv1.z, Cv1.w,
                        Cv2.x, Cv2.y, Cv2.z, Cv2.w, Cv3.x, Cv3.y, Cv3.z, Cv3.w};

        float du = dt * u;
        float yv = 0.f;
        if (arith) {
            float p  = __expf(dt * a0);
            float rr = __expf(dt * da);
#pragma unroll
            for (int n = 0; n < DS; n++) {
                h[n] = fmaf(p, h[n], du * Bl[n]);
                yv   = fmaf(h[n], Cl[n], yv);
                p *= rr;
            }
        } else {
#pragma unroll
            for (int n = 0; n < DS; n++) {
                float p = __expf(dt * Ar[n]);
                h[n] = fmaf(p, h[n], du * Bl[n]);
                yv   = fmaf(h[n], Cl[n], yv);
            }
        }
        yv = fmaf(u, Dd, yv);
        float zz = g_xz[r * (2 * DI) + DI + d];
        float val = yv * siluf_(zz);
        __nv_bfloat16 hh, ll;
        split1(val, hh, ll);
        g_yhi[r * DI + d] = hh;
        g_ylo[r * DI + d] = ll;
    }
}

// ---------------------------------------------------------------------------
extern "C" void kernel_launch(void* const* d_in, const int* in_sizes, int n_in,
                              void* d_out, int out_size) {
    const float* x         = (const float*)d_in[0];
    const float* norm_w    = (const float*)d_in[1];
    const float* in_proj_w = (const float*)d_in[2];
    const float* conv_w    = (const float*)d_in[3];
    const float* conv_b    = (const float*)d_in[4];
    const float* x_proj_w  = (const float*)d_in[5];
    const float* dt_proj_w = (const float*)d_in[6];
    const float* dt_proj_b = (const float*)d_in[7];
    const float* A_log     = (const float*)d_in[8];
    const float* Dp        = (const float*)d_in[9];
    const float* mix_out_w = (const float*)d_in[10];
    const float* gate_w    = (const float*)d_in[11];
    const float* gate_b    = (const float*)d_in[12];
    const float* proj_w    = (const float*)d_in[13];
    const float* proj_b    = (const float*)d_in[14];
    float* out = (float*)d_out;

    float *xz, *dt, *S;
    __nv_bfloat16 *xnhi, *xnlo, *xbhi, *xblo, *x48hi, *x48lo;
    __nv_bfloat16 *yhi, *ylo, *oohi, *oolo, *cbhi, *cblo, *whi, *wlo;
    cudaGetSymbolAddress((void**)&xz,    g_xz);
    cudaGetSymbolAddress((void**)&dt,    g_dt);
    cudaGetSymbolAddress((void**)&S,     g_S);
    cudaGetSymbolAddress((void**)&xnhi,  g_xnhi);
    cudaGetSymbolAddress((void**)&xnlo,  g_xnlo);
    cudaGetSymbolAddress((void**)&xbhi,  g_xbhi);
    cudaGetSymbolAddress((void**)&xblo,  g_xblo);
    cudaGetSymbolAddress((void**)&x48hi, g_x48hi);
    cudaGetSymbolAddress((void**)&x48lo, g_x48lo);
    cudaGetSymbolAddress((void**)&yhi,   g_yhi);
    cudaGetSymbolAddress((void**)&ylo,   g_ylo);
    cudaGetSymbolAddress((void**)&oohi,  g_oohi);
    cudaGetSymbolAddress((void**)&oolo,  g_oolo);
    cudaGetSymbolAddress((void**)&cbhi,  g_cbhi);
    cudaGetSymbolAddress((void**)&cblo,  g_cblo);
    cudaGetSymbolAddress((void**)&whi,   g_whi);
    cudaGetSymbolAddress((void**)&wlo,   g_wlo);

    const int SMEM32 = 4 * 3 * 128 * 32 * 2;   // 98304
    const int SMEM16 = 4 * 3 * 128 * 32 * 1;   // 49152
    cudaFuncSetAttribute(gemm_as<32, EPI_STORE, 1>,    cudaFuncAttributeMaxDynamicSharedMemorySize, SMEM32);
    cudaFuncSetAttribute(gemm_as<32, EPI_STORE, 8>,    cudaFuncAttributeMaxDynamicSharedMemorySize, SMEM32);
    cudaFuncSetAttribute(gemm_as<16, EPI_SOFTPLUS, 1>, cudaFuncAttributeMaxDynamicSharedMemorySize, SMEM16);
    cudaFuncSetAttribute(gemm_as<32, EPI_STORE, 2>,    cudaFuncAttributeMaxDynamicSharedMemorySize, SMEM32);
    cudaFuncSetAttribute(gemm_as<32, EPI_STORE, 4>,    cudaFuncAttributeMaxDynamicSharedMemorySize, SMEM32);
    cudaFuncSetAttribute(gemm_as<32, EPI_ATOM, 4>,     cudaFuncAttributeMaxDynamicSharedMemorySize, SMEM32);

    setup_A_kernel<<<(2 * DI * DS + 255) / 256, 256>>>(A_log);
    check_arith_kernel<<<(2 * DI + 127) / 128, 128>>>();

    split_weights_kernel<<<(unsigned)((WTOTAL / 4 + 255) / 256), 256>>>(
        in_proj_w, x_proj_w, dt_proj_w, mix_out_w, gate_w, proj_w);

    rmsnorm_kernel<<<2 * MM, 256>>>(x, norm_w);

    const int MY = (MM + 127) / 128;   // 13

    // in_proj: 624 CTAs
    gemm_as<32, EPI_STORE, 1><<<dim3(2 * DI / 128, MY, 2), 256, SMEM32>>>(
        xnhi, xnlo, CM, (size_t)MM * CM,
        whi + WOFF_IN, wlo + WOFF_IN, CM, (size_t)2 * DI * CM,
        xz, 2 * DI, (size_t)MM * 2 * DI,
        MM, 2 * DI, CM, nullptr, 0);

    conv_silu_kernel<<<(2 * MM * (DI / 4) + 255) / 256, 256>>>(conv_w, conv_b);

    // x_proj: split-K=8 partial stores into g_S, then fused combine
    gemm_as<32, EPI_STORE, 8><<<dim3(1, MY, 2 * 8), 256, SMEM32>>>(
        xbhi, xblo, DI, (size_t)MM * DI,
        whi + WOFF_XP, wlo + WOFF_XP, DI, (size_t)80 * DI,
        S, 80, (size_t)8 * MM * 80,
        MM, 80, DI, nullptr, 0);
    xproj_combine_kernel<<<(2 * MM * 20 + 255) / 256, 256>>>();

    // dt_proj + softplus (312 CTAs)
    gemm_as<16, EPI_SOFTPLUS, 1><<<dim3(DI / 128, MY, 2), 256, SMEM16>>>(
        x48hi, x48lo, DR, (size_t)MM * DR,
        whi + WOFF_DT, wlo + WOFF_DT, DR, (size_t)DI * DR,
        dt, DI, (size_t)MM * DI,
        MM, DI, DR, dt_proj_b, DI);

    // chunked scan
    scan_p1<<<dim3(DI / 128, BB, 2 * CH), 128>>>();
    scan_p2<<<(2 * BB * DI + 255) / 256, 256>>>();
    scan_p3<<<dim3(DI / 128, BB, 2 * CH), 128>>>(Dp);

    // out_proj: KS=2 partial stores into xz, then single combine
    gemm_as<32, EPI_STORE, 2><<<dim3(CM / 128, MY, 2 * 2), 256, SMEM32>>>(
        yhi, ylo, DI, (size_t)MM * DI,
        whi + WOFF_OUT, wlo + WOFF_OUT, DI, (size_t)CM * DI,
        xz, CM, (size_t)2 * MM * CM,
        MM, CM, DI, nullptr, 0);
    oout_combine_kernel<<<(2 * MM * 192 + 255) / 256, 256>>>(x);

    // gate: KS=4 partial stores into xz
    gemm_as<32, EPI_STORE, 4><<<dim3(CM / 128, MY, 4), 256, SMEM32>>>(
        oohi, oolo, 2 * CM, 0,
        whi + WOFF_GATE, wlo + WOFF_GATE, 2 * CM, 0,
        xz, CM, 0,
        MM, CM, 2 * CM, nullptr, 0);

    // sigmoid combine (+ bias pre-init of out)
    gate_combine_kernel<<<(MM * 192 + 255) / 256, 256>>>(gate_b, proj_b, out);

    // final: atomic split-K=4 on bias-preinitialized out (312 CTAs)
    gemm_as<32, EPI_ATOM, 4><<<dim3(CM / 128, MY, 4), 256, SMEM32>>>(
        cbhi, cblo, CM, 0,
        whi + WOFF_PROJ, wlo + WOFF_PROJ, CM, 0,
        out, CM, 0,
        MM, CM, CM, nullptr, 0);

    (void)in_sizes; (void)n_in; (void)out_size;
}